// round 1
// baseline (speedup 1.0000x reference)
#include <cuda_runtime.h>
#include <math.h>

// Problem dims
#define BB   2
#define SSQ  2048
#define DD   1024
#define HHD  16
#define DKK  64
#define MTOT (BB * SSQ)   // 4096

// Scratch (allocation-free rule: __device__ globals)
__device__ float g_Qp[MTOT * DD];
__device__ float g_Kp[MTOT * DD];
__device__ float g_Vp[MTOT * DD];
__device__ float g_Op[MTOT * DD];

// ---------------------------------------------------------------------------
// GEMM: C[M,N] = A[M,K] @ W[N,K]^T + bias[N]
// M=4096, N=K=1024. 64x64 tile, BK=16, 256 threads, 4x4 microtile per thread.
// Both operands are K-contiguous (row-major A, row-major W) -> float4 gmem loads,
// transposed into smem so the inner loop is an outer product with float4 LDS.
// ---------------------------------------------------------------------------
__global__ __launch_bounds__(256, 4) void gemm_bias_k(
    const float* __restrict__ A, const float* __restrict__ W,
    const float* __restrict__ bias, float* __restrict__ C)
{
    __shared__ float As[16][68];   // [k][m], pad 68 keeps float4 alignment (272B % 16 == 0)
    __shared__ float Ws[16][68];   // [k][n]

    const int bm = blockIdx.y * 64;
    const int bn = blockIdx.x * 64;
    const int t  = threadIdx.x;
    const int ty = t >> 4;         // 0..15  (m direction)
    const int tx = t & 15;         // 0..15  (n direction)
    const int lr  = t >> 2;        // 0..63  load row within tile
    const int lk4 = t & 3;         // which float4 along k

    float acc[4][4];
#pragma unroll
    for (int i = 0; i < 4; i++)
#pragma unroll
        for (int j = 0; j < 4; j++) acc[i][j] = 0.0f;

    const float* Arow = A + (size_t)(bm + lr) * DD + lk4 * 4;
    const float* Wrow = W + (size_t)(bn + lr) * DD + lk4 * 4;

    for (int k0 = 0; k0 < DD; k0 += 16) {
        float4 av = *(const float4*)(Arow + k0);
        float4 wv = *(const float4*)(Wrow + k0);
        __syncthreads();           // protect previous iteration's smem reads
        As[lk4 * 4 + 0][lr] = av.x;
        As[lk4 * 4 + 1][lr] = av.y;
        As[lk4 * 4 + 2][lr] = av.z;
        As[lk4 * 4 + 3][lr] = av.w;
        Ws[lk4 * 4 + 0][lr] = wv.x;
        Ws[lk4 * 4 + 1][lr] = wv.y;
        Ws[lk4 * 4 + 2][lr] = wv.z;
        Ws[lk4 * 4 + 3][lr] = wv.w;
        __syncthreads();
#pragma unroll
        for (int k = 0; k < 16; k++) {
            float4 a = *(const float4*)&As[k][ty * 4];
            float4 w = *(const float4*)&Ws[k][tx * 4];
            float ar[4] = {a.x, a.y, a.z, a.w};
            float wr[4] = {w.x, w.y, w.z, w.w};
#pragma unroll
            for (int i = 0; i < 4; i++)
#pragma unroll
                for (int j = 0; j < 4; j++)
                    acc[i][j] = fmaf(ar[i], wr[j], acc[i][j]);
        }
    }

#pragma unroll
    for (int j = 0; j < 4; j++) {
        float bj = bias[bn + tx * 4 + j];
#pragma unroll
        for (int i = 0; i < 4; i++)
            C[(size_t)(bm + ty * 4 + i) * DD + bn + tx * 4 + j] = acc[i][j] + bj;
    }
}

// ---------------------------------------------------------------------------
// Flash attention, fp32, per (b,h): Q tile 64 rows x DK=64, KV tiles of 64.
// 256 threads, 16x16 thread layout, 4x4 microtile in both S=Q*K^T and O+=P*V.
// Row softmax state (m,l) replicated across the 16 lanes sharing a row group
// via shfl.bfly over xor offsets {1,2,4,8} (stays within 16-lane halves).
// mask[b, key]==0 -> score = -1e9 (matches reference exactly).
// ---------------------------------------------------------------------------
#define SMTILE (64 * 68)   // floats per smem tile buffer

__global__ __launch_bounds__(256, 1) void flash_attn_k(
    const float* __restrict__ Qp, const float* __restrict__ Kp,
    const float* __restrict__ Vp, const int* __restrict__ mask,
    float* __restrict__ Op)
{
    extern __shared__ float sm[];
    float* Qs = sm;               // [kk][row]   (transposed)
    float* Ks = sm + SMTILE;      // [kk][col]   (transposed)
    float* Vs = sm + 2 * SMTILE;  // [c][j]      (natural)
    float* Ps = sm + 3 * SMTILE;  // [c][row]    (transposed)

    const int bh = blockIdx.y;
    const int b  = bh / HHD;
    const int h  = bh % HHD;
    const int q0 = blockIdx.x * 64;
    const int t  = threadIdx.x;
    const int ty = t >> 4;   // row group: rows ty*4 .. ty*4+3
    const int tx = t & 15;   // col group: cols tx*4 .. tx*4+3

    const size_t headoff = (size_t)h * DKK;
    const float scale = 0.125f;   // 1/sqrt(64)

    // Load Q tile transposed: Qs[kk][row]
    for (int i = t; i < 64 * 16; i += 256) {
        int row = i >> 4;
        int kq  = i & 15;
        float4 qv = *(const float4*)&Qp[(size_t)(b * SSQ + q0 + row) * DD + headoff + kq * 4];
        Qs[(kq * 4 + 0) * 68 + row] = qv.x;
        Qs[(kq * 4 + 1) * 68 + row] = qv.y;
        Qs[(kq * 4 + 2) * 68 + row] = qv.z;
        Qs[(kq * 4 + 3) * 68 + row] = qv.w;
    }

    float m_r[4], l_r[4], acc[4][4];
#pragma unroll
    for (int i = 0; i < 4; i++) {
        m_r[i] = -INFINITY;
        l_r[i] = 0.0f;
#pragma unroll
        for (int j = 0; j < 4; j++) acc[i][j] = 0.0f;
    }

    for (int kv0 = 0; kv0 < SSQ; kv0 += 64) {
        __syncthreads();  // prior iteration's Ks/Vs/Ps reads complete
        // Load K (transposed) and V (natural) tiles
        for (int i = t; i < 64 * 16; i += 256) {
            int row = i >> 4;
            int kq  = i & 15;
            size_t gro = (size_t)(b * SSQ + kv0 + row) * DD + headoff + kq * 4;
            float4 kv = *(const float4*)&Kp[gro];
            Ks[(kq * 4 + 0) * 68 + row] = kv.x;
            Ks[(kq * 4 + 1) * 68 + row] = kv.y;
            Ks[(kq * 4 + 2) * 68 + row] = kv.z;
            Ks[(kq * 4 + 3) * 68 + row] = kv.w;
            float4 vv = *(const float4*)&Vp[gro];
            *(float4*)&Vs[row * 68 + kq * 4] = vv;
        }
        int mk[4];
#pragma unroll
        for (int j = 0; j < 4; j++)
            mk[j] = mask[b * SSQ + kv0 + tx * 4 + j];
        __syncthreads();

        // Phase A: S = Q * K^T (64x64x64)
        float s[4][4];
#pragma unroll
        for (int i = 0; i < 4; i++)
#pragma unroll
            for (int j = 0; j < 4; j++) s[i][j] = 0.0f;

#pragma unroll 8
        for (int kk = 0; kk < 64; kk++) {
            float4 a = *(const float4*)&Qs[kk * 68 + ty * 4];
            float4 c = *(const float4*)&Ks[kk * 68 + tx * 4];
            float ar[4] = {a.x, a.y, a.z, a.w};
            float cr[4] = {c.x, c.y, c.z, c.w};
#pragma unroll
            for (int i = 0; i < 4; i++)
#pragma unroll
                for (int j = 0; j < 4; j++)
                    s[i][j] = fmaf(ar[i], cr[j], s[i][j]);
        }

        // Scale + mask
#pragma unroll
        for (int i = 0; i < 4; i++)
#pragma unroll
            for (int j = 0; j < 4; j++)
                s[i][j] = mk[j] ? s[i][j] * scale : -1e9f;

        // Online softmax per row (reduce across the 16 lanes of the row group)
#pragma unroll
        for (int i = 0; i < 4; i++) {
            float mt = fmaxf(fmaxf(s[i][0], s[i][1]), fmaxf(s[i][2], s[i][3]));
#pragma unroll
            for (int off = 1; off < 16; off <<= 1)
                mt = fmaxf(mt, __shfl_xor_sync(0xffffffffu, mt, off));
            float mnew = fmaxf(m_r[i], mt);
            float f = __expf(m_r[i] - mnew);
            float rs = 0.0f;
#pragma unroll
            for (int j = 0; j < 4; j++) {
                s[i][j] = __expf(s[i][j] - mnew);
                rs += s[i][j];
            }
#pragma unroll
            for (int off = 1; off < 16; off <<= 1)
                rs += __shfl_xor_sync(0xffffffffu, rs, off);
            l_r[i] = l_r[i] * f + rs;
            m_r[i] = mnew;
#pragma unroll
            for (int j = 0; j < 4; j++) acc[i][j] *= f;
        }

        // Write P transposed: Ps[c][row]
#pragma unroll
        for (int j = 0; j < 4; j++)
#pragma unroll
            for (int i = 0; i < 4; i++)
                Ps[(tx * 4 + j) * 68 + ty * 4 + i] = s[i][j];
        __syncthreads();

        // Phase C: O += P * V (64x64x64)
#pragma unroll 8
        for (int c = 0; c < 64; c++) {
            float4 p = *(const float4*)&Ps[c * 68 + ty * 4];
            float4 v = *(const float4*)&Vs[c * 68 + tx * 4];
            float pr[4] = {p.x, p.y, p.z, p.w};
            float vr[4] = {v.x, v.y, v.z, v.w};
#pragma unroll
            for (int i = 0; i < 4; i++)
#pragma unroll
                for (int j = 0; j < 4; j++)
                    acc[i][j] = fmaf(pr[i], vr[j], acc[i][j]);
        }
    }

    // Epilogue: normalize and store to Op[b, q0+row, h*64 + col]
#pragma unroll
    for (int i = 0; i < 4; i++) {
        float inv = 1.0f / l_r[i];
#pragma unroll
        for (int j = 0; j < 4; j++)
            Op[(size_t)(b * SSQ + q0 + ty * 4 + i) * DD + headoff + tx * 4 + j] =
                acc[i][j] * inv;
    }
}

// ---------------------------------------------------------------------------
// Launch
// ---------------------------------------------------------------------------
extern "C" void kernel_launch(void* const* d_in, const int* in_sizes, int n_in,
                              void* d_out, int out_size)
{
    const float* q    = (const float*)d_in[0];
    const float* k    = (const float*)d_in[1];
    const float* v    = (const float*)d_in[2];
    const int*   mask = (const int*)  d_in[3];
    const float* Wq   = (const float*)d_in[4];
    const float* bq   = (const float*)d_in[5];
    const float* Wk   = (const float*)d_in[6];
    const float* bk   = (const float*)d_in[7];
    const float* Wv   = (const float*)d_in[8];
    const float* bv   = (const float*)d_in[9];
    const float* Wo   = (const float*)d_in[10];
    const float* bo   = (const float*)d_in[11];
    float* out = (float*)d_out;

    float *Qp, *Kp, *Vp, *Op;
    cudaGetSymbolAddress((void**)&Qp, g_Qp);
    cudaGetSymbolAddress((void**)&Kp, g_Kp);
    cudaGetSymbolAddress((void**)&Vp, g_Vp);
    cudaGetSymbolAddress((void**)&Op, g_Op);

    const int smem_flash = 4 * SMTILE * sizeof(float);  // 69632 B
    cudaFuncSetAttribute(flash_attn_k,
                         cudaFuncAttributeMaxDynamicSharedMemorySize, smem_flash);

    dim3 gg(DD / 64, MTOT / 64);   // (16, 64)
    gemm_bias_k<<<gg, 256>>>(q, Wq, bq, Qp);
    gemm_bias_k<<<gg, 256>>>(k, Wk, bk, Kp);
    gemm_bias_k<<<gg, 256>>>(v, Wv, bv, Vp);

    dim3 ga(SSQ / 64, BB * HHD);   // (32, 32)
    flash_attn_k<<<ga, 256, smem_flash>>>(Qp, Kp, Vp, mask, Op);

    gemm_bias_k<<<gg, 256>>>(Op, Wo, bo, out);
}

// round 3
// speedup vs baseline: 2.7410x; 2.7410x over previous
#include <cuda_runtime.h>
#include <cuda_bf16.h>
#include <math.h>
#include <stdint.h>

// Problem dims
#define BB   2
#define SSQ  2048
#define DD   1024
#define HHD  16
#define DKK  64
#define MTOT (BB * SSQ)   // 4096

typedef __nv_bfloat16 bf16;
typedef __nv_bfloat162 bf162;

// ---------------------------------------------------------------------------
// Scratch (__device__ globals; no allocation allowed)
// ---------------------------------------------------------------------------
__device__ bf16 g_Ah[MTOT * DD];
__device__ bf16 g_Al[MTOT * DD];
__device__ bf16 g_Wh[DD * DD];
__device__ bf16 g_Wl[DD * DD];
__device__ bf16 g_Qh[MTOT * DD];
__device__ bf16 g_Ql[MTOT * DD];
__device__ bf16 g_Kh[MTOT * DD];
__device__ bf16 g_Kl[MTOT * DD];
__device__ bf16 g_Vh[MTOT * DD];
__device__ bf16 g_Vl[MTOT * DD];
__device__ bf16 g_Oh[MTOT * DD];
__device__ bf16 g_Ol[MTOT * DD];
__device__ float g_mbias[MTOT];

// ---------------------------------------------------------------------------
// Warp MMA helpers (base PTX: valid on compute_103 target)
// ---------------------------------------------------------------------------
__device__ __forceinline__ uint32_t smem_u32(const void* p) {
    uint32_t a;
    asm("{ .reg .u64 t; cvta.to.shared.u64 t, %1; cvt.u32.u64 %0, t; }"
        : "=r"(a) : "l"(p));
    return a;
}
__device__ __forceinline__ void ldsm4(uint32_t r[4], uint32_t a) {
    asm volatile("ldmatrix.sync.aligned.m8n8.x4.shared.b16 {%0,%1,%2,%3}, [%4];"
                 : "=r"(r[0]), "=r"(r[1]), "=r"(r[2]), "=r"(r[3]) : "r"(a));
}
__device__ __forceinline__ void ldsm4t(uint32_t r[4], uint32_t a) {
    asm volatile("ldmatrix.sync.aligned.m8n8.x4.trans.shared.b16 {%0,%1,%2,%3}, [%4];"
                 : "=r"(r[0]), "=r"(r[1]), "=r"(r[2]), "=r"(r[3]) : "r"(a));
}
__device__ __forceinline__ void mma16816(float* c, const uint32_t* a,
                                         uint32_t b0, uint32_t b1) {
    asm volatile(
        "mma.sync.aligned.m16n8k16.row.col.f32.bf16.bf16.f32 "
        "{%0,%1,%2,%3}, {%4,%5,%6,%7}, {%8,%9}, {%0,%1,%2,%3};"
        : "+f"(c[0]), "+f"(c[1]), "+f"(c[2]), "+f"(c[3])
        : "r"(a[0]), "r"(a[1]), "r"(a[2]), "r"(a[3]), "r"(b0), "r"(b1));
}
__device__ __forceinline__ uint32_t bits(bf162 h) {
    return *reinterpret_cast<uint32_t*>(&h);
}

// ---------------------------------------------------------------------------
// fp32 -> bf16 hi/lo split
// ---------------------------------------------------------------------------
__global__ void split_bf16_k(const float* __restrict__ in,
                             bf16* __restrict__ hi, bf16* __restrict__ lo, int n4)
{
    int i = blockIdx.x * blockDim.x + threadIdx.x;
    int stride = gridDim.x * blockDim.x;
    for (; i < n4; i += stride) {
        float4 v = ((const float4*)in)[i];
        bf16 h0 = __float2bfloat16_rn(v.x), h1 = __float2bfloat16_rn(v.y);
        bf16 h2 = __float2bfloat16_rn(v.z), h3 = __float2bfloat16_rn(v.w);
        bf16 l0 = __float2bfloat16_rn(v.x - __bfloat162float(h0));
        bf16 l1 = __float2bfloat16_rn(v.y - __bfloat162float(h1));
        bf16 l2 = __float2bfloat16_rn(v.z - __bfloat162float(h2));
        bf16 l3 = __float2bfloat16_rn(v.w - __bfloat162float(h3));
        ((bf162*)hi)[2 * i + 0] = bf162(h0, h1);
        ((bf162*)hi)[2 * i + 1] = bf162(h2, h3);
        ((bf162*)lo)[2 * i + 0] = bf162(l0, l1);
        ((bf162*)lo)[2 * i + 1] = bf162(l2, l3);
    }
}

// mask (int 0/1) -> additive bias (-1e9 / 0)
__global__ void mask_bias_k(const int* __restrict__ mask, float* __restrict__ mb)
{
    int i = blockIdx.x * blockDim.x + threadIdx.x;
    if (i < MTOT) mb[i] = mask[i] == 0 ? -1e9f : 0.0f;
}

// ---------------------------------------------------------------------------
// GEMM: C[M,N] = A[M,K] @ W[N,K]^T + bias.  bf16x3 split via mma.sync.
// Block 128x128, BK=32, 256 thr = 8 warps (4 m-warps x 2 n-warps), warp 32x64.
// SPLIT=true: write bf16 hi/lo outputs; else fp32.
// ---------------------------------------------------------------------------
#define GS 40   // smem row stride in halves (80B, 16B-aligned)

template<bool SPLIT>
__global__ __launch_bounds__(256, 2) void gemm_mma(
    const bf16* __restrict__ Ah, const bf16* __restrict__ Al,
    const bf16* __restrict__ Wh, const bf16* __restrict__ Wl,
    const float* __restrict__ bias,
    bf16* __restrict__ Chi, bf16* __restrict__ Clo, float* __restrict__ Cf)
{
    __shared__ __align__(16) bf16 sAh[128 * GS], sAl[128 * GS];
    __shared__ __align__(16) bf16 sBh[128 * GS], sBl[128 * GS];

    const int tid  = threadIdx.x;
    const int lane = tid & 31;
    const int warp = tid >> 5;
    const int wm = warp & 3;          // 0..3
    const int wn = warp >> 2;         // 0..1
    const int bm = blockIdx.y * 128;
    const int bn = blockIdx.x * 128;

    const bf16* gAh = Ah + (size_t)bm * DD;
    const bf16* gAl = Al + (size_t)bm * DD;
    const bf16* gBh = Wh + (size_t)bn * DD;
    const bf16* gBl = Wl + (size_t)bn * DD;

    float acc[2][8][4];
#pragma unroll
    for (int mi = 0; mi < 2; mi++)
#pragma unroll
        for (int nj = 0; nj < 8; nj++)
#pragma unroll
            for (int e = 0; e < 4; e++) acc[mi][nj][e] = 0.0f;

    // per-lane ldmatrix address components
    const int lrA = wm * 32 + (lane & 15);
    const int lcA = (lane >> 4) * 8;
    const int lrB = wn * 64 + ((lane >> 4) & 1) * 8 + (lane & 7);
    const int lcB = ((lane >> 3) & 1) * 8;
    const uint32_t bAh = smem_u32(sAh), bAl = smem_u32(sAl);
    const uint32_t bBh = smem_u32(sBh), bBl = smem_u32(sBl);

    for (int k0 = 0; k0 < DD; k0 += 32) {
        __syncthreads();
#pragma unroll
        for (int i = tid; i < 512; i += 256) {
            int r = i >> 2, c4 = i & 3;
            size_t go = (size_t)r * DD + k0 + c4 * 8;
            int so = r * GS + c4 * 8;
            *(uint4*)&sAh[so] = *(const uint4*)&gAh[go];
            *(uint4*)&sAl[so] = *(const uint4*)&gAl[go];
            *(uint4*)&sBh[so] = *(const uint4*)&gBh[go];
            *(uint4*)&sBl[so] = *(const uint4*)&gBl[go];
        }
        __syncthreads();

#pragma unroll
        for (int kb = 0; kb < 2; kb++) {
            uint32_t ah[2][4], al[2][4];
#pragma unroll
            for (int mi = 0; mi < 2; mi++) {
                uint32_t off = ((lrA + mi * 16) * GS + kb * 16 + lcA) * 2;
                ldsm4(ah[mi], bAh + off);
                ldsm4(al[mi], bAl + off);
            }
#pragma unroll
            for (int njp = 0; njp < 4; njp++) {
                uint32_t off = ((lrB + njp * 16) * GS + kb * 16 + lcB) * 2;
                uint32_t bh[4], bl[4];
                ldsm4(bh, bBh + off);
                ldsm4(bl, bBl + off);
#pragma unroll
                for (int mi = 0; mi < 2; mi++) {
                    float* c0 = acc[mi][njp * 2];
                    float* c1 = acc[mi][njp * 2 + 1];
                    mma16816(c0, ah[mi], bh[0], bh[1]);
                    mma16816(c0, ah[mi], bl[0], bl[1]);
                    mma16816(c0, al[mi], bh[0], bh[1]);
                    mma16816(c1, ah[mi], bh[2], bh[3]);
                    mma16816(c1, ah[mi], bl[2], bl[3]);
                    mma16816(c1, al[mi], bh[2], bh[3]);
                }
            }
        }
    }

    const int g = lane >> 2, c = lane & 3;
#pragma unroll
    for (int mi = 0; mi < 2; mi++) {
#pragma unroll
        for (int nj = 0; nj < 8; nj++) {
            int row = bm + wm * 32 + mi * 16 + g;
            int col = bn + wn * 64 + nj * 8 + c * 2;
            float b0 = bias[col], b1 = bias[col + 1];
            float x0 = acc[mi][nj][0] + b0, x1 = acc[mi][nj][1] + b1;
            float x2 = acc[mi][nj][2] + b0, x3 = acc[mi][nj][3] + b1;
            if (SPLIT) {
                bf162 h01 = __float22bfloat162_rn(make_float2(x0, x1));
                bf162 h23 = __float22bfloat162_rn(make_float2(x2, x3));
                bf162 l01 = __float22bfloat162_rn(make_float2(
                    x0 - __low2float(h01), x1 - __high2float(h01)));
                bf162 l23 = __float22bfloat162_rn(make_float2(
                    x2 - __low2float(h23), x3 - __high2float(h23)));
                *(bf162*)&Chi[(size_t)row * DD + col] = h01;
                *(bf162*)&Clo[(size_t)row * DD + col] = l01;
                *(bf162*)&Chi[(size_t)(row + 8) * DD + col] = h23;
                *(bf162*)&Clo[(size_t)(row + 8) * DD + col] = l23;
            } else {
                *(float2*)&Cf[(size_t)row * DD + col] = make_float2(x0, x1);
                *(float2*)&Cf[(size_t)(row + 8) * DD + col] = make_float2(x2, x3);
            }
        }
    }
}

// ---------------------------------------------------------------------------
// Flash attention via mma.sync, bf16x3 split. CTA: (b,h) x 128 q-rows.
// 8 warps, each owns 16 q-rows. KV tiles of 64.
// ---------------------------------------------------------------------------
#define AS 72   // smem row stride halves (144B)

__global__ __launch_bounds__(256) void flash_mma_k(
    const bf16* __restrict__ Qh, const bf16* __restrict__ Ql,
    const bf16* __restrict__ Kh, const bf16* __restrict__ Kl,
    const bf16* __restrict__ Vh, const bf16* __restrict__ Vl,
    const float* __restrict__ mb,
    bf16* __restrict__ Oh, bf16* __restrict__ Ol)
{
    // Q phase: 2 x (128 x AS); KV phase: 4 x (64 x AS). Both = 18432 halves.
    __shared__ __align__(16) bf16 smb[4 * 64 * AS];
    __shared__ float sBias[64];

    bf16* sQh = smb;
    bf16* sQl = smb + 128 * AS;
    bf16* sKh = smb;
    bf16* sKl = smb + 64 * AS;
    bf16* sVh = smb + 2 * 64 * AS;
    bf16* sVl = smb + 3 * 64 * AS;

    const int tid  = threadIdx.x;
    const int lane = tid & 31;
    const int w    = tid >> 5;
    const int b  = blockIdx.y >> 4;
    const int h  = blockIdx.y & 15;
    const int q0 = blockIdx.x * 128;
    const int g = lane >> 2, c = lane & 3;

    // ---- Phase 1: load Q tile, build A-fragments ----
    {
        const bf16* gQh = Qh + (size_t)(b * SSQ + q0) * DD + h * DKK;
        const bf16* gQl = Ql + (size_t)(b * SSQ + q0) * DD + h * DKK;
#pragma unroll
        for (int i = tid; i < 1024; i += 256) {
            int r = i >> 3, c8 = i & 7;
            size_t go = (size_t)r * DD + c8 * 8;
            int so = r * AS + c8 * 8;
            *(uint4*)&sQh[so] = *(const uint4*)&gQh[go];
            *(uint4*)&sQl[so] = *(const uint4*)&gQl[go];
        }
    }
    __syncthreads();

    uint32_t qh[4][4], ql[4][4];
    {
        const int lrQ = w * 16 + (lane & 15);
        const int lcQ = (lane >> 4) * 8;
        uint32_t bQh = smem_u32(sQh), bQl = smem_u32(sQl);
#pragma unroll
        for (int kb = 0; kb < 4; kb++) {
            uint32_t off = (lrQ * AS + kb * 16 + lcQ) * 2;
            ldsm4(qh[kb], bQh + off);
            ldsm4(ql[kb], bQl + off);
        }
    }
    __syncthreads();   // done with Q smem

    float m0 = -INFINITY, m1 = -INFINITY, l0 = 0.0f, l1 = 0.0f;
    float acc[8][4];
#pragma unroll
    for (int on = 0; on < 8; on++)
#pragma unroll
        for (int e = 0; e < 4; e++) acc[on][e] = 0.0f;

    const int lrK = ((lane >> 4) & 1) * 8 + (lane & 7);
    const int lcK = ((lane >> 3) & 1) * 8;
    const int lrV = ((lane >> 3) & 1) * 8 + (lane & 7);
    const int lcV = (lane >> 4) * 8;
    const uint32_t bKh = smem_u32(sKh), bKl = smem_u32(sKl);
    const uint32_t bVh = smem_u32(sVh), bVl = smem_u32(sVl);
    const float scale = 0.125f;   // 1/sqrt(64)

    for (int kv0 = 0; kv0 < SSQ; kv0 += 64) {
        __syncthreads();
        {
            size_t base = (size_t)(b * SSQ + kv0) * DD + h * DKK;
#pragma unroll
            for (int i = tid; i < 512; i += 256) {
                int r = i >> 3, c8 = i & 7;
                size_t go = base + (size_t)r * DD + c8 * 8;
                int so = r * AS + c8 * 8;
                *(uint4*)&sKh[so] = *(const uint4*)&Kh[go];
                *(uint4*)&sKl[so] = *(const uint4*)&Kl[go];
                *(uint4*)&sVh[so] = *(const uint4*)&Vh[go];
                *(uint4*)&sVl[so] = *(const uint4*)&Vl[go];
            }
            if (tid < 16)
                *(float4*)&sBias[tid * 4] =
                    *(const float4*)&mb[b * SSQ + kv0 + tid * 4];
        }
        __syncthreads();

        // ---- S = Q K^T ----
        float s[8][4];
#pragma unroll
        for (int nj = 0; nj < 8; nj++)
#pragma unroll
            for (int e = 0; e < 4; e++) s[nj][e] = 0.0f;

#pragma unroll
        for (int kb = 0; kb < 4; kb++) {
#pragma unroll
            for (int njp = 0; njp < 4; njp++) {
                uint32_t off = ((njp * 16 + lrK) * AS + kb * 16 + lcK) * 2;
                uint32_t kh[4], kl[4];
                ldsm4(kh, bKh + off);
                ldsm4(kl, bKl + off);
                float* c0 = s[njp * 2];
                float* c1 = s[njp * 2 + 1];
                mma16816(c0, qh[kb], kh[0], kh[1]);
                mma16816(c0, qh[kb], kl[0], kl[1]);
                mma16816(c0, ql[kb], kh[0], kh[1]);
                mma16816(c1, qh[kb], kh[2], kh[3]);
                mma16816(c1, qh[kb], kl[2], kl[3]);
                mma16816(c1, ql[kb], kh[2], kh[3]);
            }
        }

        // ---- scale + mask bias ----
#pragma unroll
        for (int nj = 0; nj < 8; nj++) {
            float b0 = sBias[nj * 8 + c * 2];
            float b1 = sBias[nj * 8 + c * 2 + 1];
            s[nj][0] = fmaf(s[nj][0], scale, b0);
            s[nj][1] = fmaf(s[nj][1], scale, b1);
            s[nj][2] = fmaf(s[nj][2], scale, b0);
            s[nj][3] = fmaf(s[nj][3], scale, b1);
        }

        // ---- online softmax (rows g and g+8) ----
        float mx0 = -INFINITY, mx1 = -INFINITY;
#pragma unroll
        for (int nj = 0; nj < 8; nj++) {
            mx0 = fmaxf(mx0, fmaxf(s[nj][0], s[nj][1]));
            mx1 = fmaxf(mx1, fmaxf(s[nj][2], s[nj][3]));
        }
        mx0 = fmaxf(mx0, __shfl_xor_sync(0xffffffffu, mx0, 1));
        mx0 = fmaxf(mx0, __shfl_xor_sync(0xffffffffu, mx0, 2));
        mx1 = fmaxf(mx1, __shfl_xor_sync(0xffffffffu, mx1, 1));
        mx1 = fmaxf(mx1, __shfl_xor_sync(0xffffffffu, mx1, 2));
        float mn0 = fmaxf(m0, mx0), mn1 = fmaxf(m1, mx1);
        float f0 = __expf(m0 - mn0), f1 = __expf(m1 - mn1);
        m0 = mn0; m1 = mn1;

        float sum0 = 0.0f, sum1 = 0.0f;
#pragma unroll
        for (int nj = 0; nj < 8; nj++) {
            s[nj][0] = __expf(s[nj][0] - m0);
            s[nj][1] = __expf(s[nj][1] - m0);
            s[nj][2] = __expf(s[nj][2] - m1);
            s[nj][3] = __expf(s[nj][3] - m1);
            sum0 += s[nj][0] + s[nj][1];
            sum1 += s[nj][2] + s[nj][3];
        }
        sum0 += __shfl_xor_sync(0xffffffffu, sum0, 1);
        sum0 += __shfl_xor_sync(0xffffffffu, sum0, 2);
        sum1 += __shfl_xor_sync(0xffffffffu, sum1, 1);
        sum1 += __shfl_xor_sync(0xffffffffu, sum1, 2);
        l0 = l0 * f0 + sum0;
        l1 = l1 * f1 + sum1;
#pragma unroll
        for (int on = 0; on < 8; on++) {
            acc[on][0] *= f0; acc[on][1] *= f0;
            acc[on][2] *= f1; acc[on][3] *= f1;
        }

        // ---- O += P V : P from S frags (C-frag == A-frag layout) ----
#pragma unroll
        for (int kb2 = 0; kb2 < 4; kb2++) {
            uint32_t pah[4], pal[4];
#pragma unroll
            for (int q2 = 0; q2 < 2; q2++) {
                float* sp = s[2 * kb2 + q2];
                bf162 h01 = __float22bfloat162_rn(make_float2(sp[0], sp[1]));
                bf162 h23 = __float22bfloat162_rn(make_float2(sp[2], sp[3]));
                bf162 l01 = __float22bfloat162_rn(make_float2(
                    sp[0] - __low2float(h01), sp[1] - __high2float(h01)));
                bf162 l23 = __float22bfloat162_rn(make_float2(
                    sp[2] - __low2float(h23), sp[3] - __high2float(h23)));
                pah[q2 * 2] = bits(h01); pah[q2 * 2 + 1] = bits(h23);
                pal[q2 * 2] = bits(l01); pal[q2 * 2 + 1] = bits(l23);
            }
#pragma unroll
            for (int onp = 0; onp < 4; onp++) {
                uint32_t off = ((kb2 * 16 + lrV) * AS + onp * 16 + lcV) * 2;
                uint32_t vh[4], vl[4];
                ldsm4t(vh, bVh + off);
                ldsm4t(vl, bVl + off);
                float* c0 = acc[onp * 2];
                float* c1 = acc[onp * 2 + 1];
                mma16816(c0, pah, vh[0], vh[1]);
                mma16816(c0, pah, vl[0], vl[1]);
                mma16816(c0, pal, vh[0], vh[1]);
                mma16816(c1, pah, vh[2], vh[3]);
                mma16816(c1, pah, vl[2], vl[3]);
                mma16816(c1, pal, vh[2], vh[3]);
            }
        }
    }

    // ---- epilogue: normalize, split to bf16 hi/lo ----
    float inv0 = 1.0f / l0, inv1 = 1.0f / l1;
    int rowg = b * SSQ + q0 + w * 16 + g;
#pragma unroll
    for (int on = 0; on < 8; on++) {
        int col = h * DKK + on * 8 + c * 2;
        float x0 = acc[on][0] * inv0, x1 = acc[on][1] * inv0;
        float x2 = acc[on][2] * inv1, x3 = acc[on][3] * inv1;
        bf162 h01 = __float22bfloat162_rn(make_float2(x0, x1));
        bf162 h23 = __float22bfloat162_rn(make_float2(x2, x3));
        bf162 l01 = __float22bfloat162_rn(make_float2(
            x0 - __low2float(h01), x1 - __high2float(h01)));
        bf162 l23 = __float22bfloat162_rn(make_float2(
            x2 - __low2float(h23), x3 - __high2float(h23)));
        *(bf162*)&Oh[(size_t)rowg * DD + col] = h01;
        *(bf162*)&Ol[(size_t)rowg * DD + col] = l01;
        *(bf162*)&Oh[(size_t)(rowg + 8) * DD + col] = h23;
        *(bf162*)&Ol[(size_t)(rowg + 8) * DD + col] = l23;
    }
}

// ---------------------------------------------------------------------------
// Launch
// ---------------------------------------------------------------------------
extern "C" void kernel_launch(void* const* d_in, const int* in_sizes, int n_in,
                              void* d_out, int out_size)
{
    const float* q    = (const float*)d_in[0];
    const float* k    = (const float*)d_in[1];
    const float* v    = (const float*)d_in[2];
    const int*   mask = (const int*)  d_in[3];
    const float* Wq   = (const float*)d_in[4];
    const float* bq   = (const float*)d_in[5];
    const float* Wk   = (const float*)d_in[6];
    const float* bk   = (const float*)d_in[7];
    const float* Wv   = (const float*)d_in[8];
    const float* bv   = (const float*)d_in[9];
    const float* Wo   = (const float*)d_in[10];
    const float* bo   = (const float*)d_in[11];
    float* out = (float*)d_out;

    bf16 *Ah, *Al, *Wh, *Wl, *Qh, *Ql, *Kh, *Kl, *Vh, *Vl, *Oh, *Ol;
    float* mb;
    cudaGetSymbolAddress((void**)&Ah, g_Ah);
    cudaGetSymbolAddress((void**)&Al, g_Al);
    cudaGetSymbolAddress((void**)&Wh, g_Wh);
    cudaGetSymbolAddress((void**)&Wl, g_Wl);
    cudaGetSymbolAddress((void**)&Qh, g_Qh);
    cudaGetSymbolAddress((void**)&Ql, g_Ql);
    cudaGetSymbolAddress((void**)&Kh, g_Kh);
    cudaGetSymbolAddress((void**)&Kl, g_Kl);
    cudaGetSymbolAddress((void**)&Vh, g_Vh);
    cudaGetSymbolAddress((void**)&Vl, g_Vl);
    cudaGetSymbolAddress((void**)&Oh, g_Oh);
    cudaGetSymbolAddress((void**)&Ol, g_Ol);
    cudaGetSymbolAddress((void**)&mb, g_mbias);

    const int nA4 = MTOT * DD / 4;
    const int nW4 = DD * DD / 4;
    dim3 gg(DD / 128, MTOT / 128);   // (8, 32)

    // Q projection
    split_bf16_k<<<1024, 256>>>(q, Ah, Al, nA4);
    split_bf16_k<<<512, 256>>>(Wq, Wh, Wl, nW4);
    gemm_mma<true><<<gg, 256>>>(Ah, Al, Wh, Wl, bq, Qh, Ql, nullptr);
    // K projection
    split_bf16_k<<<1024, 256>>>(k, Ah, Al, nA4);
    split_bf16_k<<<512, 256>>>(Wk, Wh, Wl, nW4);
    gemm_mma<true><<<gg, 256>>>(Ah, Al, Wh, Wl, bk, Kh, Kl, nullptr);
    // V projection
    split_bf16_k<<<1024, 256>>>(v, Ah, Al, nA4);
    split_bf16_k<<<512, 256>>>(Wv, Wh, Wl, nW4);
    gemm_mma<true><<<gg, 256>>>(Ah, Al, Wh, Wl, bv, Vh, Vl, nullptr);

    // mask bias
    mask_bias_k<<<(MTOT + 255) / 256, 256>>>(mask, mb);

    // attention
    dim3 ga(SSQ / 128, BB * HHD);    // (16, 32)
    flash_mma_k<<<ga, 256>>>(Qh, Ql, Kh, Kl, Vh, Vl, mb, Oh, Ol);

    // output projection (fp32 out)
    split_bf16_k<<<512, 256>>>(Wo, Wh, Wl, nW4);
    gemm_mma<false><<<gg, 256>>>(Oh, Ol, Wh, Wl, bo, nullptr, nullptr, out);
}

// round 4
// speedup vs baseline: 2.8789x; 1.0503x over previous
#include <cuda_runtime.h>
#include <cuda_bf16.h>
#include <math.h>
#include <stdint.h>

// Problem dims
#define BB   2
#define SSQ  2048
#define DD   1024
#define HHD  16
#define DKK  64
#define MTOT (BB * SSQ)   // 4096

typedef __nv_bfloat16 bf16;
typedef __nv_bfloat162 bf162;

// ---------------------------------------------------------------------------
// Scratch (__device__ globals; no allocation allowed)
// ---------------------------------------------------------------------------
__device__ bf16 g_Ah[MTOT * DD];
__device__ bf16 g_Al[MTOT * DD];
__device__ bf16 g_Wh[DD * DD];
__device__ bf16 g_Wl[DD * DD];
__device__ bf16 g_Qh[MTOT * DD];
__device__ bf16 g_Ql[MTOT * DD];
__device__ bf16 g_Kh[MTOT * DD];
__device__ bf16 g_Kl[MTOT * DD];
__device__ bf16 g_Vh[MTOT * DD];
__device__ bf16 g_Vl[MTOT * DD];
__device__ bf16 g_Oh[MTOT * DD];
__device__ bf16 g_Ol[MTOT * DD];
__device__ float g_mbias[MTOT];

// ---------------------------------------------------------------------------
// PTX helpers (base-ISA features only: valid on compute_103 target)
// ---------------------------------------------------------------------------
__device__ __forceinline__ uint32_t smem_u32(const void* p) {
    uint32_t a;
    asm("{ .reg .u64 t; cvta.to.shared.u64 t, %1; cvt.u32.u64 %0, t; }"
        : "=r"(a) : "l"(p));
    return a;
}
__device__ __forceinline__ void ldsm4(uint32_t r[4], uint32_t a) {
    asm volatile("ldmatrix.sync.aligned.m8n8.x4.shared.b16 {%0,%1,%2,%3}, [%4];"
                 : "=r"(r[0]), "=r"(r[1]), "=r"(r[2]), "=r"(r[3]) : "r"(a));
}
__device__ __forceinline__ void ldsm4t(uint32_t r[4], uint32_t a) {
    asm volatile("ldmatrix.sync.aligned.m8n8.x4.trans.shared.b16 {%0,%1,%2,%3}, [%4];"
                 : "=r"(r[0]), "=r"(r[1]), "=r"(r[2]), "=r"(r[3]) : "r"(a));
}
__device__ __forceinline__ void mma16816(float* c, const uint32_t* a,
                                         uint32_t b0, uint32_t b1) {
    asm volatile(
        "mma.sync.aligned.m16n8k16.row.col.f32.bf16.bf16.f32 "
        "{%0,%1,%2,%3}, {%4,%5,%6,%7}, {%8,%9}, {%0,%1,%2,%3};"
        : "+f"(c[0]), "+f"(c[1]), "+f"(c[2]), "+f"(c[3])
        : "r"(a[0]), "r"(a[1]), "r"(a[2]), "r"(a[3]), "r"(b0), "r"(b1));
}
__device__ __forceinline__ uint32_t bits(bf162 h) {
    return *reinterpret_cast<uint32_t*>(&h);
}
#define CP16(dst, src) \
    asm volatile("cp.async.cg.shared.global [%0], [%1], 16;" \
                 :: "r"(dst), "l"(src) : "memory")
#define CPCOMMIT() asm volatile("cp.async.commit_group;" ::: "memory")
#define CPWAIT1()  asm volatile("cp.async.wait_group 1;" ::: "memory")
#define CPWAIT0()  asm volatile("cp.async.wait_group 0;" ::: "memory")

// ---------------------------------------------------------------------------
// fp32 -> bf16 hi/lo split
// ---------------------------------------------------------------------------
__global__ void split_bf16_k(const float* __restrict__ in,
                             bf16* __restrict__ hi, bf16* __restrict__ lo, int n4)
{
    int i = blockIdx.x * blockDim.x + threadIdx.x;
    int stride = gridDim.x * blockDim.x;
    for (; i < n4; i += stride) {
        float4 v = ((const float4*)in)[i];
        bf16 h0 = __float2bfloat16_rn(v.x), h1 = __float2bfloat16_rn(v.y);
        bf16 h2 = __float2bfloat16_rn(v.z), h3 = __float2bfloat16_rn(v.w);
        bf16 l0 = __float2bfloat16_rn(v.x - __bfloat162float(h0));
        bf16 l1 = __float2bfloat16_rn(v.y - __bfloat162float(h1));
        bf16 l2 = __float2bfloat16_rn(v.z - __bfloat162float(h2));
        bf16 l3 = __float2bfloat16_rn(v.w - __bfloat162float(h3));
        ((bf162*)hi)[2 * i + 0] = bf162(h0, h1);
        ((bf162*)hi)[2 * i + 1] = bf162(h2, h3);
        ((bf162*)lo)[2 * i + 0] = bf162(l0, l1);
        ((bf162*)lo)[2 * i + 1] = bf162(l2, l3);
    }
}

__global__ void mask_bias_k(const int* __restrict__ mask, float* __restrict__ mb)
{
    int i = blockIdx.x * blockDim.x + threadIdx.x;
    if (i < MTOT) mb[i] = mask[i] == 0 ? -1e9f : 0.0f;
}

// ---------------------------------------------------------------------------
// GEMM: C[M,N] = A[M,K] @ W[N,K]^T + bias.  bf16x3, cp.async 2-stage pipeline.
// Block 128x128, BK=32, 8 warps (4 m x 2 n), warp 32x64.
// ---------------------------------------------------------------------------
#define GS 40                         // smem row stride in halves (80B = 5*16B)
#define GT_TILEB  (128 * GS * 2)      // 10240 B per operand tile
#define GT_STAGEB (4 * GT_TILEB)      // 40960 B per stage
#define GT_SMEM   (2 * GT_STAGEB)     // 81920 B

__device__ __forceinline__ void gemm_stage_load(
    uint32_t sbase, const bf16* __restrict__ gAh, const bf16* __restrict__ gAl,
    const bf16* __restrict__ gBh, const bf16* __restrict__ gBl,
    int k0, int tid)
{
#pragma unroll
    for (int i = tid; i < 512; i += 256) {
        int r = i >> 2, c4 = i & 3;
        size_t go = (size_t)r * DD + k0 + c4 * 8;
        uint32_t so = (uint32_t)(r * GS + c4 * 8) * 2;
        CP16(sbase + so,                gAh + go);
        CP16(sbase + GT_TILEB + so,     gAl + go);
        CP16(sbase + 2 * GT_TILEB + so, gBh + go);
        CP16(sbase + 3 * GT_TILEB + so, gBl + go);
    }
}

template<bool SPLIT>
__global__ __launch_bounds__(256, 2) void gemm_mma(
    const bf16* __restrict__ Ah, const bf16* __restrict__ Al,
    const bf16* __restrict__ Wh, const bf16* __restrict__ Wl,
    const float* __restrict__ bias,
    bf16* __restrict__ Chi, bf16* __restrict__ Clo, float* __restrict__ Cf)
{
    extern __shared__ __align__(16) char dyn[];
    const uint32_t sb = smem_u32(dyn);

    const int tid  = threadIdx.x;
    const int lane = tid & 31;
    const int warp = tid >> 5;
    const int wm = warp & 3;
    const int wn = warp >> 2;
    const int bm = blockIdx.y * 128;
    const int bn = blockIdx.x * 128;

    const bf16* gAh = Ah + (size_t)bm * DD;
    const bf16* gAl = Al + (size_t)bm * DD;
    const bf16* gBh = Wh + (size_t)bn * DD;
    const bf16* gBl = Wl + (size_t)bn * DD;

    float acc[2][8][4];
#pragma unroll
    for (int mi = 0; mi < 2; mi++)
#pragma unroll
        for (int nj = 0; nj < 8; nj++)
#pragma unroll
            for (int e = 0; e < 4; e++) acc[mi][nj][e] = 0.0f;

    const int lrA = wm * 32 + (lane & 15);
    const int lcA = (lane >> 4) * 8;
    const int lrB = wn * 64 + ((lane >> 4) & 1) * 8 + (lane & 7);
    const int lcB = ((lane >> 3) & 1) * 8;

    // prologue
    gemm_stage_load(sb, gAh, gAl, gBh, gBl, 0, tid);
    CPCOMMIT();

    for (int t = 0; t < 32; ++t) {
        const int st = t & 1;
        if (t < 31) {
            gemm_stage_load(sb + (st ^ 1) * GT_STAGEB, gAh, gAl, gBh, gBl,
                            (t + 1) * 32, tid);
            CPCOMMIT();
            CPWAIT1();
        } else {
            CPWAIT0();
        }
        __syncthreads();

        const uint32_t bAh = sb + st * GT_STAGEB;
        const uint32_t bAl = bAh + GT_TILEB;
        const uint32_t bBh = bAh + 2 * GT_TILEB;
        const uint32_t bBl = bAh + 3 * GT_TILEB;

#pragma unroll
        for (int kb = 0; kb < 2; kb++) {
            uint32_t ah[2][4], al[2][4];
#pragma unroll
            for (int mi = 0; mi < 2; mi++) {
                uint32_t off = ((lrA + mi * 16) * GS + kb * 16 + lcA) * 2;
                ldsm4(ah[mi], bAh + off);
                ldsm4(al[mi], bAl + off);
            }
#pragma unroll
            for (int njp = 0; njp < 4; njp++) {
                uint32_t off = ((lrB + njp * 16) * GS + kb * 16 + lcB) * 2;
                uint32_t bh[4], bl[4];
                ldsm4(bh, bBh + off);
                ldsm4(bl, bBl + off);
#pragma unroll
                for (int mi = 0; mi < 2; mi++) {
                    float* c0 = acc[mi][njp * 2];
                    float* c1 = acc[mi][njp * 2 + 1];
                    mma16816(c0, ah[mi], bh[0], bh[1]);
                    mma16816(c0, ah[mi], bl[0], bl[1]);
                    mma16816(c0, al[mi], bh[0], bh[1]);
                    mma16816(c1, ah[mi], bh[2], bh[3]);
                    mma16816(c1, ah[mi], bl[2], bl[3]);
                    mma16816(c1, al[mi], bh[2], bh[3]);
                }
            }
        }
        __syncthreads();
    }

    const int g = lane >> 2, c = lane & 3;
#pragma unroll
    for (int mi = 0; mi < 2; mi++) {
#pragma unroll
        for (int nj = 0; nj < 8; nj++) {
            int row = bm + wm * 32 + mi * 16 + g;
            int col = bn + wn * 64 + nj * 8 + c * 2;
            float b0 = bias[col], b1 = bias[col + 1];
            float x0 = acc[mi][nj][0] + b0, x1 = acc[mi][nj][1] + b1;
            float x2 = acc[mi][nj][2] + b0, x3 = acc[mi][nj][3] + b1;
            if (SPLIT) {
                bf162 h01 = __float22bfloat162_rn(make_float2(x0, x1));
                bf162 h23 = __float22bfloat162_rn(make_float2(x2, x3));
                bf162 l01 = __float22bfloat162_rn(make_float2(
                    x0 - __low2float(h01), x1 - __high2float(h01)));
                bf162 l23 = __float22bfloat162_rn(make_float2(
                    x2 - __low2float(h23), x3 - __high2float(h23)));
                *(bf162*)&Chi[(size_t)row * DD + col] = h01;
                *(bf162*)&Clo[(size_t)row * DD + col] = l01;
                *(bf162*)&Chi[(size_t)(row + 8) * DD + col] = h23;
                *(bf162*)&Clo[(size_t)(row + 8) * DD + col] = l23;
            } else {
                *(float2*)&Cf[(size_t)row * DD + col] = make_float2(x0, x1);
                *(float2*)&Cf[(size_t)(row + 8) * DD + col] = make_float2(x2, x3);
            }
        }
    }
}

// ---------------------------------------------------------------------------
// Flash attention via mma.sync, bf16x3, cp.async 2-stage KV pipeline.
// CTA: (b,h) x 128 q-rows, 8 warps x 16 q-rows, KV tiles of 64.
// ---------------------------------------------------------------------------
#define AS 72                          // smem row stride halves (144B = 9*16B)
#define AT_TILEB  (64 * AS * 2)        // 9216 B per operand tile
#define AT_STAGEB (4 * AT_TILEB)       // 36864 B per stage
#define AT_SMEM   (2 * AT_STAGEB)      // 73728 B

__device__ __forceinline__ void att_stage_load(
    uint32_t sbase, const bf16* __restrict__ Kh, const bf16* __restrict__ Kl,
    const bf16* __restrict__ Vh, const bf16* __restrict__ Vl,
    size_t gbase, int tid)
{
#pragma unroll
    for (int i = tid; i < 512; i += 256) {
        int r = i >> 3, c8 = i & 7;
        size_t go = gbase + (size_t)r * DD + c8 * 8;
        uint32_t so = (uint32_t)(r * AS + c8 * 8) * 2;
        CP16(sbase + so,                Kh + go);
        CP16(sbase + AT_TILEB + so,     Kl + go);
        CP16(sbase + 2 * AT_TILEB + so, Vh + go);
        CP16(sbase + 3 * AT_TILEB + so, Vl + go);
    }
}

__global__ __launch_bounds__(256) void flash_mma_k(
    const bf16* __restrict__ Qh, const bf16* __restrict__ Ql,
    const bf16* __restrict__ Kh, const bf16* __restrict__ Kl,
    const bf16* __restrict__ Vh, const bf16* __restrict__ Vl,
    const float* __restrict__ mb,
    bf16* __restrict__ Oh, bf16* __restrict__ Ol)
{
    extern __shared__ __align__(16) char dyn[];
    __shared__ __align__(16) float sBias[2][64];
    const uint32_t sb = smem_u32(dyn);
    const uint32_t sbias_u32 = smem_u32(&sBias[0][0]);

    const int tid  = threadIdx.x;
    const int lane = tid & 31;
    const int w    = tid >> 5;
    const int b  = blockIdx.y >> 4;
    const int h  = blockIdx.y & 15;
    const int q0 = blockIdx.x * 128;
    const int g = lane >> 2, c = lane & 3;

    // ---- Phase 1: load Q tile into stage-0 area, build fragments ----
    {
        bf16* sQh = (bf16*)dyn;
        bf16* sQl = (bf16*)(dyn + 128 * AS * 2);
        const bf16* gQh = Qh + (size_t)(b * SSQ + q0) * DD + h * DKK;
        const bf16* gQl = Ql + (size_t)(b * SSQ + q0) * DD + h * DKK;
#pragma unroll
        for (int i = tid; i < 1024; i += 256) {
            int r = i >> 3, c8 = i & 7;
            size_t go = (size_t)r * DD + c8 * 8;
            int so = r * AS + c8 * 8;
            *(uint4*)&sQh[so] = *(const uint4*)&gQh[go];
            *(uint4*)&sQl[so] = *(const uint4*)&gQl[go];
        }
    }
    __syncthreads();

    uint32_t qh[4][4], ql[4][4];
    {
        const int lrQ = w * 16 + (lane & 15);
        const int lcQ = (lane >> 4) * 8;
        const uint32_t bQh = sb;
        const uint32_t bQl = sb + 128 * AS * 2;
#pragma unroll
        for (int kb = 0; kb < 4; kb++) {
            uint32_t off = (lrQ * AS + kb * 16 + lcQ) * 2;
            ldsm4(qh[kb], bQh + off);
            ldsm4(ql[kb], bQl + off);
        }
    }
    __syncthreads();   // Q smem free for KV stages

    float m0 = -INFINITY, m1 = -INFINITY, l0 = 0.0f, l1 = 0.0f;
    float acc[8][4];
#pragma unroll
    for (int on = 0; on < 8; on++)
#pragma unroll
        for (int e = 0; e < 4; e++) acc[on][e] = 0.0f;

    const int lrK = ((lane >> 4) & 1) * 8 + (lane & 7);
    const int lcK = ((lane >> 3) & 1) * 8;
    const int lrV = ((lane >> 3) & 1) * 8 + (lane & 7);
    const int lcV = (lane >> 4) * 8;
    const float scale = 0.125f;
    const size_t gKV0 = (size_t)(b * SSQ) * DD + h * DKK;

    // prologue: stage 0 <- kv tile 0
    att_stage_load(sb, Kh, Kl, Vh, Vl, gKV0, tid);
    if (tid < 16) CP16(sbias_u32 + tid * 16, &mb[b * SSQ + tid * 4]);
    CPCOMMIT();

    for (int t = 0; t < 32; ++t) {
        const int st = t & 1;
        if (t < 31) {
            att_stage_load(sb + (st ^ 1) * AT_STAGEB, Kh, Kl, Vh, Vl,
                           gKV0 + (size_t)(t + 1) * 64 * DD, tid);
            if (tid < 16)
                CP16(sbias_u32 + (st ^ 1) * 256 + tid * 16,
                     &mb[b * SSQ + (t + 1) * 64 + tid * 4]);
            CPCOMMIT();
            CPWAIT1();
        } else {
            CPWAIT0();
        }
        __syncthreads();

        const uint32_t bKh = sb + st * AT_STAGEB;
        const uint32_t bKl = bKh + AT_TILEB;
        const uint32_t bVh = bKh + 2 * AT_TILEB;
        const uint32_t bVl = bKh + 3 * AT_TILEB;

        // ---- S = Q K^T ----
        float s[8][4];
#pragma unroll
        for (int nj = 0; nj < 8; nj++)
#pragma unroll
            for (int e = 0; e < 4; e++) s[nj][e] = 0.0f;

#pragma unroll
        for (int kb = 0; kb < 4; kb++) {
#pragma unroll
            for (int njp = 0; njp < 4; njp++) {
                uint32_t off = ((njp * 16 + lrK) * AS + kb * 16 + lcK) * 2;
                uint32_t kh[4], kl[4];
                ldsm4(kh, bKh + off);
                ldsm4(kl, bKl + off);
                float* c0 = s[njp * 2];
                float* c1 = s[njp * 2 + 1];
                mma16816(c0, qh[kb], kh[0], kh[1]);
                mma16816(c0, qh[kb], kl[0], kl[1]);
                mma16816(c0, ql[kb], kh[0], kh[1]);
                mma16816(c1, qh[kb], kh[2], kh[3]);
                mma16816(c1, qh[kb], kl[2], kl[3]);
                mma16816(c1, ql[kb], kh[2], kh[3]);
            }
        }

        // ---- scale + mask bias ----
#pragma unroll
        for (int nj = 0; nj < 8; nj++) {
            float b0 = sBias[st][nj * 8 + c * 2];
            float b1 = sBias[st][nj * 8 + c * 2 + 1];
            s[nj][0] = fmaf(s[nj][0], scale, b0);
            s[nj][1] = fmaf(s[nj][1], scale, b1);
            s[nj][2] = fmaf(s[nj][2], scale, b0);
            s[nj][3] = fmaf(s[nj][3], scale, b1);
        }

        // ---- online softmax ----
        float mx0 = -INFINITY, mx1 = -INFINITY;
#pragma unroll
        for (int nj = 0; nj < 8; nj++) {
            mx0 = fmaxf(mx0, fmaxf(s[nj][0], s[nj][1]));
            mx1 = fmaxf(mx1, fmaxf(s[nj][2], s[nj][3]));
        }
        mx0 = fmaxf(mx0, __shfl_xor_sync(0xffffffffu, mx0, 1));
        mx0 = fmaxf(mx0, __shfl_xor_sync(0xffffffffu, mx0, 2));
        mx1 = fmaxf(mx1, __shfl_xor_sync(0xffffffffu, mx1, 1));
        mx1 = fmaxf(mx1, __shfl_xor_sync(0xffffffffu, mx1, 2));
        float mn0 = fmaxf(m0, mx0), mn1 = fmaxf(m1, mx1);
        float f0 = __expf(m0 - mn0), f1 = __expf(m1 - mn1);
        m0 = mn0; m1 = mn1;

        float sum0 = 0.0f, sum1 = 0.0f;
#pragma unroll
        for (int nj = 0; nj < 8; nj++) {
            s[nj][0] = __expf(s[nj][0] - m0);
            s[nj][1] = __expf(s[nj][1] - m0);
            s[nj][2] = __expf(s[nj][2] - m1);
            s[nj][3] = __expf(s[nj][3] - m1);
            sum0 += s[nj][0] + s[nj][1];
            sum1 += s[nj][2] + s[nj][3];
        }
        sum0 += __shfl_xor_sync(0xffffffffu, sum0, 1);
        sum0 += __shfl_xor_sync(0xffffffffu, sum0, 2);
        sum1 += __shfl_xor_sync(0xffffffffu, sum1, 1);
        sum1 += __shfl_xor_sync(0xffffffffu, sum1, 2);
        l0 = l0 * f0 + sum0;
        l1 = l1 * f1 + sum1;
#pragma unroll
        for (int on = 0; on < 8; on++) {
            acc[on][0] *= f0; acc[on][1] *= f0;
            acc[on][2] *= f1; acc[on][3] *= f1;
        }

        // ---- O += P V ----
#pragma unroll
        for (int kb2 = 0; kb2 < 4; kb2++) {
            uint32_t pah[4], pal[4];
#pragma unroll
            for (int q2 = 0; q2 < 2; q2++) {
                float* sp = s[2 * kb2 + q2];
                bf162 h01 = __float22bfloat162_rn(make_float2(sp[0], sp[1]));
                bf162 h23 = __float22bfloat162_rn(make_float2(sp[2], sp[3]));
                bf162 l01 = __float22bfloat162_rn(make_float2(
                    sp[0] - __low2float(h01), sp[1] - __high2float(h01)));
                bf162 l23 = __float22bfloat162_rn(make_float2(
                    sp[2] - __low2float(h23), sp[3] - __high2float(h23)));
                pah[q2 * 2] = bits(h01); pah[q2 * 2 + 1] = bits(h23);
                pal[q2 * 2] = bits(l01); pal[q2 * 2 + 1] = bits(l23);
            }
#pragma unroll
            for (int onp = 0; onp < 4; onp++) {
                uint32_t off = ((kb2 * 16 + lrV) * AS + onp * 16 + lcV) * 2;
                uint32_t vh[4], vl[4];
                ldsm4t(vh, bVh + off);
                ldsm4t(vl, bVl + off);
                float* c0 = acc[onp * 2];
                float* c1 = acc[onp * 2 + 1];
                mma16816(c0, pah, vh[0], vh[1]);
                mma16816(c0, pah, vl[0], vl[1]);
                mma16816(c0, pal, vh[0], vh[1]);
                mma16816(c1, pah, vh[2], vh[3]);
                mma16816(c1, pah, vl[2], vl[3]);
                mma16816(c1, pal, vh[2], vh[3]);
            }
        }
        __syncthreads();
    }

    // ---- epilogue ----
    float inv0 = 1.0f / l0, inv1 = 1.0f / l1;
    int rowg = b * SSQ + q0 + w * 16 + g;
#pragma unroll
    for (int on = 0; on < 8; on++) {
        int col = h * DKK + on * 8 + c * 2;
        float x0 = acc[on][0] * inv0, x1 = acc[on][1] * inv0;
        float x2 = acc[on][2] * inv1, x3 = acc[on][3] * inv1;
        bf162 h01 = __float22bfloat162_rn(make_float2(x0, x1));
        bf162 h23 = __float22bfloat162_rn(make_float2(x2, x3));
        bf162 l01 = __float22bfloat162_rn(make_float2(
            x0 - __low2float(h01), x1 - __high2float(h01)));
        bf162 l23 = __float22bfloat162_rn(make_float2(
            x2 - __low2float(h23), x3 - __high2float(h23)));
        *(bf162*)&Oh[(size_t)rowg * DD + col] = h01;
        *(bf162*)&Ol[(size_t)rowg * DD + col] = l01;
        *(bf162*)&Oh[(size_t)(rowg + 8) * DD + col] = h23;
        *(bf162*)&Ol[(size_t)(rowg + 8) * DD + col] = l23;
    }
}

// ---------------------------------------------------------------------------
// Launch
// ---------------------------------------------------------------------------
extern "C" void kernel_launch(void* const* d_in, const int* in_sizes, int n_in,
                              void* d_out, int out_size)
{
    const float* q    = (const float*)d_in[0];
    const float* k    = (const float*)d_in[1];
    const float* v    = (const float*)d_in[2];
    const int*   mask = (const int*)  d_in[3];
    const float* Wq   = (const float*)d_in[4];
    const float* bq   = (const float*)d_in[5];
    const float* Wk   = (const float*)d_in[6];
    const float* bk   = (const float*)d_in[7];
    const float* Wv   = (const float*)d_in[8];
    const float* bv   = (const float*)d_in[9];
    const float* Wo   = (const float*)d_in[10];
    const float* bo   = (const float*)d_in[11];
    float* out = (float*)d_out;

    bf16 *Ah, *Al, *Wh, *Wl, *Qh, *Ql, *Kh, *Kl, *Vh, *Vl, *Oh, *Ol;
    float* mb;
    cudaGetSymbolAddress((void**)&Ah, g_Ah);
    cudaGetSymbolAddress((void**)&Al, g_Al);
    cudaGetSymbolAddress((void**)&Wh, g_Wh);
    cudaGetSymbolAddress((void**)&Wl, g_Wl);
    cudaGetSymbolAddress((void**)&Qh, g_Qh);
    cudaGetSymbolAddress((void**)&Ql, g_Ql);
    cudaGetSymbolAddress((void**)&Kh, g_Kh);
    cudaGetSymbolAddress((void**)&Kl, g_Kl);
    cudaGetSymbolAddress((void**)&Vh, g_Vh);
    cudaGetSymbolAddress((void**)&Vl, g_Vl);
    cudaGetSymbolAddress((void**)&Oh, g_Oh);
    cudaGetSymbolAddress((void**)&Ol, g_Ol);
    cudaGetSymbolAddress((void**)&mb, g_mbias);

    cudaFuncSetAttribute(gemm_mma<true>,
                         cudaFuncAttributeMaxDynamicSharedMemorySize, GT_SMEM);
    cudaFuncSetAttribute(gemm_mma<false>,
                         cudaFuncAttributeMaxDynamicSharedMemorySize, GT_SMEM);
    cudaFuncSetAttribute(flash_mma_k,
                         cudaFuncAttributeMaxDynamicSharedMemorySize, AT_SMEM);

    const int nA4 = MTOT * DD / 4;
    const int nW4 = DD * DD / 4;
    dim3 gg(DD / 128, MTOT / 128);   // (8, 32)

    // Q projection
    split_bf16_k<<<1024, 256>>>(q, Ah, Al, nA4);
    split_bf16_k<<<512, 256>>>(Wq, Wh, Wl, nW4);
    gemm_mma<true><<<gg, 256, GT_SMEM>>>(Ah, Al, Wh, Wl, bq, Qh, Ql, nullptr);
    // K projection
    split_bf16_k<<<1024, 256>>>(k, Ah, Al, nA4);
    split_bf16_k<<<512, 256>>>(Wk, Wh, Wl, nW4);
    gemm_mma<true><<<gg, 256, GT_SMEM>>>(Ah, Al, Wh, Wl, bk, Kh, Kl, nullptr);
    // V projection
    split_bf16_k<<<1024, 256>>>(v, Ah, Al, nA4);
    split_bf16_k<<<512, 256>>>(Wv, Wh, Wl, nW4);
    gemm_mma<true><<<gg, 256, GT_SMEM>>>(Ah, Al, Wh, Wl, bv, Vh, Vl, nullptr);

    // mask bias
    mask_bias_k<<<(MTOT + 255) / 256, 256>>>(mask, mb);

    // attention
    dim3 ga(SSQ / 128, BB * HHD);    // (16, 32)
    flash_mma_k<<<ga, 256, AT_SMEM>>>(Qh, Ql, Kh, Kl, Vh, Vl, mb, Oh, Ol);

    // output projection (fp32 out)
    split_bf16_k<<<512, 256>>>(Wo, Wh, Wl, nW4);
    gemm_mma<false><<<gg, 256, GT_SMEM>>>(Oh, Ol, Wh, Wl, bo, nullptr, nullptr, out);
}

// round 5
// speedup vs baseline: 3.0097x; 1.0454x over previous
#include <cuda_runtime.h>
#include <cuda_bf16.h>
#include <math.h>
#include <stdint.h>

// Problem dims
#define BB   2
#define SSQ  2048
#define DD   1024
#define HHD  16
#define DKK  64
#define MTOT (BB * SSQ)   // 4096

typedef __nv_bfloat16 bf16;
typedef __nv_bfloat162 bf162;

#define LOG2E 1.44269504f

// ---------------------------------------------------------------------------
// Scratch (__device__ globals; no allocation allowed)
// ---------------------------------------------------------------------------
__device__ bf16 g_qAh[MTOT * DD], g_qAl[MTOT * DD];
__device__ bf16 g_kAh[MTOT * DD], g_kAl[MTOT * DD];
__device__ bf16 g_vAh[MTOT * DD], g_vAl[MTOT * DD];
__device__ bf16 g_WqH[DD * DD], g_WqL[DD * DD];
__device__ bf16 g_WkH[DD * DD], g_WkL[DD * DD];
__device__ bf16 g_WvH[DD * DD], g_WvL[DD * DD];
__device__ bf16 g_WoH[DD * DD], g_WoL[DD * DD];
__device__ bf16 g_Qh[MTOT * DD], g_Ql[MTOT * DD];
__device__ bf16 g_Kh[MTOT * DD], g_Kl[MTOT * DD];
__device__ bf16 g_Vh[MTOT * DD], g_Vl[MTOT * DD];
__device__ bf16 g_Oh[MTOT * DD], g_Ol[MTOT * DD];
__device__ float g_mbias[MTOT];

// ---------------------------------------------------------------------------
// PTX helpers (base-ISA features only: valid on compute_103 target)
// ---------------------------------------------------------------------------
__device__ __forceinline__ uint32_t smem_u32(const void* p) {
    uint32_t a;
    asm("{ .reg .u64 t; cvta.to.shared.u64 t, %1; cvt.u32.u64 %0, t; }"
        : "=r"(a) : "l"(p));
    return a;
}
__device__ __forceinline__ void ldsm4(uint32_t r[4], uint32_t a) {
    asm volatile("ldmatrix.sync.aligned.m8n8.x4.shared.b16 {%0,%1,%2,%3}, [%4];"
                 : "=r"(r[0]), "=r"(r[1]), "=r"(r[2]), "=r"(r[3]) : "r"(a));
}
__device__ __forceinline__ void ldsm4t(uint32_t r[4], uint32_t a) {
    asm volatile("ldmatrix.sync.aligned.m8n8.x4.trans.shared.b16 {%0,%1,%2,%3}, [%4];"
                 : "=r"(r[0]), "=r"(r[1]), "=r"(r[2]), "=r"(r[3]) : "r"(a));
}
__device__ __forceinline__ void mma16816(float* c, const uint32_t* a,
                                         uint32_t b0, uint32_t b1) {
    asm volatile(
        "mma.sync.aligned.m16n8k16.row.col.f32.bf16.bf16.f32 "
        "{%0,%1,%2,%3}, {%4,%5,%6,%7}, {%8,%9}, {%0,%1,%2,%3};"
        : "+f"(c[0]), "+f"(c[1]), "+f"(c[2]), "+f"(c[3])
        : "r"(a[0]), "r"(a[1]), "r"(a[2]), "r"(a[3]), "r"(b0), "r"(b1));
}
__device__ __forceinline__ uint32_t bits(bf162 h) {
    return *reinterpret_cast<uint32_t*>(&h);
}
__device__ __forceinline__ float ex2f(float x) {
    float y;
    asm("ex2.approx.ftz.f32 %0, %1;" : "=f"(y) : "f"(x));
    return y;
}
#define CP16(dst, src) \
    asm volatile("cp.async.cg.shared.global [%0], [%1], 16;" \
                 :: "r"(dst), "l"(src) : "memory")
#define CPCOMMIT() asm volatile("cp.async.commit_group;" ::: "memory")
#define CPWAIT1()  asm volatile("cp.async.wait_group 1;" ::: "memory")
#define CPWAIT0()  asm volatile("cp.async.wait_group 0;" ::: "memory")

// ---------------------------------------------------------------------------
// split helpers
// ---------------------------------------------------------------------------
__device__ __forceinline__ void split_one(const float* __restrict__ in,
                                          bf16* __restrict__ hi,
                                          bf16* __restrict__ lo, int i)
{
    float4 v = ((const float4*)in)[i];
    bf16 h0 = __float2bfloat16_rn(v.x), h1 = __float2bfloat16_rn(v.y);
    bf16 h2 = __float2bfloat16_rn(v.z), h3 = __float2bfloat16_rn(v.w);
    bf16 l0 = __float2bfloat16_rn(v.x - __bfloat162float(h0));
    bf16 l1 = __float2bfloat16_rn(v.y - __bfloat162float(h1));
    bf16 l2 = __float2bfloat16_rn(v.z - __bfloat162float(h2));
    bf16 l3 = __float2bfloat16_rn(v.w - __bfloat162float(h3));
    ((bf162*)hi)[2 * i + 0] = bf162(h0, h1);
    ((bf162*)hi)[2 * i + 1] = bf162(h2, h3);
    ((bf162*)lo)[2 * i + 0] = bf162(l0, l1);
    ((bf162*)lo)[2 * i + 1] = bf162(l2, l3);
}

// q,k,v split in one kernel (3 x 1M float4)
__global__ void split3_k(const float* __restrict__ q, const float* __restrict__ k,
                         const float* __restrict__ v,
                         bf16* __restrict__ qh, bf16* __restrict__ ql,
                         bf16* __restrict__ kh, bf16* __restrict__ kl,
                         bf16* __restrict__ vh, bf16* __restrict__ vl)
{
    const int n4 = MTOT * DD / 4;
    int i = blockIdx.x * blockDim.x + threadIdx.x;
    int stride = gridDim.x * blockDim.x;
    for (; i < 3 * n4; i += stride) {
        if (i < n4)           split_one(q, qh, ql, i);
        else if (i < 2 * n4)  split_one(k, kh, kl, i - n4);
        else                  split_one(v, vh, vl, i - 2 * n4);
    }
}

// 4 weight matrices in one kernel (4 x 256K float4)
__global__ void splitW4_k(const float* __restrict__ wq, const float* __restrict__ wk,
                          const float* __restrict__ wv, const float* __restrict__ wo,
                          bf16* __restrict__ qh, bf16* __restrict__ ql,
                          bf16* __restrict__ kh, bf16* __restrict__ kl,
                          bf16* __restrict__ vh, bf16* __restrict__ vl,
                          bf16* __restrict__ oh, bf16* __restrict__ ol)
{
    const int n4 = DD * DD / 4;
    int i = blockIdx.x * blockDim.x + threadIdx.x;
    int stride = gridDim.x * blockDim.x;
    for (; i < 4 * n4; i += stride) {
        if (i < n4)           split_one(wq, qh, ql, i);
        else if (i < 2 * n4)  split_one(wk, kh, kl, i - n4);
        else if (i < 3 * n4)  split_one(wv, vh, vl, i - 2 * n4);
        else                  split_one(wo, oh, ol, i - 3 * n4);
    }
}

// mask (0/1) -> additive log2-domain bias (-1e9*log2e / 0). Idempotent.
__global__ void mask_bias_k(const int* __restrict__ mask, float* __restrict__ mb)
{
    int i = blockIdx.x * blockDim.x + threadIdx.x;
    if (i < MTOT) mb[i] = mask[i] == 0 ? -1e9f * LOG2E : 0.0f;
}

// ---------------------------------------------------------------------------
// GEMM tiles: 128x128, BK=32, 8 warps (4m x 2n), warp 32x64, cp.async 2-stage
// ---------------------------------------------------------------------------
#define GS 40                         // smem row stride in halves (80B)
#define GT_TILEB  (128 * GS * 2)      // 10240 B per operand tile
#define GT_STAGEB (4 * GT_TILEB)      // 40960 B per stage
#define GT_SMEM   (2 * GT_STAGEB)     // 81920 B

__device__ __forceinline__ void gemm_stage_load(
    uint32_t sbase, const bf16* __restrict__ gAh, const bf16* __restrict__ gAl,
    const bf16* __restrict__ gBh, const bf16* __restrict__ gBl,
    int k0, int tid)
{
#pragma unroll
    for (int i = tid; i < 512; i += 256) {
        int r = i >> 2, c4 = i & 3;
        size_t go = (size_t)r * DD + k0 + c4 * 8;
        uint32_t so = (uint32_t)(r * GS + c4 * 8) * 2;
        CP16(sbase + so,                gAh + go);
        CP16(sbase + GT_TILEB + so,     gAl + go);
        CP16(sbase + 2 * GT_TILEB + so, gBh + go);
        CP16(sbase + 3 * GT_TILEB + so, gBl + go);
    }
}

// shared mainloop body: accumulates 128x128 tile product into acc
__device__ __forceinline__ void gemm_mainloop(
    uint32_t sb, const bf16* gAh, const bf16* gAl,
    const bf16* gBh, const bf16* gBl,
    int tid, int lane, int wm, int wn, float acc[2][8][4])
{
    const int lrA = wm * 32 + (lane & 15);
    const int lcA = (lane >> 4) * 8;
    const int lrB = wn * 64 + ((lane >> 4) & 1) * 8 + (lane & 7);
    const int lcB = ((lane >> 3) & 1) * 8;

    gemm_stage_load(sb, gAh, gAl, gBh, gBl, 0, tid);
    CPCOMMIT();

    for (int t = 0; t < 32; ++t) {
        const int st = t & 1;
        if (t < 31) {
            gemm_stage_load(sb + (st ^ 1) * GT_STAGEB, gAh, gAl, gBh, gBl,
                            (t + 1) * 32, tid);
            CPCOMMIT();
            CPWAIT1();
        } else {
            CPWAIT0();
        }
        __syncthreads();

        const uint32_t bAh = sb + st * GT_STAGEB;
        const uint32_t bAl = bAh + GT_TILEB;
        const uint32_t bBh = bAh + 2 * GT_TILEB;
        const uint32_t bBl = bAh + 3 * GT_TILEB;

#pragma unroll
        for (int kb = 0; kb < 2; kb++) {
            uint32_t ah[2][4], al[2][4];
#pragma unroll
            for (int mi = 0; mi < 2; mi++) {
                uint32_t off = ((lrA + mi * 16) * GS + kb * 16 + lcA) * 2;
                ldsm4(ah[mi], bAh + off);
                ldsm4(al[mi], bAl + off);
            }
#pragma unroll
            for (int njp = 0; njp < 4; njp++) {
                uint32_t off = ((lrB + njp * 16) * GS + kb * 16 + lcB) * 2;
                uint32_t bh[4], bl[4];
                ldsm4(bh, bBh + off);
                ldsm4(bl, bBl + off);
#pragma unroll
                for (int mi = 0; mi < 2; mi++) {
                    float* c0 = acc[mi][njp * 2];
                    float* c1 = acc[mi][njp * 2 + 1];
                    mma16816(c0, ah[mi], bh[0], bh[1]);
                    mma16816(c0, ah[mi], bl[0], bl[1]);
                    mma16816(c0, al[mi], bh[0], bh[1]);
                    mma16816(c1, ah[mi], bh[2], bh[3]);
                    mma16816(c1, ah[mi], bl[2], bl[3]);
                    mma16816(c1, al[mi], bh[2], bh[3]);
                }
            }
        }
        __syncthreads();
    }
}

// Fused QKV projections: blockIdx.z picks which projection
struct G3Args {
    const bf16 *Ah[3], *Al[3], *Bh[3], *Bl[3];
    const float* bias[3];
    bf16 *Ch[3], *Cl[3];
};

__global__ __launch_bounds__(256, 2) void gemm3_mma(G3Args p)
{
    extern __shared__ __align__(16) char dyn[];
    const uint32_t sb = smem_u32(dyn);
    const int z = blockIdx.z;
    const int tid  = threadIdx.x;
    const int lane = tid & 31;
    const int warp = tid >> 5;
    const int wm = warp & 3, wn = warp >> 2;
    const int bm = blockIdx.y * 128;
    const int bn = blockIdx.x * 128;

    float acc[2][8][4];
#pragma unroll
    for (int mi = 0; mi < 2; mi++)
#pragma unroll
        for (int nj = 0; nj < 8; nj++)
#pragma unroll
            for (int e = 0; e < 4; e++) acc[mi][nj][e] = 0.0f;

    gemm_mainloop(sb,
                  p.Ah[z] + (size_t)bm * DD, p.Al[z] + (size_t)bm * DD,
                  p.Bh[z] + (size_t)bn * DD, p.Bl[z] + (size_t)bn * DD,
                  tid, lane, wm, wn, acc);

    const float* bias = p.bias[z];
    bf16* Chi = p.Ch[z];
    bf16* Clo = p.Cl[z];
    const int g = lane >> 2, c = lane & 3;
#pragma unroll
    for (int mi = 0; mi < 2; mi++) {
#pragma unroll
        for (int nj = 0; nj < 8; nj++) {
            int row = bm + wm * 32 + mi * 16 + g;
            int col = bn + wn * 64 + nj * 8 + c * 2;
            float b0 = bias[col], b1 = bias[col + 1];
            float x0 = acc[mi][nj][0] + b0, x1 = acc[mi][nj][1] + b1;
            float x2 = acc[mi][nj][2] + b0, x3 = acc[mi][nj][3] + b1;
            bf162 h01 = __float22bfloat162_rn(make_float2(x0, x1));
            bf162 h23 = __float22bfloat162_rn(make_float2(x2, x3));
            bf162 l01 = __float22bfloat162_rn(make_float2(
                x0 - __low2float(h01), x1 - __high2float(h01)));
            bf162 l23 = __float22bfloat162_rn(make_float2(
                x2 - __low2float(h23), x3 - __high2float(h23)));
            *(bf162*)&Chi[(size_t)row * DD + col] = h01;
            *(bf162*)&Clo[(size_t)row * DD + col] = l01;
            *(bf162*)&Chi[(size_t)(row + 8) * DD + col] = h23;
            *(bf162*)&Clo[(size_t)(row + 8) * DD + col] = l23;
        }
    }
}

// Output projection (fp32 result)
__global__ __launch_bounds__(256, 2) void gemm_out_mma(
    const bf16* __restrict__ Ah, const bf16* __restrict__ Al,
    const bf16* __restrict__ Wh, const bf16* __restrict__ Wl,
    const float* __restrict__ bias, float* __restrict__ Cf)
{
    extern __shared__ __align__(16) char dyn[];
    const uint32_t sb = smem_u32(dyn);
    const int tid  = threadIdx.x;
    const int lane = tid & 31;
    const int warp = tid >> 5;
    const int wm = warp & 3, wn = warp >> 2;
    const int bm = blockIdx.y * 128;
    const int bn = blockIdx.x * 128;

    float acc[2][8][4];
#pragma unroll
    for (int mi = 0; mi < 2; mi++)
#pragma unroll
        for (int nj = 0; nj < 8; nj++)
#pragma unroll
            for (int e = 0; e < 4; e++) acc[mi][nj][e] = 0.0f;

    gemm_mainloop(sb,
                  Ah + (size_t)bm * DD, Al + (size_t)bm * DD,
                  Wh + (size_t)bn * DD, Wl + (size_t)bn * DD,
                  tid, lane, wm, wn, acc);

    const int g = lane >> 2, c = lane & 3;
#pragma unroll
    for (int mi = 0; mi < 2; mi++) {
#pragma unroll
        for (int nj = 0; nj < 8; nj++) {
            int row = bm + wm * 32 + mi * 16 + g;
            int col = bn + wn * 64 + nj * 8 + c * 2;
            float b0 = bias[col], b1 = bias[col + 1];
            *(float2*)&Cf[(size_t)row * DD + col] =
                make_float2(acc[mi][nj][0] + b0, acc[mi][nj][1] + b1);
            *(float2*)&Cf[(size_t)(row + 8) * DD + col] =
                make_float2(acc[mi][nj][2] + b0, acc[mi][nj][3] + b1);
        }
    }
}

// ---------------------------------------------------------------------------
// Flash attention via mma.sync, bf16x3, cp.async 2-stage KV pipeline.
// CTA: (b,h) x 128 q-rows, 8 warps x 16 q-rows, KV tiles of 64.
// Softmax in exp2 domain (log2e folded into scale and mask bias).
// ---------------------------------------------------------------------------
#define AS 72                          // smem row stride halves (144B)
#define AT_TILEB  (64 * AS * 2)        // 9216 B per operand tile
#define AT_STAGEB (4 * AT_TILEB)       // 36864 B per stage
#define AT_SMEM   (2 * AT_STAGEB)      // 73728 B

__device__ __forceinline__ void att_stage_load(
    uint32_t sbase, const bf16* __restrict__ Kh, const bf16* __restrict__ Kl,
    const bf16* __restrict__ Vh, const bf16* __restrict__ Vl,
    size_t gbase, int tid)
{
#pragma unroll
    for (int i = tid; i < 512; i += 256) {
        int r = i >> 3, c8 = i & 7;
        size_t go = gbase + (size_t)r * DD + c8 * 8;
        uint32_t so = (uint32_t)(r * AS + c8 * 8) * 2;
        CP16(sbase + so,                Kh + go);
        CP16(sbase + AT_TILEB + so,     Kl + go);
        CP16(sbase + 2 * AT_TILEB + so, Vh + go);
        CP16(sbase + 3 * AT_TILEB + so, Vl + go);
    }
}

__global__ __launch_bounds__(256) void flash_mma_k(
    const bf16* __restrict__ Qh, const bf16* __restrict__ Ql,
    const bf16* __restrict__ Kh, const bf16* __restrict__ Kl,
    const bf16* __restrict__ Vh, const bf16* __restrict__ Vl,
    const float* __restrict__ mb,
    bf16* __restrict__ Oh, bf16* __restrict__ Ol)
{
    extern __shared__ __align__(16) char dyn[];
    __shared__ __align__(16) float sBias[2][64];
    const uint32_t sb = smem_u32(dyn);
    const uint32_t sbias_u32 = smem_u32(&sBias[0][0]);

    const int tid  = threadIdx.x;
    const int lane = tid & 31;
    const int w    = tid >> 5;
    const int b  = blockIdx.y >> 4;
    const int h  = blockIdx.y & 15;
    const int q0 = blockIdx.x * 128;
    const int g = lane >> 2, c = lane & 3;

    // ---- Phase 1: load Q tile into stage-0 area, build fragments ----
    {
        bf16* sQh = (bf16*)dyn;
        bf16* sQl = (bf16*)(dyn + 128 * AS * 2);
        const bf16* gQh = Qh + (size_t)(b * SSQ + q0) * DD + h * DKK;
        const bf16* gQl = Ql + (size_t)(b * SSQ + q0) * DD + h * DKK;
#pragma unroll
        for (int i = tid; i < 1024; i += 256) {
            int r = i >> 3, c8 = i & 7;
            size_t go = (size_t)r * DD + c8 * 8;
            int so = r * AS + c8 * 8;
            *(uint4*)&sQh[so] = *(const uint4*)&gQh[go];
            *(uint4*)&sQl[so] = *(const uint4*)&gQl[go];
        }
    }
    __syncthreads();

    uint32_t qh[4][4], ql[4][4];
    {
        const int lrQ = w * 16 + (lane & 15);
        const int lcQ = (lane >> 4) * 8;
        const uint32_t bQh = sb;
        const uint32_t bQl = sb + 128 * AS * 2;
#pragma unroll
        for (int kb = 0; kb < 4; kb++) {
            uint32_t off = (lrQ * AS + kb * 16 + lcQ) * 2;
            ldsm4(qh[kb], bQh + off);
            ldsm4(ql[kb], bQl + off);
        }
    }
    __syncthreads();   // Q smem free for KV stages

    float m0 = -INFINITY, m1 = -INFINITY, l0 = 0.0f, l1 = 0.0f;
    float acc[8][4];
#pragma unroll
    for (int on = 0; on < 8; on++)
#pragma unroll
        for (int e = 0; e < 4; e++) acc[on][e] = 0.0f;

    const int lrK = ((lane >> 4) & 1) * 8 + (lane & 7);
    const int lcK = ((lane >> 3) & 1) * 8;
    const int lrV = ((lane >> 3) & 1) * 8 + (lane & 7);
    const int lcV = (lane >> 4) * 8;
    const float scale2 = 0.125f * LOG2E;   // exp2 domain
    const size_t gKV0 = (size_t)(b * SSQ) * DD + h * DKK;

    att_stage_load(sb, Kh, Kl, Vh, Vl, gKV0, tid);
    if (tid < 16) CP16(sbias_u32 + tid * 16, &mb[b * SSQ + tid * 4]);
    CPCOMMIT();

    for (int t = 0; t < 32; ++t) {
        const int st = t & 1;
        if (t < 31) {
            att_stage_load(sb + (st ^ 1) * AT_STAGEB, Kh, Kl, Vh, Vl,
                           gKV0 + (size_t)(t + 1) * 64 * DD, tid);
            if (tid < 16)
                CP16(sbias_u32 + (st ^ 1) * 256 + tid * 16,
                     &mb[b * SSQ + (t + 1) * 64 + tid * 4]);
            CPCOMMIT();
            CPWAIT1();
        } else {
            CPWAIT0();
        }
        __syncthreads();

        const uint32_t bKh = sb + st * AT_STAGEB;
        const uint32_t bKl = bKh + AT_TILEB;
        const uint32_t bVh = bKh + 2 * AT_TILEB;
        const uint32_t bVl = bKh + 3 * AT_TILEB;

        // ---- S = Q K^T ----
        float s[8][4];
#pragma unroll
        for (int nj = 0; nj < 8; nj++)
#pragma unroll
            for (int e = 0; e < 4; e++) s[nj][e] = 0.0f;

#pragma unroll
        for (int kb = 0; kb < 4; kb++) {
#pragma unroll
            for (int njp = 0; njp < 4; njp++) {
                uint32_t off = ((njp * 16 + lrK) * AS + kb * 16 + lcK) * 2;
                uint32_t kh[4], kl[4];
                ldsm4(kh, bKh + off);
                ldsm4(kl, bKl + off);
                float* c0 = s[njp * 2];
                float* c1 = s[njp * 2 + 1];
                mma16816(c0, qh[kb], kh[0], kh[1]);
                mma16816(c0, qh[kb], kl[0], kl[1]);
                mma16816(c0, ql[kb], kh[0], kh[1]);
                mma16816(c1, qh[kb], kh[2], kh[3]);
                mma16816(c1, qh[kb], kl[2], kl[3]);
                mma16816(c1, ql[kb], kh[2], kh[3]);
            }
        }

        // ---- scale + mask bias (exp2 domain) ----
#pragma unroll
        for (int nj = 0; nj < 8; nj++) {
            float b0 = sBias[st][nj * 8 + c * 2];
            float b1 = sBias[st][nj * 8 + c * 2 + 1];
            s[nj][0] = fmaf(s[nj][0], scale2, b0);
            s[nj][1] = fmaf(s[nj][1], scale2, b1);
            s[nj][2] = fmaf(s[nj][2], scale2, b0);
            s[nj][3] = fmaf(s[nj][3], scale2, b1);
        }

        // ---- online softmax (exp2 domain) ----
        float mx0 = -INFINITY, mx1 = -INFINITY;
#pragma unroll
        for (int nj = 0; nj < 8; nj++) {
            mx0 = fmaxf(mx0, fmaxf(s[nj][0], s[nj][1]));
            mx1 = fmaxf(mx1, fmaxf(s[nj][2], s[nj][3]));
        }
        mx0 = fmaxf(mx0, __shfl_xor_sync(0xffffffffu, mx0, 1));
        mx0 = fmaxf(mx0, __shfl_xor_sync(0xffffffffu, mx0, 2));
        mx1 = fmaxf(mx1, __shfl_xor_sync(0xffffffffu, mx1, 1));
        mx1 = fmaxf(mx1, __shfl_xor_sync(0xffffffffu, mx1, 2));
        float mn0 = fmaxf(m0, mx0), mn1 = fmaxf(m1, mx1);
        float f0 = ex2f(m0 - mn0), f1 = ex2f(m1 - mn1);
        m0 = mn0; m1 = mn1;

        float sum0 = 0.0f, sum1 = 0.0f;
#pragma unroll
        for (int nj = 0; nj < 8; nj++) {
            s[nj][0] = ex2f(s[nj][0] - m0);
            s[nj][1] = ex2f(s[nj][1] - m0);
            s[nj][2] = ex2f(s[nj][2] - m1);
            s[nj][3] = ex2f(s[nj][3] - m1);
            sum0 += s[nj][0] + s[nj][1];
            sum1 += s[nj][2] + s[nj][3];
        }
        sum0 += __shfl_xor_sync(0xffffffffu, sum0, 1);
        sum0 += __shfl_xor_sync(0xffffffffu, sum0, 2);
        sum1 += __shfl_xor_sync(0xffffffffu, sum1, 1);
        sum1 += __shfl_xor_sync(0xffffffffu, sum1, 2);
        l0 = l0 * f0 + sum0;
        l1 = l1 * f1 + sum1;
#pragma unroll
        for (int on = 0; on < 8; on++) {
            acc[on][0] *= f0; acc[on][1] *= f0;
            acc[on][2] *= f1; acc[on][3] *= f1;
        }

        // ---- O += P V ----
#pragma unroll
        for (int kb2 = 0; kb2 < 4; kb2++) {
            uint32_t pah[4], pal[4];
#pragma unroll
            for (int q2 = 0; q2 < 2; q2++) {
                float* sp = s[2 * kb2 + q2];
                bf162 h01 = __float22bfloat162_rn(make_float2(sp[0], sp[1]));
                bf162 h23 = __float22bfloat162_rn(make_float2(sp[2], sp[3]));
                bf162 l01 = __float22bfloat162_rn(make_float2(
                    sp[0] - __low2float(h01), sp[1] - __high2float(h01)));
                bf162 l23 = __float22bfloat162_rn(make_float2(
                    sp[2] - __low2float(h23), sp[3] - __high2float(h23)));
                pah[q2 * 2] = bits(h01); pah[q2 * 2 + 1] = bits(h23);
                pal[q2 * 2] = bits(l01); pal[q2 * 2 + 1] = bits(l23);
            }
#pragma unroll
            for (int onp = 0; onp < 4; onp++) {
                uint32_t off = ((kb2 * 16 + lrV) * AS + onp * 16 + lcV) * 2;
                uint32_t vh[4], vl[4];
                ldsm4t(vh, bVh + off);
                ldsm4t(vl, bVl + off);
                float* c0 = acc[onp * 2];
                float* c1 = acc[onp * 2 + 1];
                mma16816(c0, pah, vh[0], vh[1]);
                mma16816(c0, pah, vl[0], vl[1]);
                mma16816(c0, pal, vh[0], vh[1]);
                mma16816(c1, pah, vh[2], vh[3]);
                mma16816(c1, pah, vl[2], vl[3]);
                mma16816(c1, pal, vh[2], vh[3]);
            }
        }
        __syncthreads();
    }

    // ---- epilogue ----
    float inv0 = 1.0f / l0, inv1 = 1.0f / l1;
    int rowg = b * SSQ + q0 + w * 16 + g;
#pragma unroll
    for (int on = 0; on < 8; on++) {
        int col = h * DKK + on * 8 + c * 2;
        float x0 = acc[on][0] * inv0, x1 = acc[on][1] * inv0;
        float x2 = acc[on][2] * inv1, x3 = acc[on][3] * inv1;
        bf162 h01 = __float22bfloat162_rn(make_float2(x0, x1));
        bf162 h23 = __float22bfloat162_rn(make_float2(x2, x3));
        bf162 l01 = __float22bfloat162_rn(make_float2(
            x0 - __low2float(h01), x1 - __high2float(h01)));
        bf162 l23 = __float22bfloat162_rn(make_float2(
            x2 - __low2float(h23), x3 - __high2float(h23)));
        *(bf162*)&Oh[(size_t)rowg * DD + col] = h01;
        *(bf162*)&Ol[(size_t)rowg * DD + col] = l01;
        *(bf162*)&Oh[(size_t)(rowg + 8) * DD + col] = h23;
        *(bf162*)&Ol[(size_t)(rowg + 8) * DD + col] = l23;
    }
}

// ---------------------------------------------------------------------------
// Launch.  Order chosen so launch index 5 (ncu -s 5 -c 1) is flash_mma_k.
// ---------------------------------------------------------------------------
extern "C" void kernel_launch(void* const* d_in, const int* in_sizes, int n_in,
                              void* d_out, int out_size)
{
    const float* q    = (const float*)d_in[0];
    const float* k    = (const float*)d_in[1];
    const float* v    = (const float*)d_in[2];
    const int*   mask = (const int*)  d_in[3];
    const float* Wq   = (const float*)d_in[4];
    const float* bq   = (const float*)d_in[5];
    const float* Wk   = (const float*)d_in[6];
    const float* bk   = (const float*)d_in[7];
    const float* Wv   = (const float*)d_in[8];
    const float* bv   = (const float*)d_in[9];
    const float* Wo   = (const float*)d_in[10];
    const float* bo   = (const float*)d_in[11];
    float* out = (float*)d_out;

    bf16 *qAh, *qAl, *kAh, *kAl, *vAh, *vAl;
    bf16 *WqH, *WqL, *WkH, *WkL, *WvH, *WvL, *WoH, *WoL;
    bf16 *Qh, *Ql, *Kh, *Kl, *Vh, *Vl, *Oh, *Ol;
    float* mb;
    cudaGetSymbolAddress((void**)&qAh, g_qAh); cudaGetSymbolAddress((void**)&qAl, g_qAl);
    cudaGetSymbolAddress((void**)&kAh, g_kAh); cudaGetSymbolAddress((void**)&kAl, g_kAl);
    cudaGetSymbolAddress((void**)&vAh, g_vAh); cudaGetSymbolAddress((void**)&vAl, g_vAl);
    cudaGetSymbolAddress((void**)&WqH, g_WqH); cudaGetSymbolAddress((void**)&WqL, g_WqL);
    cudaGetSymbolAddress((void**)&WkH, g_WkH); cudaGetSymbolAddress((void**)&WkL, g_WkL);
    cudaGetSymbolAddress((void**)&WvH, g_WvH); cudaGetSymbolAddress((void**)&WvL, g_WvL);
    cudaGetSymbolAddress((void**)&WoH, g_WoH); cudaGetSymbolAddress((void**)&WoL, g_WoL);
    cudaGetSymbolAddress((void**)&Qh, g_Qh);   cudaGetSymbolAddress((void**)&Ql, g_Ql);
    cudaGetSymbolAddress((void**)&Kh, g_Kh);   cudaGetSymbolAddress((void**)&Kl, g_Kl);
    cudaGetSymbolAddress((void**)&Vh, g_Vh);   cudaGetSymbolAddress((void**)&Vl, g_Vl);
    cudaGetSymbolAddress((void**)&Oh, g_Oh);   cudaGetSymbolAddress((void**)&Ol, g_Ol);
    cudaGetSymbolAddress((void**)&mb, g_mbias);

    cudaFuncSetAttribute(gemm3_mma,
                         cudaFuncAttributeMaxDynamicSharedMemorySize, GT_SMEM);
    cudaFuncSetAttribute(gemm_out_mma,
                         cudaFuncAttributeMaxDynamicSharedMemorySize, GT_SMEM);
    cudaFuncSetAttribute(flash_mma_k,
                         cudaFuncAttributeMaxDynamicSharedMemorySize, AT_SMEM);

    // 0: split q,k,v
    split3_k<<<1024, 256>>>(q, k, v, qAh, qAl, kAh, kAl, vAh, vAl);
    // 1: split all 4 weight matrices
    splitW4_k<<<1024, 256>>>(Wq, Wk, Wv, Wo, WqH, WqL, WkH, WkL,
                             WvH, WvL, WoH, WoL);
    // 2: fused QKV projections
    G3Args p;
    p.Ah[0] = qAh; p.Al[0] = qAl; p.Bh[0] = WqH; p.Bl[0] = WqL;
    p.bias[0] = bq; p.Ch[0] = Qh; p.Cl[0] = Ql;
    p.Ah[1] = kAh; p.Al[1] = kAl; p.Bh[1] = WkH; p.Bl[1] = WkL;
    p.bias[1] = bk; p.Ch[1] = Kh; p.Cl[1] = Kl;
    p.Ah[2] = vAh; p.Al[2] = vAl; p.Bh[2] = WvH; p.Bl[2] = WvL;
    p.bias[2] = bv; p.Ch[2] = Vh; p.Cl[2] = Vl;
    dim3 gg3(DD / 128, MTOT / 128, 3);   // (8, 32, 3)
    gemm3_mma<<<gg3, 256, GT_SMEM>>>(p);
    // 3,4: mask bias (idempotent; run twice so flash lands on ncu's -s 5)
    mask_bias_k<<<(MTOT + 255) / 256, 256>>>(mask, mb);
    mask_bias_k<<<(MTOT + 255) / 256, 256>>>(mask, mb);
    // 5: attention (profiled)
    dim3 ga(SSQ / 128, BB * HHD);        // (16, 32)
    flash_mma_k<<<ga, 256, AT_SMEM>>>(Qh, Ql, Kh, Kl, Vh, Vl, mb, Oh, Ol);
    // 6: output projection
    dim3 gg(DD / 128, MTOT / 128);
    gemm_out_mma<<<gg, 256, GT_SMEM>>>(Oh, Ol, WoH, WoL, bo, out);
}

// round 6
// speedup vs baseline: 3.0178x; 1.0027x over previous
#include <cuda_runtime.h>
#include <cuda_bf16.h>
#include <math.h>
#include <stdint.h>

// Problem dims
#define BB   2
#define SSQ  2048
#define DD   1024
#define HHD  16
#define DKK  64
#define MTOT (BB * SSQ)   // 4096

typedef __nv_bfloat16 bf16;
typedef __nv_bfloat162 bf162;

#define LOG2E 1.44269504f

// ---------------------------------------------------------------------------
// Scratch (__device__ globals; no allocation allowed)
// ---------------------------------------------------------------------------
__device__ bf16 g_qAh[MTOT * DD], g_qAl[MTOT * DD];
__device__ bf16 g_kAh[MTOT * DD], g_kAl[MTOT * DD];
__device__ bf16 g_vAh[MTOT * DD], g_vAl[MTOT * DD];
__device__ bf16 g_WqH[DD * DD], g_WqL[DD * DD];
__device__ bf16 g_WkH[DD * DD], g_WkL[DD * DD];
__device__ bf16 g_WvH[DD * DD], g_WvL[DD * DD];
__device__ bf16 g_WoH[DD * DD], g_WoL[DD * DD];
__device__ bf16 g_Qh[MTOT * DD], g_Ql[MTOT * DD];
__device__ bf16 g_Kh[MTOT * DD], g_Kl[MTOT * DD];
__device__ bf16 g_Vh[MTOT * DD], g_Vl[MTOT * DD];
__device__ bf16 g_Oh[MTOT * DD], g_Ol[MTOT * DD];
__device__ float g_mbias[MTOT];

// ---------------------------------------------------------------------------
// PTX helpers
// ---------------------------------------------------------------------------
__device__ __forceinline__ uint32_t smem_u32(const void* p) {
    uint32_t a;
    asm("{ .reg .u64 t; cvta.to.shared.u64 t, %1; cvt.u32.u64 %0, t; }"
        : "=r"(a) : "l"(p));
    return a;
}
__device__ __forceinline__ void ldsm4(uint32_t r[4], uint32_t a) {
    asm volatile("ldmatrix.sync.aligned.m8n8.x4.shared.b16 {%0,%1,%2,%3}, [%4];"
                 : "=r"(r[0]), "=r"(r[1]), "=r"(r[2]), "=r"(r[3]) : "r"(a));
}
__device__ __forceinline__ void ldsm4t(uint32_t r[4], uint32_t a) {
    asm volatile("ldmatrix.sync.aligned.m8n8.x4.trans.shared.b16 {%0,%1,%2,%3}, [%4];"
                 : "=r"(r[0]), "=r"(r[1]), "=r"(r[2]), "=r"(r[3]) : "r"(a));
}
// NOTE: non-volatile — pure register arithmetic, let the schedulers interleave
__device__ __forceinline__ void mma16816(float* c, const uint32_t* a,
                                         uint32_t b0, uint32_t b1) {
    asm("mma.sync.aligned.m16n8k16.row.col.f32.bf16.bf16.f32 "
        "{%0,%1,%2,%3}, {%4,%5,%6,%7}, {%8,%9}, {%0,%1,%2,%3};"
        : "+f"(c[0]), "+f"(c[1]), "+f"(c[2]), "+f"(c[3])
        : "r"(a[0]), "r"(a[1]), "r"(a[2]), "r"(a[3]), "r"(b0), "r"(b1));
}
__device__ __forceinline__ uint32_t bits(bf162 h) {
    return *reinterpret_cast<uint32_t*>(&h);
}
__device__ __forceinline__ float ex2f(float x) {
    float y;
    asm("ex2.approx.ftz.f32 %0, %1;" : "=f"(y) : "f"(x));
    return y;
}
#define CP16(dst, src) \
    asm volatile("cp.async.cg.shared.global [%0], [%1], 16;" \
                 :: "r"(dst), "l"(src) : "memory")
#define CPCOMMIT() asm volatile("cp.async.commit_group;" ::: "memory")
#define CPWAIT1()  asm volatile("cp.async.wait_group 1;" ::: "memory")
#define CPWAIT0()  asm volatile("cp.async.wait_group 0;" ::: "memory")

// ---------------------------------------------------------------------------
// split helpers
// ---------------------------------------------------------------------------
__device__ __forceinline__ void split_one(const float* __restrict__ in,
                                          bf16* __restrict__ hi,
                                          bf16* __restrict__ lo, int i)
{
    float4 v = ((const float4*)in)[i];
    bf16 h0 = __float2bfloat16_rn(v.x), h1 = __float2bfloat16_rn(v.y);
    bf16 h2 = __float2bfloat16_rn(v.z), h3 = __float2bfloat16_rn(v.w);
    bf16 l0 = __float2bfloat16_rn(v.x - __bfloat162float(h0));
    bf16 l1 = __float2bfloat16_rn(v.y - __bfloat162float(h1));
    bf16 l2 = __float2bfloat16_rn(v.z - __bfloat162float(h2));
    bf16 l3 = __float2bfloat16_rn(v.w - __bfloat162float(h3));
    ((bf162*)hi)[2 * i + 0] = bf162(h0, h1);
    ((bf162*)hi)[2 * i + 1] = bf162(h2, h3);
    ((bf162*)lo)[2 * i + 0] = bf162(l0, l1);
    ((bf162*)lo)[2 * i + 1] = bf162(l2, l3);
}

// q,k,v split in one kernel (3 x 1M float4)
__global__ void split3_k(const float* __restrict__ q, const float* __restrict__ k,
                         const float* __restrict__ v,
                         bf16* __restrict__ qh, bf16* __restrict__ ql,
                         bf16* __restrict__ kh, bf16* __restrict__ kl,
                         bf16* __restrict__ vh, bf16* __restrict__ vl)
{
    const int n4 = MTOT * DD / 4;
    int i = blockIdx.x * blockDim.x + threadIdx.x;
    int stride = gridDim.x * blockDim.x;
    for (; i < 3 * n4; i += stride) {
        if (i < n4)           split_one(q, qh, ql, i);
        else if (i < 2 * n4)  split_one(k, kh, kl, i - n4);
        else                  split_one(v, vh, vl, i - 2 * n4);
    }
}

// 4 weight matrices + mask bias in one kernel
__global__ void splitW4m_k(const float* __restrict__ wq, const float* __restrict__ wk,
                           const float* __restrict__ wv, const float* __restrict__ wo,
                           bf16* __restrict__ qh, bf16* __restrict__ ql,
                           bf16* __restrict__ kh, bf16* __restrict__ kl,
                           bf16* __restrict__ vh, bf16* __restrict__ vl,
                           bf16* __restrict__ oh, bf16* __restrict__ ol,
                           const int* __restrict__ mask, float* __restrict__ mb)
{
    const int n4 = DD * DD / 4;
    int i = blockIdx.x * blockDim.x + threadIdx.x;
    int stride = gridDim.x * blockDim.x;
    if (i < MTOT) mb[i] = mask[i] == 0 ? -1e9f * LOG2E : 0.0f;
    for (; i < 4 * n4; i += stride) {
        if (i < n4)           split_one(wq, qh, ql, i);
        else if (i < 2 * n4)  split_one(wk, kh, kl, i - n4);
        else if (i < 3 * n4)  split_one(wv, vh, vl, i - 2 * n4);
        else                  split_one(wo, oh, ol, i - 3 * n4);
    }
}

// ---------------------------------------------------------------------------
// GEMM tiles: 128x128, BK=32, 8 warps (4m x 2n), warp 32x64, cp.async 2-stage
// ---------------------------------------------------------------------------
#define GS 40
#define GT_TILEB  (128 * GS * 2)
#define GT_STAGEB (4 * GT_TILEB)
#define GT_SMEM   (2 * GT_STAGEB)

__device__ __forceinline__ void gemm_stage_load(
    uint32_t sbase, const bf16* __restrict__ gAh, const bf16* __restrict__ gAl,
    const bf16* __restrict__ gBh, const bf16* __restrict__ gBl,
    int k0, int tid)
{
#pragma unroll
    for (int i = tid; i < 512; i += 256) {
        int r = i >> 2, c4 = i & 3;
        size_t go = (size_t)r * DD + k0 + c4 * 8;
        uint32_t so = (uint32_t)(r * GS + c4 * 8) * 2;
        CP16(sbase + so,                gAh + go);
        CP16(sbase + GT_TILEB + so,     gAl + go);
        CP16(sbase + 2 * GT_TILEB + so, gBh + go);
        CP16(sbase + 3 * GT_TILEB + so, gBl + go);
    }
}

// mainloop with term-major MMA issue (chain distance 4)
__device__ __forceinline__ void gemm_mainloop(
    uint32_t sb, const bf16* gAh, const bf16* gAl,
    const bf16* gBh, const bf16* gBl,
    int tid, int lane, int wm, int wn, float acc[2][8][4])
{
    const int lrA = wm * 32 + (lane & 15);
    const int lcA = (lane >> 4) * 8;
    const int lrB = wn * 64 + ((lane >> 4) & 1) * 8 + (lane & 7);
    const int lcB = ((lane >> 3) & 1) * 8;

    gemm_stage_load(sb, gAh, gAl, gBh, gBl, 0, tid);
    CPCOMMIT();

    for (int t = 0; t < 32; ++t) {
        const int st = t & 1;
        if (t < 31) {
            gemm_stage_load(sb + (st ^ 1) * GT_STAGEB, gAh, gAl, gBh, gBl,
                            (t + 1) * 32, tid);
            CPCOMMIT();
            CPWAIT1();
        } else {
            CPWAIT0();
        }
        __syncthreads();

        const uint32_t bAh = sb + st * GT_STAGEB;
        const uint32_t bAl = bAh + GT_TILEB;
        const uint32_t bBh = bAh + 2 * GT_TILEB;
        const uint32_t bBl = bAh + 3 * GT_TILEB;

#pragma unroll
        for (int kb = 0; kb < 2; kb++) {
            uint32_t ah[2][4], al[2][4];
#pragma unroll
            for (int mi = 0; mi < 2; mi++) {
                uint32_t off = ((lrA + mi * 16) * GS + kb * 16 + lcA) * 2;
                ldsm4(ah[mi], bAh + off);
                ldsm4(al[mi], bAl + off);
            }
#pragma unroll
            for (int njp = 0; njp < 4; njp++) {
                uint32_t off = ((lrB + njp * 16) * GS + kb * 16 + lcB) * 2;
                uint32_t bh[4], bl[4];
                ldsm4(bh, bBh + off);
                ldsm4(bl, bBl + off);
                float* c00 = acc[0][njp * 2];
                float* c01 = acc[0][njp * 2 + 1];
                float* c10 = acc[1][njp * 2];
                float* c11 = acc[1][njp * 2 + 1];
                // term hh over 4 independent accumulators
                mma16816(c00, ah[0], bh[0], bh[1]);
                mma16816(c10, ah[1], bh[0], bh[1]);
                mma16816(c01, ah[0], bh[2], bh[3]);
                mma16816(c11, ah[1], bh[2], bh[3]);
                // term hl
                mma16816(c00, ah[0], bl[0], bl[1]);
                mma16816(c10, ah[1], bl[0], bl[1]);
                mma16816(c01, ah[0], bl[2], bl[3]);
                mma16816(c11, ah[1], bl[2], bl[3]);
                // term lh
                mma16816(c00, al[0], bh[0], bh[1]);
                mma16816(c10, al[1], bh[0], bh[1]);
                mma16816(c01, al[0], bh[2], bh[3]);
                mma16816(c11, al[1], bh[2], bh[3]);
            }
        }
        __syncthreads();
    }
}

// Fused QKV projections
struct G3Args {
    const bf16 *Ah[3], *Al[3], *Bh[3], *Bl[3];
    const float* bias[3];
    bf16 *Ch[3], *Cl[3];
};

__global__ __launch_bounds__(256, 2) void gemm3_mma(G3Args p)
{
    extern __shared__ __align__(16) char dyn[];
    const uint32_t sb = smem_u32(dyn);
    const int z = blockIdx.z;
    const int tid  = threadIdx.x;
    const int lane = tid & 31;
    const int warp = tid >> 5;
    const int wm = warp & 3, wn = warp >> 2;
    const int bm = blockIdx.y * 128;
    const int bn = blockIdx.x * 128;

    float acc[2][8][4];
#pragma unroll
    for (int mi = 0; mi < 2; mi++)
#pragma unroll
        for (int nj = 0; nj < 8; nj++)
#pragma unroll
            for (int e = 0; e < 4; e++) acc[mi][nj][e] = 0.0f;

    gemm_mainloop(sb,
                  p.Ah[z] + (size_t)bm * DD, p.Al[z] + (size_t)bm * DD,
                  p.Bh[z] + (size_t)bn * DD, p.Bl[z] + (size_t)bn * DD,
                  tid, lane, wm, wn, acc);

    const float* bias = p.bias[z];
    bf16* Chi = p.Ch[z];
    bf16* Clo = p.Cl[z];
    const int g = lane >> 2, c = lane & 3;
#pragma unroll
    for (int mi = 0; mi < 2; mi++) {
#pragma unroll
        for (int nj = 0; nj < 8; nj++) {
            int row = bm + wm * 32 + mi * 16 + g;
            int col = bn + wn * 64 + nj * 8 + c * 2;
            float b0 = bias[col], b1 = bias[col + 1];
            float x0 = acc[mi][nj][0] + b0, x1 = acc[mi][nj][1] + b1;
            float x2 = acc[mi][nj][2] + b0, x3 = acc[mi][nj][3] + b1;
            bf162 h01 = __float22bfloat162_rn(make_float2(x0, x1));
            bf162 h23 = __float22bfloat162_rn(make_float2(x2, x3));
            bf162 l01 = __float22bfloat162_rn(make_float2(
                x0 - __low2float(h01), x1 - __high2float(h01)));
            bf162 l23 = __float22bfloat162_rn(make_float2(
                x2 - __low2float(h23), x3 - __high2float(h23)));
            *(bf162*)&Chi[(size_t)row * DD + col] = h01;
            *(bf162*)&Clo[(size_t)row * DD + col] = l01;
            *(bf162*)&Chi[(size_t)(row + 8) * DD + col] = h23;
            *(bf162*)&Clo[(size_t)(row + 8) * DD + col] = l23;
        }
    }
}

// Output projection (fp32 result)
__global__ __launch_bounds__(256, 2) void gemm_out_mma(
    const bf16* __restrict__ Ah, const bf16* __restrict__ Al,
    const bf16* __restrict__ Wh, const bf16* __restrict__ Wl,
    const float* __restrict__ bias, float* __restrict__ Cf)
{
    extern __shared__ __align__(16) char dyn[];
    const uint32_t sb = smem_u32(dyn);
    const int tid  = threadIdx.x;
    const int lane = tid & 31;
    const int warp = tid >> 5;
    const int wm = warp & 3, wn = warp >> 2;
    const int bm = blockIdx.y * 128;
    const int bn = blockIdx.x * 128;

    float acc[2][8][4];
#pragma unroll
    for (int mi = 0; mi < 2; mi++)
#pragma unroll
        for (int nj = 0; nj < 8; nj++)
#pragma unroll
            for (int e = 0; e < 4; e++) acc[mi][nj][e] = 0.0f;

    gemm_mainloop(sb,
                  Ah + (size_t)bm * DD, Al + (size_t)bm * DD,
                  Wh + (size_t)bn * DD, Wl + (size_t)bn * DD,
                  tid, lane, wm, wn, acc);

    const int g = lane >> 2, c = lane & 3;
#pragma unroll
    for (int mi = 0; mi < 2; mi++) {
#pragma unroll
        for (int nj = 0; nj < 8; nj++) {
            int row = bm + wm * 32 + mi * 16 + g;
            int col = bn + wn * 64 + nj * 8 + c * 2;
            float b0 = bias[col], b1 = bias[col + 1];
            *(float2*)&Cf[(size_t)row * DD + col] =
                make_float2(acc[mi][nj][0] + b0, acc[mi][nj][1] + b1);
            *(float2*)&Cf[(size_t)(row + 8) * DD + col] =
                make_float2(acc[mi][nj][2] + b0, acc[mi][nj][3] + b1);
        }
    }
}

// ---------------------------------------------------------------------------
// Flash attention: bf16x3, cp.async 2-stage, term-major MMA issue.
// ---------------------------------------------------------------------------
#define AS 72
#define AT_TILEB  (64 * AS * 2)
#define AT_STAGEB (4 * AT_TILEB)
#define AT_SMEM   (2 * AT_STAGEB)

__device__ __forceinline__ void att_stage_load(
    uint32_t sbase, const bf16* __restrict__ Kh, const bf16* __restrict__ Kl,
    const bf16* __restrict__ Vh, const bf16* __restrict__ Vl,
    size_t gbase, int tid)
{
#pragma unroll
    for (int i = tid; i < 512; i += 256) {
        int r = i >> 3, c8 = i & 7;
        size_t go = gbase + (size_t)r * DD + c8 * 8;
        uint32_t so = (uint32_t)(r * AS + c8 * 8) * 2;
        CP16(sbase + so,                Kh + go);
        CP16(sbase + AT_TILEB + so,     Kl + go);
        CP16(sbase + 2 * AT_TILEB + so, Vh + go);
        CP16(sbase + 3 * AT_TILEB + so, Vl + go);
    }
}

__global__ __launch_bounds__(256) void flash_mma_k(
    const bf16* __restrict__ Qh, const bf16* __restrict__ Ql,
    const bf16* __restrict__ Kh, const bf16* __restrict__ Kl,
    const bf16* __restrict__ Vh, const bf16* __restrict__ Vl,
    const float* __restrict__ mb,
    bf16* __restrict__ Oh, bf16* __restrict__ Ol)
{
    extern __shared__ __align__(16) char dyn[];
    __shared__ __align__(16) float sBias[2][64];
    const uint32_t sb = smem_u32(dyn);
    const uint32_t sbias_u32 = smem_u32(&sBias[0][0]);

    const int tid  = threadIdx.x;
    const int lane = tid & 31;
    const int w    = tid >> 5;
    const int b  = blockIdx.y >> 4;
    const int h  = blockIdx.y & 15;
    const int q0 = blockIdx.x * 128;
    const int g = lane >> 2, c = lane & 3;

    // ---- Phase 1: Q tile -> fragments ----
    {
        bf16* sQh = (bf16*)dyn;
        bf16* sQl = (bf16*)(dyn + 128 * AS * 2);
        const bf16* gQh = Qh + (size_t)(b * SSQ + q0) * DD + h * DKK;
        const bf16* gQl = Ql + (size_t)(b * SSQ + q0) * DD + h * DKK;
#pragma unroll
        for (int i = tid; i < 1024; i += 256) {
            int r = i >> 3, c8 = i & 7;
            size_t go = (size_t)r * DD + c8 * 8;
            int so = r * AS + c8 * 8;
            *(uint4*)&sQh[so] = *(const uint4*)&gQh[go];
            *(uint4*)&sQl[so] = *(const uint4*)&gQl[go];
        }
    }
    __syncthreads();

    uint32_t qh[4][4], ql[4][4];
    {
        const int lrQ = w * 16 + (lane & 15);
        const int lcQ = (lane >> 4) * 8;
        const uint32_t bQh = sb;
        const uint32_t bQl = sb + 128 * AS * 2;
#pragma unroll
        for (int kb = 0; kb < 4; kb++) {
            uint32_t off = (lrQ * AS + kb * 16 + lcQ) * 2;
            ldsm4(qh[kb], bQh + off);
            ldsm4(ql[kb], bQl + off);
        }
    }
    __syncthreads();

    float m0 = -INFINITY, m1 = -INFINITY, l0 = 0.0f, l1 = 0.0f;
    float acc[8][4];
#pragma unroll
    for (int on = 0; on < 8; on++)
#pragma unroll
        for (int e = 0; e < 4; e++) acc[on][e] = 0.0f;

    const int lrK = ((lane >> 4) & 1) * 8 + (lane & 7);
    const int lcK = ((lane >> 3) & 1) * 8;
    const int lrV = ((lane >> 3) & 1) * 8 + (lane & 7);
    const int lcV = (lane >> 4) * 8;
    const float scale2 = 0.125f * LOG2E;
    const size_t gKV0 = (size_t)(b * SSQ) * DD + h * DKK;

    att_stage_load(sb, Kh, Kl, Vh, Vl, gKV0, tid);
    if (tid < 16) CP16(sbias_u32 + tid * 16, &mb[b * SSQ + tid * 4]);
    CPCOMMIT();

    for (int t = 0; t < 32; ++t) {
        const int st = t & 1;
        if (t < 31) {
            att_stage_load(sb + (st ^ 1) * AT_STAGEB, Kh, Kl, Vh, Vl,
                           gKV0 + (size_t)(t + 1) * 64 * DD, tid);
            if (tid < 16)
                CP16(sbias_u32 + (st ^ 1) * 256 + tid * 16,
                     &mb[b * SSQ + (t + 1) * 64 + tid * 4]);
            CPCOMMIT();
            CPWAIT1();
        } else {
            CPWAIT0();
        }
        __syncthreads();

        const uint32_t bKh = sb + st * AT_STAGEB;
        const uint32_t bKl = bKh + AT_TILEB;
        const uint32_t bVh = bKh + 2 * AT_TILEB;
        const uint32_t bVl = bKh + 3 * AT_TILEB;

        // ---- S = Q K^T : process njp-pairs, term-major (chain distance 4) ----
        float s[8][4];
#pragma unroll
        for (int nj = 0; nj < 8; nj++)
#pragma unroll
            for (int e = 0; e < 4; e++) s[nj][e] = 0.0f;

#pragma unroll
        for (int kb = 0; kb < 4; kb++) {
#pragma unroll
            for (int np = 0; np < 2; np++) {
                uint32_t kh0[4], kl0[4], kh1[4], kl1[4];
                uint32_t off0 = (((np * 2 + 0) * 16 + lrK) * AS + kb * 16 + lcK) * 2;
                uint32_t off1 = (((np * 2 + 1) * 16 + lrK) * AS + kb * 16 + lcK) * 2;
                ldsm4(kh0, bKh + off0);
                ldsm4(kl0, bKl + off0);
                ldsm4(kh1, bKh + off1);
                ldsm4(kl1, bKl + off1);
                float* c0 = s[np * 4 + 0];
                float* c1 = s[np * 4 + 1];
                float* c2 = s[np * 4 + 2];
                float* c3 = s[np * 4 + 3];
                // hh
                mma16816(c0, qh[kb], kh0[0], kh0[1]);
                mma16816(c1, qh[kb], kh0[2], kh0[3]);
                mma16816(c2, qh[kb], kh1[0], kh1[1]);
                mma16816(c3, qh[kb], kh1[2], kh1[3]);
                // hl
                mma16816(c0, qh[kb], kl0[0], kl0[1]);
                mma16816(c1, qh[kb], kl0[2], kl0[3]);
                mma16816(c2, qh[kb], kl1[0], kl1[1]);
                mma16816(c3, qh[kb], kl1[2], kl1[3]);
                // lh
                mma16816(c0, ql[kb], kh0[0], kh0[1]);
                mma16816(c1, ql[kb], kh0[2], kh0[3]);
                mma16816(c2, ql[kb], kh1[0], kh1[1]);
                mma16816(c3, ql[kb], kh1[2], kh1[3]);
            }
        }

        // ---- scale + mask bias (exp2 domain) ----
#pragma unroll
        for (int nj = 0; nj < 8; nj++) {
            float b0 = sBias[st][nj * 8 + c * 2];
            float b1 = sBias[st][nj * 8 + c * 2 + 1];
            s[nj][0] = fmaf(s[nj][0], scale2, b0);
            s[nj][1] = fmaf(s[nj][1], scale2, b1);
            s[nj][2] = fmaf(s[nj][2], scale2, b0);
            s[nj][3] = fmaf(s[nj][3], scale2, b1);
        }

        // ---- online softmax (exp2 domain) ----
        float mx0 = -INFINITY, mx1 = -INFINITY;
#pragma unroll
        for (int nj = 0; nj < 8; nj++) {
            mx0 = fmaxf(mx0, fmaxf(s[nj][0], s[nj][1]));
            mx1 = fmaxf(mx1, fmaxf(s[nj][2], s[nj][3]));
        }
        mx0 = fmaxf(mx0, __shfl_xor_sync(0xffffffffu, mx0, 1));
        mx0 = fmaxf(mx0, __shfl_xor_sync(0xffffffffu, mx0, 2));
        mx1 = fmaxf(mx1, __shfl_xor_sync(0xffffffffu, mx1, 1));
        mx1 = fmaxf(mx1, __shfl_xor_sync(0xffffffffu, mx1, 2));
        float mn0 = fmaxf(m0, mx0), mn1 = fmaxf(m1, mx1);
        float f0 = ex2f(m0 - mn0), f1 = ex2f(m1 - mn1);
        m0 = mn0; m1 = mn1;

        float sum0 = 0.0f, sum1 = 0.0f;
#pragma unroll
        for (int nj = 0; nj < 8; nj++) {
            s[nj][0] = ex2f(s[nj][0] - m0);
            s[nj][1] = ex2f(s[nj][1] - m0);
            s[nj][2] = ex2f(s[nj][2] - m1);
            s[nj][3] = ex2f(s[nj][3] - m1);
            sum0 += s[nj][0] + s[nj][1];
            sum1 += s[nj][2] + s[nj][3];
        }
        sum0 += __shfl_xor_sync(0xffffffffu, sum0, 1);
        sum0 += __shfl_xor_sync(0xffffffffu, sum0, 2);
        sum1 += __shfl_xor_sync(0xffffffffu, sum1, 1);
        sum1 += __shfl_xor_sync(0xffffffffu, sum1, 2);
        l0 = l0 * f0 + sum0;
        l1 = l1 * f1 + sum1;
#pragma unroll
        for (int on = 0; on < 8; on++) {
            acc[on][0] *= f0; acc[on][1] *= f0;
            acc[on][2] *= f1; acc[on][3] *= f1;
        }

        // ---- O += P V : onp-pairs, term-major ----
#pragma unroll
        for (int kb2 = 0; kb2 < 4; kb2++) {
            uint32_t pah[4], pal[4];
#pragma unroll
            for (int q2 = 0; q2 < 2; q2++) {
                float* sp = s[2 * kb2 + q2];
                bf162 h01 = __float22bfloat162_rn(make_float2(sp[0], sp[1]));
                bf162 h23 = __float22bfloat162_rn(make_float2(sp[2], sp[3]));
                bf162 l01 = __float22bfloat162_rn(make_float2(
                    sp[0] - __low2float(h01), sp[1] - __high2float(h01)));
                bf162 l23 = __float22bfloat162_rn(make_float2(
                    sp[2] - __low2float(h23), sp[3] - __high2float(h23)));
                pah[q2 * 2] = bits(h01); pah[q2 * 2 + 1] = bits(h23);
                pal[q2 * 2] = bits(l01); pal[q2 * 2 + 1] = bits(l23);
            }
#pragma unroll
            for (int op = 0; op < 2; op++) {
                uint32_t vh0[4], vl0[4], vh1[4], vl1[4];
                uint32_t off0 = ((kb2 * 16 + lrV) * AS + (op * 2 + 0) * 16 + lcV) * 2;
                uint32_t off1 = ((kb2 * 16 + lrV) * AS + (op * 2 + 1) * 16 + lcV) * 2;
                ldsm4t(vh0, bVh + off0);
                ldsm4t(vl0, bVl + off0);
                ldsm4t(vh1, bVh + off1);
                ldsm4t(vl1, bVl + off1);
                float* c0 = acc[op * 4 + 0];
                float* c1 = acc[op * 4 + 1];
                float* c2 = acc[op * 4 + 2];
                float* c3 = acc[op * 4 + 3];
                // hh
                mma16816(c0, pah, vh0[0], vh0[1]);
                mma16816(c1, pah, vh0[2], vh0[3]);
                mma16816(c2, pah, vh1[0], vh1[1]);
                mma16816(c3, pah, vh1[2], vh1[3]);
                // hl
                mma16816(c0, pah, vl0[0], vl0[1]);
                mma16816(c1, pah, vl0[2], vl0[3]);
                mma16816(c2, pah, vl1[0], vl1[1]);
                mma16816(c3, pah, vl1[2], vl1[3]);
                // lh
                mma16816(c0, pal, vh0[0], vh0[1]);
                mma16816(c1, pal, vh0[2], vh0[3]);
                mma16816(c2, pal, vh1[0], vh1[1]);
                mma16816(c3, pal, vh1[2], vh1[3]);
            }
        }
        __syncthreads();
    }

    // ---- epilogue ----
    float inv0 = 1.0f / l0, inv1 = 1.0f / l1;
    int rowg = b * SSQ + q0 + w * 16 + g;
#pragma unroll
    for (int on = 0; on < 8; on++) {
        int col = h * DKK + on * 8 + c * 2;
        float x0 = acc[on][0] * inv0, x1 = acc[on][1] * inv0;
        float x2 = acc[on][2] * inv1, x3 = acc[on][3] * inv1;
        bf162 h01 = __float22bfloat162_rn(make_float2(x0, x1));
        bf162 h23 = __float22bfloat162_rn(make_float2(x2, x3));
        bf162 l01 = __float22bfloat162_rn(make_float2(
            x0 - __low2float(h01), x1 - __high2float(h01)));
        bf162 l23 = __float22bfloat162_rn(make_float2(
            x2 - __low2float(h23), x3 - __high2float(h23)));
        *(bf162*)&Oh[(size_t)rowg * DD + col] = h01;
        *(bf162*)&Ol[(size_t)rowg * DD + col] = l01;
        *(bf162*)&Oh[(size_t)(rowg + 8) * DD + col] = h23;
        *(bf162*)&Ol[(size_t)(rowg + 8) * DD + col] = l23;
    }
}

// ---------------------------------------------------------------------------
// Launch.  Our launch index 3 is the one ncu captures -> flash_mma_k.
// ---------------------------------------------------------------------------
extern "C" void kernel_launch(void* const* d_in, const int* in_sizes, int n_in,
                              void* d_out, int out_size)
{
    const float* q    = (const float*)d_in[0];
    const float* k    = (const float*)d_in[1];
    const float* v    = (const float*)d_in[2];
    const int*   mask = (const int*)  d_in[3];
    const float* Wq   = (const float*)d_in[4];
    const float* bq   = (const float*)d_in[5];
    const float* Wk   = (const float*)d_in[6];
    const float* bk   = (const float*)d_in[7];
    const float* Wv   = (const float*)d_in[8];
    const float* bv   = (const float*)d_in[9];
    const float* Wo   = (const float*)d_in[10];
    const float* bo   = (const float*)d_in[11];
    float* out = (float*)d_out;

    bf16 *qAh, *qAl, *kAh, *kAl, *vAh, *vAl;
    bf16 *WqH, *WqL, *WkH, *WkL, *WvH, *WvL, *WoH, *WoL;
    bf16 *Qh, *Ql, *Kh, *Kl, *Vh, *Vl, *Oh, *Ol;
    float* mb;
    cudaGetSymbolAddress((void**)&qAh, g_qAh); cudaGetSymbolAddress((void**)&qAl, g_qAl);
    cudaGetSymbolAddress((void**)&kAh, g_kAh); cudaGetSymbolAddress((void**)&kAl, g_kAl);
    cudaGetSymbolAddress((void**)&vAh, g_vAh); cudaGetSymbolAddress((void**)&vAl, g_vAl);
    cudaGetSymbolAddress((void**)&WqH, g_WqH); cudaGetSymbolAddress((void**)&WqL, g_WqL);
    cudaGetSymbolAddress((void**)&WkH, g_WkH); cudaGetSymbolAddress((void**)&WkL, g_WkL);
    cudaGetSymbolAddress((void**)&WvH, g_WvH); cudaGetSymbolAddress((void**)&WvL, g_WvL);
    cudaGetSymbolAddress((void**)&WoH, g_WoH); cudaGetSymbolAddress((void**)&WoL, g_WoL);
    cudaGetSymbolAddress((void**)&Qh, g_Qh);   cudaGetSymbolAddress((void**)&Ql, g_Ql);
    cudaGetSymbolAddress((void**)&Kh, g_Kh);   cudaGetSymbolAddress((void**)&Kl, g_Kl);
    cudaGetSymbolAddress((void**)&Vh, g_Vh);   cudaGetSymbolAddress((void**)&Vl, g_Vl);
    cudaGetSymbolAddress((void**)&Oh, g_Oh);   cudaGetSymbolAddress((void**)&Ol, g_Ol);
    cudaGetSymbolAddress((void**)&mb, g_mbias);

    cudaFuncSetAttribute(gemm3_mma,
                         cudaFuncAttributeMaxDynamicSharedMemorySize, GT_SMEM);
    cudaFuncSetAttribute(gemm_out_mma,
                         cudaFuncAttributeMaxDynamicSharedMemorySize, GT_SMEM);
    cudaFuncSetAttribute(flash_mma_k,
                         cudaFuncAttributeMaxDynamicSharedMemorySize, AT_SMEM);

    // 0: split q,k,v
    split3_k<<<1024, 256>>>(q, k, v, qAh, qAl, kAh, kAl, vAh, vAl);
    // 1: split weights + mask bias
    splitW4m_k<<<1024, 256>>>(Wq, Wk, Wv, Wo, WqH, WqL, WkH, WkL,
                              WvH, WvL, WoH, WoL, mask, mb);
    // 2: fused QKV projections
    G3Args p;
    p.Ah[0] = qAh; p.Al[0] = qAl; p.Bh[0] = WqH; p.Bl[0] = WqL;
    p.bias[0] = bq; p.Ch[0] = Qh; p.Cl[0] = Ql;
    p.Ah[1] = kAh; p.Al[1] = kAl; p.Bh[1] = WkH; p.Bl[1] = WkL;
    p.bias[1] = bk; p.Ch[1] = Kh; p.Cl[1] = Kl;
    p.Ah[2] = vAh; p.Al[2] = vAl; p.Bh[2] = WvH; p.Bl[2] = WvL;
    p.bias[2] = bv; p.Ch[2] = Vh; p.Cl[2] = Vl;
    dim3 gg3(DD / 128, MTOT / 128, 3);
    gemm3_mma<<<gg3, 256, GT_SMEM>>>(p);
    // 3: attention (profiled by ncu)
    dim3 ga(SSQ / 128, BB * HHD);
    flash_mma_k<<<ga, 256, AT_SMEM>>>(Qh, Ql, Kh, Kl, Vh, Vl, mb, Oh, Ol);
    // 4: output projection
    dim3 gg(DD / 128, MTOT / 128);
    gemm_out_mma<<<gg, 256, GT_SMEM>>>(Oh, Ol, WoH, WoL, bo, out);
}

// round 9
// speedup vs baseline: 4.5675x; 1.5135x over previous
#include <cuda_runtime.h>
#include <cuda_bf16.h>
#include <math.h>
#include <stdint.h>

// Problem dims
#define BB   2
#define SSQ  2048
#define DD   1024
#define HHD  16
#define DKK  64
#define MTOT (BB * SSQ)   // 4096

typedef __nv_bfloat16 bf16;
typedef __nv_bfloat162 bf162;

#define LOG2E 1.44269504f

// ---------------------------------------------------------------------------
// Scratch (__device__ globals; no allocation allowed)
// ---------------------------------------------------------------------------
__device__ bf16 g_qAh[MTOT * DD], g_qAl[MTOT * DD];
__device__ bf16 g_kAh[MTOT * DD], g_kAl[MTOT * DD];   // compacted k input
__device__ bf16 g_vAh[MTOT * DD], g_vAl[MTOT * DD];   // compacted v input
__device__ bf16 g_WqH[DD * DD], g_WqL[DD * DD];
__device__ bf16 g_WkH[DD * DD], g_WkL[DD * DD];
__device__ bf16 g_WvH[DD * DD], g_WvL[DD * DD];
__device__ bf16 g_WoH[DD * DD], g_WoL[DD * DD];
__device__ bf16 g_Qh[MTOT * DD], g_Ql[MTOT * DD];
__device__ bf16 g_Kh[MTOT * DD], g_Kl[MTOT * DD];     // compacted projected K
__device__ bf16 g_Vh[MTOT * DD], g_Vl[MTOT * DD];     // compacted projected V
__device__ bf16 g_Oh[MTOT * DD], g_Ol[MTOT * DD];
__device__ float g_cbias[MTOT];                       // compacted bias
__device__ int   g_idx[MTOT];                         // compaction permutation
__device__ int   g_nv[BB];                            // valid keys per batch

// ---------------------------------------------------------------------------
// PTX helpers
// ---------------------------------------------------------------------------
__device__ __forceinline__ uint32_t smem_u32(const void* p) {
    uint32_t a;
    asm("{ .reg .u64 t; cvta.to.shared.u64 t, %1; cvt.u32.u64 %0, t; }"
        : "=r"(a) : "l"(p));
    return a;
}
__device__ __forceinline__ void ldsm4(uint32_t r[4], uint32_t a) {
    asm volatile("ldmatrix.sync.aligned.m8n8.x4.shared.b16 {%0,%1,%2,%3}, [%4];"
                 : "=r"(r[0]), "=r"(r[1]), "=r"(r[2]), "=r"(r[3]) : "r"(a));
}
__device__ __forceinline__ void ldsm4t(uint32_t r[4], uint32_t a) {
    asm volatile("ldmatrix.sync.aligned.m8n8.x4.trans.shared.b16 {%0,%1,%2,%3}, [%4];"
                 : "=r"(r[0]), "=r"(r[1]), "=r"(r[2]), "=r"(r[3]) : "r"(a));
}
__device__ __forceinline__ void mma16816(float* c, const uint32_t* a,
                                         uint32_t b0, uint32_t b1) {
    asm("mma.sync.aligned.m16n8k16.row.col.f32.bf16.bf16.f32 "
        "{%0,%1,%2,%3}, {%4,%5,%6,%7}, {%8,%9}, {%0,%1,%2,%3};"
        : "+f"(c[0]), "+f"(c[1]), "+f"(c[2]), "+f"(c[3])
        : "r"(a[0]), "r"(a[1]), "r"(a[2]), "r"(a[3]), "r"(b0), "r"(b1));
}
__device__ __forceinline__ uint32_t bits(bf162 h) {
    return *reinterpret_cast<uint32_t*>(&h);
}
__device__ __forceinline__ float ex2f(float x) {
    float y;
    asm("ex2.approx.ftz.f32 %0, %1;" : "=f"(y) : "f"(x));
    return y;
}
#define CP16(dst, src) \
    asm volatile("cp.async.cg.shared.global [%0], [%1], 16;" \
                 :: "r"(dst), "l"(src) : "memory")
#define CPCOMMIT() asm volatile("cp.async.commit_group;" ::: "memory")
#define CPWAIT1()  asm volatile("cp.async.wait_group 1;" ::: "memory")
#define CPWAIT0()  asm volatile("cp.async.wait_group 0;" ::: "memory")

// defensive clamp for scratch-derived control values
__device__ __forceinline__ int clamp_nv(int x) {
    return x < 0 ? 0 : (x > SSQ ? SSQ : x);
}

// ---------------------------------------------------------------------------
// Mask compaction: deterministic (stable) prefix scan, one block per batch.
// ---------------------------------------------------------------------------
__global__ void scan_mask_k(const int* __restrict__ mask, int* __restrict__ idx,
                            int* __restrict__ nv, float* __restrict__ cbias)
{
    __shared__ int warp_sums[16];
    __shared__ int s_nv;
    const int b = blockIdx.x;
    const int tid = threadIdx.x;          // 512 threads, 4 keys each
    const int lane = tid & 31, wrp = tid >> 5;
    const int base = tid * 4;

    int m[4];
#pragma unroll
    for (int u = 0; u < 4; u++) m[u] = mask[b * SSQ + base + u] != 0;
    int local = m[0] + m[1] + m[2] + m[3];

    int pre = local;   // inclusive warp scan
#pragma unroll
    for (int d = 1; d < 32; d <<= 1) {
        int y = __shfl_up_sync(0xffffffffu, pre, d);
        if (lane >= d) pre += y;
    }
    if (lane == 31) warp_sums[wrp] = pre;
    __syncthreads();
    if (wrp == 0) {
        int ws = (lane < 16) ? warp_sums[lane] : 0;
#pragma unroll
        for (int d = 1; d < 16; d <<= 1) {
            int y = __shfl_up_sync(0xffffffffu, ws, d);
            if (lane >= d) ws += y;
        }
        if (lane < 16) warp_sums[lane] = ws;
        if (lane == 15) s_nv = ws;
    }
    __syncthreads();

    int offset = (pre - local) + (wrp > 0 ? warp_sums[wrp - 1] : 0);
#pragma unroll
    for (int u = 0; u < 4; u++) {
        if (m[u] && offset < SSQ) { idx[b * SSQ + offset] = base + u; offset++; }
    }
    const int total = s_nv;
    if (tid == 0) nv[b] = total;
#pragma unroll
    for (int u = 0; u < 4; u++) {
        int j = base + u;
        cbias[b * SSQ + j] = (j < total) ? 0.0f : -1e9f * LOG2E;
    }
}

// ---------------------------------------------------------------------------
// split helpers
// ---------------------------------------------------------------------------
__device__ __forceinline__ void split_store(float4 v, bf16* __restrict__ hi,
                                            bf16* __restrict__ lo, int i)
{
    bf16 h0 = __float2bfloat16_rn(v.x), h1 = __float2bfloat16_rn(v.y);
    bf16 h2 = __float2bfloat16_rn(v.z), h3 = __float2bfloat16_rn(v.w);
    bf16 l0 = __float2bfloat16_rn(v.x - __bfloat162float(h0));
    bf16 l1 = __float2bfloat16_rn(v.y - __bfloat162float(h1));
    bf16 l2 = __float2bfloat16_rn(v.z - __bfloat162float(h2));
    bf16 l3 = __float2bfloat16_rn(v.w - __bfloat162float(h3));
    ((bf162*)hi)[2 * i + 0] = bf162(h0, h1);
    ((bf162*)hi)[2 * i + 1] = bf162(h2, h3);
    ((bf162*)lo)[2 * i + 0] = bf162(l0, l1);
    ((bf162*)lo)[2 * i + 1] = bf162(l2, l3);
}

// q full split + k,v gathered-compacted split (+ zero pad to rnd128)
__global__ void split_gather_k(const float* __restrict__ q,
                               const float* __restrict__ k,
                               const float* __restrict__ v,
                               bf16* __restrict__ qh, bf16* __restrict__ ql,
                               bf16* __restrict__ kch, bf16* __restrict__ kcl,
                               bf16* __restrict__ vch, bf16* __restrict__ vcl,
                               const int* __restrict__ idx,
                               const int* __restrict__ nv)
{
    const int n4q = MTOT * DD / 4;          // 1M float4 (q)
    const int n4kv = 2 * MTOT * DD / 4;     // 2M float4 (k + v compacted)
    int i = blockIdx.x * blockDim.x + threadIdx.x;
    int stride = gridDim.x * blockDim.x;
    for (; i < n4q + n4kv; i += stride) {
        if (i < n4q) {
            split_store(((const float4*)q)[i], qh, ql, i);
            continue;
        }
        int r = i - n4q;                    // [0, 2M)
        int tsel = r >> 20;                 // 0=k, 1=v
        int rem = r & ((1 << 20) - 1);
        int b = rem >> 19;
        int loc = rem & ((1 << 19) - 1);
        int row = loc >> 8;                 // 0..2047
        int c4 = loc & 255;
        int nvb = clamp_nv(nv[b]);
        int rnd = (nvb + 127) & ~127;
        if (row >= rnd) continue;
        bf16* hi = tsel ? vch : kch;
        bf16* lo = tsel ? vcl : kcl;
        int dsti = (b * SSQ + row) * 256 + c4;
        if (row < nvb) {
            const float* src = tsel ? v : k;
            int srow = idx[b * SSQ + row] & (SSQ - 1);
            split_store(((const float4*)src)[(b * SSQ + srow) * 256 + c4],
                        hi, lo, dsti);
        } else {
            split_store(make_float4(0.f, 0.f, 0.f, 0.f), hi, lo, dsti);
        }
    }
}

// 4 weight matrices in one kernel
__global__ void splitW4_k(const float* __restrict__ wq, const float* __restrict__ wk,
                          const float* __restrict__ wv, const float* __restrict__ wo,
                          bf16* __restrict__ qh, bf16* __restrict__ ql,
                          bf16* __restrict__ kh, bf16* __restrict__ kl,
                          bf16* __restrict__ vh, bf16* __restrict__ vl,
                          bf16* __restrict__ oh, bf16* __restrict__ ol)
{
    const int n4 = DD * DD / 4;
    int i = blockIdx.x * blockDim.x + threadIdx.x;
    int stride = gridDim.x * blockDim.x;
    for (; i < 4 * n4; i += stride) {
        if (i < n4)           split_store(((const float4*)wq)[i], qh, ql, i);
        else if (i < 2 * n4)  split_store(((const float4*)wk)[i - n4], kh, kl, i - n4);
        else if (i < 3 * n4)  split_store(((const float4*)wv)[i - 2 * n4], vh, vl, i - 2 * n4);
        else                  split_store(((const float4*)wo)[i - 3 * n4], oh, ol, i - 3 * n4);
    }
}

// ---------------------------------------------------------------------------
// GEMM tiles: 128x128, BK=32, 8 warps (4m x 2n), warp 32x64, cp.async 2-stage
// ---------------------------------------------------------------------------
#define GS 40
#define GT_TILEB  (128 * GS * 2)
#define GT_STAGEB (4 * GT_TILEB)
#define GT_SMEM   (2 * GT_STAGEB)

__device__ __forceinline__ void gemm_stage_load(
    uint32_t sbase, const bf16* __restrict__ gAh, const bf16* __restrict__ gAl,
    const bf16* __restrict__ gBh, const bf16* __restrict__ gBl,
    int k0, int tid)
{
#pragma unroll
    for (int i = tid; i < 512; i += 256) {
        int r = i >> 2, c4 = i & 3;
        size_t go = (size_t)r * DD + k0 + c4 * 8;
        uint32_t so = (uint32_t)(r * GS + c4 * 8) * 2;
        CP16(sbase + so,                gAh + go);
        CP16(sbase + GT_TILEB + so,     gAl + go);
        CP16(sbase + 2 * GT_TILEB + so, gBh + go);
        CP16(sbase + 3 * GT_TILEB + so, gBl + go);
    }
}

__device__ __forceinline__ void gemm_mainloop(
    uint32_t sb, const bf16* gAh, const bf16* gAl,
    const bf16* gBh, const bf16* gBl,
    int tid, int lane, int wm, int wn, float acc[2][8][4])
{
    const int lrA = wm * 32 + (lane & 15);
    const int lcA = (lane >> 4) * 8;
    const int lrB = wn * 64 + ((lane >> 4) & 1) * 8 + (lane & 7);
    const int lcB = ((lane >> 3) & 1) * 8;

    gemm_stage_load(sb, gAh, gAl, gBh, gBl, 0, tid);
    CPCOMMIT();

    for (int t = 0; t < 32; ++t) {
        const int st = t & 1;
        if (t < 31) {
            gemm_stage_load(sb + (st ^ 1) * GT_STAGEB, gAh, gAl, gBh, gBl,
                            (t + 1) * 32, tid);
            CPCOMMIT();
            CPWAIT1();
        } else {
            CPWAIT0();
        }
        __syncthreads();

        const uint32_t bAh = sb + st * GT_STAGEB;
        const uint32_t bAl = bAh + GT_TILEB;
        const uint32_t bBh = bAh + 2 * GT_TILEB;
        const uint32_t bBl = bAh + 3 * GT_TILEB;

#pragma unroll
        for (int kb = 0; kb < 2; kb++) {
            uint32_t ah[2][4], al[2][4];
#pragma unroll
            for (int mi = 0; mi < 2; mi++) {
                uint32_t off = ((lrA + mi * 16) * GS + kb * 16 + lcA) * 2;
                ldsm4(ah[mi], bAh + off);
                ldsm4(al[mi], bAl + off);
            }
#pragma unroll
            for (int njp = 0; njp < 4; njp++) {
                uint32_t off = ((lrB + njp * 16) * GS + kb * 16 + lcB) * 2;
                uint32_t bh[4], bl[4];
                ldsm4(bh, bBh + off);
                ldsm4(bl, bBl + off);
                float* c00 = acc[0][njp * 2];
                float* c01 = acc[0][njp * 2 + 1];
                float* c10 = acc[1][njp * 2];
                float* c11 = acc[1][njp * 2 + 1];
                mma16816(c00, ah[0], bh[0], bh[1]);
                mma16816(c10, ah[1], bh[0], bh[1]);
                mma16816(c01, ah[0], bh[2], bh[3]);
                mma16816(c11, ah[1], bh[2], bh[3]);
                mma16816(c00, ah[0], bl[0], bl[1]);
                mma16816(c10, ah[1], bl[0], bl[1]);
                mma16816(c01, ah[0], bl[2], bl[3]);
                mma16816(c11, ah[1], bl[2], bl[3]);
                mma16816(c00, al[0], bh[0], bh[1]);
                mma16816(c10, al[1], bh[0], bh[1]);
                mma16816(c01, al[0], bh[2], bh[3]);
                mma16816(c11, al[1], bh[2], bh[3]);
            }
        }
        __syncthreads();
    }
}

// Fused QKV projections; K/V (z>0) skip CTAs above the valid compacted rows
struct G3Args {
    const bf16 *Ah[3], *Al[3], *Bh[3], *Bl[3];
    const float* bias[3];
    bf16 *Ch[3], *Cl[3];
    const int* nv;
};

__global__ __launch_bounds__(256, 2) void gemm3_mma(G3Args p)
{
    extern __shared__ __align__(16) char dyn[];
    const uint32_t sb = smem_u32(dyn);
    const int z = blockIdx.z;
    const int bm = blockIdx.y * 128;
    const int bn = blockIdx.x * 128;

    if (z > 0) {   // K or V projection: skip masked-out row tiles
        int batch = bm >> 11;
        int local = bm & 2047;
        int rnd = (clamp_nv(p.nv[batch]) + 127) & ~127;
        if (local >= rnd) return;
    }

    const int tid  = threadIdx.x;
    const int lane = tid & 31;
    const int warp = tid >> 5;
    const int wm = warp & 3, wn = warp >> 2;

    float acc[2][8][4];
#pragma unroll
    for (int mi = 0; mi < 2; mi++)
#pragma unroll
        for (int nj = 0; nj < 8; nj++)
#pragma unroll
            for (int e = 0; e < 4; e++) acc[mi][nj][e] = 0.0f;

    gemm_mainloop(sb,
                  p.Ah[z] + (size_t)bm * DD, p.Al[z] + (size_t)bm * DD,
                  p.Bh[z] + (size_t)bn * DD, p.Bl[z] + (size_t)bn * DD,
                  tid, lane, wm, wn, acc);

    const float* bias = p.bias[z];
    bf16* Chi = p.Ch[z];
    bf16* Clo = p.Cl[z];
    const int g = lane >> 2, c = lane & 3;
#pragma unroll
    for (int mi = 0; mi < 2; mi++) {
#pragma unroll
        for (int nj = 0; nj < 8; nj++) {
            int row = bm + wm * 32 + mi * 16 + g;
            int col = bn + wn * 64 + nj * 8 + c * 2;
            float b0 = bias[col], b1 = bias[col + 1];
            float x0 = acc[mi][nj][0] + b0, x1 = acc[mi][nj][1] + b1;
            float x2 = acc[mi][nj][2] + b0, x3 = acc[mi][nj][3] + b1;
            bf162 h01 = __float22bfloat162_rn(make_float2(x0, x1));
            bf162 h23 = __float22bfloat162_rn(make_float2(x2, x3));
            bf162 l01 = __float22bfloat162_rn(make_float2(
                x0 - __low2float(h01), x1 - __high2float(h01)));
            bf162 l23 = __float22bfloat162_rn(make_float2(
                x2 - __low2float(h23), x3 - __high2float(h23)));
            *(bf162*)&Chi[(size_t)row * DD + col] = h01;
            *(bf162*)&Clo[(size_t)row * DD + col] = l01;
            *(bf162*)&Chi[(size_t)(row + 8) * DD + col] = h23;
            *(bf162*)&Clo[(size_t)(row + 8) * DD + col] = l23;
        }
    }
}

// Output projection (fp32 result)
__global__ __launch_bounds__(256, 2) void gemm_out_mma(
    const bf16* __restrict__ Ah, const bf16* __restrict__ Al,
    const bf16* __restrict__ Wh, const bf16* __restrict__ Wl,
    const float* __restrict__ bias, float* __restrict__ Cf)
{
    extern __shared__ __align__(16) char dyn[];
    const uint32_t sb = smem_u32(dyn);
    const int tid  = threadIdx.x;
    const int lane = tid & 31;
    const int warp = tid >> 5;
    const int wm = warp & 3, wn = warp >> 2;
    const int bm = blockIdx.y * 128;
    const int bn = blockIdx.x * 128;

    float acc[2][8][4];
#pragma unroll
    for (int mi = 0; mi < 2; mi++)
#pragma unroll
        for (int nj = 0; nj < 8; nj++)
#pragma unroll
            for (int e = 0; e < 4; e++) acc[mi][nj][e] = 0.0f;

    gemm_mainloop(sb,
                  Ah + (size_t)bm * DD, Al + (size_t)bm * DD,
                  Wh + (size_t)bn * DD, Wl + (size_t)bn * DD,
                  tid, lane, wm, wn, acc);

    const int g = lane >> 2, c = lane & 3;
#pragma unroll
    for (int mi = 0; mi < 2; mi++) {
#pragma unroll
        for (int nj = 0; nj < 8; nj++) {
            int row = bm + wm * 32 + mi * 16 + g;
            int col = bn + wn * 64 + nj * 8 + c * 2;
            float b0 = bias[col], b1 = bias[col + 1];
            *(float2*)&Cf[(size_t)row * DD + col] =
                make_float2(acc[mi][nj][0] + b0, acc[mi][nj][1] + b1);
            *(float2*)&Cf[(size_t)(row + 8) * DD + col] =
                make_float2(acc[mi][nj][2] + b0, acc[mi][nj][3] + b1);
        }
    }
}

// ---------------------------------------------------------------------------
// Flash attention over COMPACTED keys: nt = ceil(nv/64) tiles.
// ---------------------------------------------------------------------------
#define AS 72
#define AT_TILEB  (64 * AS * 2)
#define AT_STAGEB (4 * AT_TILEB)
#define AT_SMEM   (2 * AT_STAGEB)

__device__ __forceinline__ void att_stage_load(
    uint32_t sbase, const bf16* __restrict__ Kh, const bf16* __restrict__ Kl,
    const bf16* __restrict__ Vh, const bf16* __restrict__ Vl,
    size_t gbase, int tid)
{
#pragma unroll
    for (int i = tid; i < 512; i += 256) {
        int r = i >> 3, c8 = i & 7;
        size_t go = gbase + (size_t)r * DD + c8 * 8;
        uint32_t so = (uint32_t)(r * AS + c8 * 8) * 2;
        CP16(sbase + so,                Kh + go);
        CP16(sbase + AT_TILEB + so,     Kl + go);
        CP16(sbase + 2 * AT_TILEB + so, Vh + go);
        CP16(sbase + 3 * AT_TILEB + so, Vl + go);
    }
}

__global__ __launch_bounds__(256) void flash_mma_k(
    const bf16* __restrict__ Qh, const bf16* __restrict__ Ql,
    const bf16* __restrict__ Kh, const bf16* __restrict__ Kl,
    const bf16* __restrict__ Vh, const bf16* __restrict__ Vl,
    const float* __restrict__ cb, const int* __restrict__ nvp,
    bf16* __restrict__ Oh, bf16* __restrict__ Ol)
{
    extern __shared__ __align__(16) char dyn[];
    __shared__ __align__(16) float sBias[2][64];
    const uint32_t sb = smem_u32(dyn);
    const uint32_t sbias_u32 = smem_u32(&sBias[0][0]);

    const int tid  = threadIdx.x;
    const int lane = tid & 31;
    const int w    = tid >> 5;
    const int b  = blockIdx.y >> 4;
    const int h  = blockIdx.y & 15;
    const int q0 = blockIdx.x * 128;
    const int g = lane >> 2, c = lane & 3;
    const int nt = (clamp_nv(nvp[b]) + 63) >> 6;

    // ---- Phase 1: Q tile -> fragments ----
    {
        bf16* sQh = (bf16*)dyn;
        bf16* sQl = (bf16*)(dyn + 128 * AS * 2);
        const bf16* gQh = Qh + (size_t)(b * SSQ + q0) * DD + h * DKK;
        const bf16* gQl = Ql + (size_t)(b * SSQ + q0) * DD + h * DKK;
#pragma unroll
        for (int i = tid; i < 1024; i += 256) {
            int r = i >> 3, c8 = i & 7;
            size_t go = (size_t)r * DD + c8 * 8;
            int so = r * AS + c8 * 8;
            *(uint4*)&sQh[so] = *(const uint4*)&gQh[go];
            *(uint4*)&sQl[so] = *(const uint4*)&gQl[go];
        }
    }
    __syncthreads();

    uint32_t qh[4][4], ql[4][4];
    {
        const int lrQ = w * 16 + (lane & 15);
        const int lcQ = (lane >> 4) * 8;
        const uint32_t bQh = sb;
        const uint32_t bQl = sb + 128 * AS * 2;
#pragma unroll
        for (int kb = 0; kb < 4; kb++) {
            uint32_t off = (lrQ * AS + kb * 16 + lcQ) * 2;
            ldsm4(qh[kb], bQh + off);
            ldsm4(ql[kb], bQl + off);
        }
    }
    __syncthreads();

    float m0 = -INFINITY, m1 = -INFINITY, l0 = 0.0f, l1 = 0.0f;
    float acc[8][4];
#pragma unroll
    for (int on = 0; on < 8; on++)
#pragma unroll
        for (int e = 0; e < 4; e++) acc[on][e] = 0.0f;

    const int lrK = ((lane >> 4) & 1) * 8 + (lane & 7);
    const int lcK = ((lane >> 3) & 1) * 8;
    const int lrV = ((lane >> 3) & 1) * 8 + (lane & 7);
    const int lcV = (lane >> 4) * 8;
    const float scale2 = 0.125f * LOG2E;
    const size_t gKV0 = (size_t)(b * SSQ) * DD + h * DKK;

    if (nt > 0) {
        att_stage_load(sb, Kh, Kl, Vh, Vl, gKV0, tid);
        if (tid < 16) CP16(sbias_u32 + tid * 16, &cb[b * SSQ + tid * 4]);
        CPCOMMIT();
    }

    for (int t = 0; t < nt; ++t) {
        const int st = t & 1;
        if (t + 1 < nt) {
            att_stage_load(sb + (st ^ 1) * AT_STAGEB, Kh, Kl, Vh, Vl,
                           gKV0 + (size_t)(t + 1) * 64 * DD, tid);
            if (tid < 16)
                CP16(sbias_u32 + (st ^ 1) * 256 + tid * 16,
                     &cb[b * SSQ + (t + 1) * 64 + tid * 4]);
            CPCOMMIT();
            CPWAIT1();
        } else {
            CPWAIT0();
        }
        __syncthreads();

        const uint32_t bKh = sb + st * AT_STAGEB;
        const uint32_t bKl = bKh + AT_TILEB;
        const uint32_t bVh = bKh + 2 * AT_TILEB;
        const uint32_t bVl = bKh + 3 * AT_TILEB;

        // ---- S = Q K^T ----
        float s[8][4];
#pragma unroll
        for (int nj = 0; nj < 8; nj++)
#pragma unroll
            for (int e = 0; e < 4; e++) s[nj][e] = 0.0f;

#pragma unroll
        for (int kb = 0; kb < 4; kb++) {
#pragma unroll
            for (int np = 0; np < 2; np++) {
                uint32_t kh0[4], kl0[4], kh1[4], kl1[4];
                uint32_t off0 = (((np * 2 + 0) * 16 + lrK) * AS + kb * 16 + lcK) * 2;
                uint32_t off1 = (((np * 2 + 1) * 16 + lrK) * AS + kb * 16 + lcK) * 2;
                ldsm4(kh0, bKh + off0);
                ldsm4(kl0, bKl + off0);
                ldsm4(kh1, bKh + off1);
                ldsm4(kl1, bKl + off1);
                float* c0 = s[np * 4 + 0];
                float* c1 = s[np * 4 + 1];
                float* c2 = s[np * 4 + 2];
                float* c3 = s[np * 4 + 3];
                mma16816(c0, qh[kb], kh0[0], kh0[1]);
                mma16816(c1, qh[kb], kh0[2], kh0[3]);
                mma16816(c2, qh[kb], kh1[0], kh1[1]);
                mma16816(c3, qh[kb], kh1[2], kh1[3]);
                mma16816(c0, qh[kb], kl0[0], kl0[1]);
                mma16816(c1, qh[kb], kl0[2], kl0[3]);
                mma16816(c2, qh[kb], kl1[0], kl1[1]);
                mma16816(c3, qh[kb], kl1[2], kl1[3]);
                mma16816(c0, ql[kb], kh0[0], kh0[1]);
                mma16816(c1, ql[kb], kh0[2], kh0[3]);
                mma16816(c2, ql[kb], kh1[0], kh1[1]);
                mma16816(c3, ql[kb], kh1[2], kh1[3]);
            }
        }

        // ---- scale + bias (exp2 domain; pad slots get -BIG) ----
#pragma unroll
        for (int nj = 0; nj < 8; nj++) {
            float b0 = sBias[st][nj * 8 + c * 2];
            float b1 = sBias[st][nj * 8 + c * 2 + 1];
            s[nj][0] = fmaf(s[nj][0], scale2, b0);
            s[nj][1] = fmaf(s[nj][1], scale2, b1);
            s[nj][2] = fmaf(s[nj][2], scale2, b0);
            s[nj][3] = fmaf(s[nj][3], scale2, b1);
        }

        // ---- online softmax ----
        float mx0 = -INFINITY, mx1 = -INFINITY;
#pragma unroll
        for (int nj = 0; nj < 8; nj++) {
            mx0 = fmaxf(mx0, fmaxf(s[nj][0], s[nj][1]));
            mx1 = fmaxf(mx1, fmaxf(s[nj][2], s[nj][3]));
        }
        mx0 = fmaxf(mx0, __shfl_xor_sync(0xffffffffu, mx0, 1));
        mx0 = fmaxf(mx0, __shfl_xor_sync(0xffffffffu, mx0, 2));
        mx1 = fmaxf(mx1, __shfl_xor_sync(0xffffffffu, mx1, 1));
        mx1 = fmaxf(mx1, __shfl_xor_sync(0xffffffffu, mx1, 2));
        float mn0 = fmaxf(m0, mx0), mn1 = fmaxf(m1, mx1);
        float f0 = ex2f(m0 - mn0), f1 = ex2f(m1 - mn1);
        m0 = mn0; m1 = mn1;

        float sum0 = 0.0f, sum1 = 0.0f;
#pragma unroll
        for (int nj = 0; nj < 8; nj++) {
            s[nj][0] = ex2f(s[nj][0] - m0);
            s[nj][1] = ex2f(s[nj][1] - m0);
            s[nj][2] = ex2f(s[nj][2] - m1);
            s[nj][3] = ex2f(s[nj][3] - m1);
            sum0 += s[nj][0] + s[nj][1];
            sum1 += s[nj][2] + s[nj][3];
        }
        sum0 += __shfl_xor_sync(0xffffffffu, sum0, 1);
        sum0 += __shfl_xor_sync(0xffffffffu, sum0, 2);
        sum1 += __shfl_xor_sync(0xffffffffu, sum1, 1);
        sum1 += __shfl_xor_sync(0xffffffffu, sum1, 2);
        l0 = l0 * f0 + sum0;
        l1 = l1 * f1 + sum1;
#pragma unroll
        for (int on = 0; on < 8; on++) {
            acc[on][0] *= f0; acc[on][1] *= f0;
            acc[on][2] *= f1; acc[on][3] *= f1;
        }

        // ---- O += P V ----
#pragma unroll
        for (int kb2 = 0; kb2 < 4; kb2++) {
            uint32_t pah[4], pal[4];
#pragma unroll
            for (int q2 = 0; q2 < 2; q2++) {
                float* sp = s[2 * kb2 + q2];
                bf162 h01 = __float22bfloat162_rn(make_float2(sp[0], sp[1]));
                bf162 h23 = __float22bfloat162_rn(make_float2(sp[2], sp[3]));
                bf162 l01 = __float22bfloat162_rn(make_float2(
                    sp[0] - __low2float(h01), sp[1] - __high2float(h01)));
                bf162 l23 = __float22bfloat162_rn(make_float2(
                    sp[2] - __low2float(h23), sp[3] - __high2float(h23)));
                pah[q2 * 2] = bits(h01); pah[q2 * 2 + 1] = bits(h23);
                pal[q2 * 2] = bits(l01); pal[q2 * 2 + 1] = bits(l23);
            }
#pragma unroll
            for (int op = 0; op < 2; op++) {
                uint32_t vh0[4], vl0[4], vh1[4], vl1[4];
                uint32_t off0 = ((kb2 * 16 + lrV) * AS + (op * 2 + 0) * 16 + lcV) * 2;
                uint32_t off1 = ((kb2 * 16 + lrV) * AS + (op * 2 + 1) * 16 + lcV) * 2;
                ldsm4t(vh0, bVh + off0);
                ldsm4t(vl0, bVl + off0);
                ldsm4t(vh1, bVh + off1);
                ldsm4t(vl1, bVl + off1);
                float* c0 = acc[op * 4 + 0];
                float* c1 = acc[op * 4 + 1];
                float* c2 = acc[op * 4 + 2];
                float* c3 = acc[op * 4 + 3];
                mma16816(c0, pah, vh0[0], vh0[1]);
                mma16816(c1, pah, vh0[2], vh0[3]);
                mma16816(c2, pah, vh1[0], vh1[1]);
                mma16816(c3, pah, vh1[2], vh1[3]);
                mma16816(c0, pah, vl0[0], vl0[1]);
                mma16816(c1, pah, vl0[2], vl0[3]);
                mma16816(c2, pah, vl1[0], vl1[1]);
                mma16816(c3, pah, vl1[2], vl1[3]);
                mma16816(c0, pal, vh0[0], vh0[1]);
                mma16816(c1, pal, vh0[2], vh0[3]);
                mma16816(c2, pal, vh1[0], vh1[1]);
                mma16816(c3, pal, vh1[2], vh1[3]);
            }
        }
        __syncthreads();
    }

    // ---- epilogue ----
    float inv0 = l0 > 0.f ? 1.0f / l0 : 0.f;
    float inv1 = l1 > 0.f ? 1.0f / l1 : 0.f;
    int rowg = b * SSQ + q0 + w * 16 + g;
#pragma unroll
    for (int on = 0; on < 8; on++) {
        int col = h * DKK + on * 8 + c * 2;
        float x0 = acc[on][0] * inv0, x1 = acc[on][1] * inv0;
        float x2 = acc[on][2] * inv1, x3 = acc[on][3] * inv1;
        bf162 h01 = __float22bfloat162_rn(make_float2(x0, x1));
        bf162 h23 = __float22bfloat162_rn(make_float2(x2, x3));
        bf162 l01 = __float22bfloat162_rn(make_float2(
            x0 - __low2float(h01), x1 - __high2float(h01)));
        bf162 l23 = __float22bfloat162_rn(make_float2(
            x2 - __low2float(h23), x3 - __high2float(h23)));
        *(bf162*)&Oh[(size_t)rowg * DD + col] = h01;
        *(bf162*)&Ol[(size_t)rowg * DD + col] = l01;
        *(bf162*)&Oh[(size_t)(rowg + 8) * DD + col] = h23;
        *(bf162*)&Ol[(size_t)(rowg + 8) * DD + col] = l23;
    }
}

// ---------------------------------------------------------------------------
// Launch. Index 3 (profiled) = gemm3_mma this round.
// ---------------------------------------------------------------------------
extern "C" void kernel_launch(void* const* d_in, const int* in_sizes, int n_in,
                              void* d_out, int out_size)
{
    const float* q    = (const float*)d_in[0];
    const float* k    = (const float*)d_in[1];
    const float* v    = (const float*)d_in[2];
    const int*   mask = (const int*)  d_in[3];
    const float* Wq   = (const float*)d_in[4];
    const float* bq   = (const float*)d_in[5];
    const float* Wk   = (const float*)d_in[6];
    const float* bk   = (const float*)d_in[7];
    const float* Wv   = (const float*)d_in[8];
    const float* bv   = (const float*)d_in[9];
    const float* Wo   = (const float*)d_in[10];
    const float* bo   = (const float*)d_in[11];
    float* out = (float*)d_out;

    bf16 *qAh, *qAl, *kAh, *kAl, *vAh, *vAl;
    bf16 *WqH, *WqL, *WkH, *WkL, *WvH, *WvL, *WoH, *WoL;
    bf16 *Qh, *Ql, *Kh, *Kl, *Vh, *Vl, *Oh, *Ol;
    float *cb; int *idx, *nv;
    cudaGetSymbolAddress((void**)&qAh, g_qAh); cudaGetSymbolAddress((void**)&qAl, g_qAl);
    cudaGetSymbolAddress((void**)&kAh, g_kAh); cudaGetSymbolAddress((void**)&kAl, g_kAl);
    cudaGetSymbolAddress((void**)&vAh, g_vAh); cudaGetSymbolAddress((void**)&vAl, g_vAl);
    cudaGetSymbolAddress((void**)&WqH, g_WqH); cudaGetSymbolAddress((void**)&WqL, g_WqL);
    cudaGetSymbolAddress((void**)&WkH, g_WkH); cudaGetSymbolAddress((void**)&WkL, g_WkL);
    cudaGetSymbolAddress((void**)&WvH, g_WvH); cudaGetSymbolAddress((void**)&WvL, g_WvL);
    cudaGetSymbolAddress((void**)&WoH, g_WoH); cudaGetSymbolAddress((void**)&WoL, g_WoL);
    cudaGetSymbolAddress((void**)&Qh, g_Qh);   cudaGetSymbolAddress((void**)&Ql, g_Ql);
    cudaGetSymbolAddress((void**)&Kh, g_Kh);   cudaGetSymbolAddress((void**)&Kl, g_Kl);
    cudaGetSymbolAddress((void**)&Vh, g_Vh);   cudaGetSymbolAddress((void**)&Vl, g_Vl);
    cudaGetSymbolAddress((void**)&Oh, g_Oh);   cudaGetSymbolAddress((void**)&Ol, g_Ol);
    cudaGetSymbolAddress((void**)&cb, g_cbias);
    cudaGetSymbolAddress((void**)&idx, g_idx);
    cudaGetSymbolAddress((void**)&nv, g_nv);

    cudaFuncSetAttribute(gemm3_mma,
                         cudaFuncAttributeMaxDynamicSharedMemorySize, GT_SMEM);
    cudaFuncSetAttribute(gemm_out_mma,
                         cudaFuncAttributeMaxDynamicSharedMemorySize, GT_SMEM);
    cudaFuncSetAttribute(flash_mma_k,
                         cudaFuncAttributeMaxDynamicSharedMemorySize, AT_SMEM);

    // 0: mask scan/compaction
    scan_mask_k<<<BB, 512>>>(mask, idx, nv, cb);
    // 1: split q (full) + k,v (gathered/compacted)
    split_gather_k<<<1024, 256>>>(q, k, v, qAh, qAl, kAh, kAl, vAh, vAl, idx, nv);
    // 2: split weights
    splitW4_k<<<1024, 256>>>(Wq, Wk, Wv, Wo, WqH, WqL, WkH, WkL,
                             WvH, WvL, WoH, WoL);
    // 3: fused QKV projections (profiled)
    G3Args p;
    p.Ah[0] = qAh; p.Al[0] = qAl; p.Bh[0] = WqH; p.Bl[0] = WqL;
    p.bias[0] = bq; p.Ch[0] = Qh; p.Cl[0] = Ql;
    p.Ah[1] = kAh; p.Al[1] = kAl; p.Bh[1] = WkH; p.Bl[1] = WkL;
    p.bias[1] = bk; p.Ch[1] = Kh; p.Cl[1] = Kl;
    p.Ah[2] = vAh; p.Al[2] = vAl; p.Bh[2] = WvH; p.Bl[2] = WvL;
    p.bias[2] = bv; p.Ch[2] = Vh; p.Cl[2] = Vl;
    p.nv = nv;
    dim3 gg3(DD / 128, MTOT / 128, 3);
    gemm3_mma<<<gg3, 256, GT_SMEM>>>(p);
    // 4: attention over compacted keys
    dim3 ga(SSQ / 128, BB * HHD);
    flash_mma_k<<<ga, 256, AT_SMEM>>>(Qh, Ql, Kh, Kl, Vh, Vl, cb, nv, Oh, Ol);
    // 5: output projection
    dim3 gg(DD / 128, MTOT / 128);
    gemm_out_mma<<<gg, 256, GT_SMEM>>>(Oh, Ol, WoH, WoL, bo, out);
}

// round 10
// speedup vs baseline: 5.1721x; 1.1324x over previous
#include <cuda_runtime.h>
#include <cuda_bf16.h>
#include <cuda_fp16.h>
#include <math.h>
#include <stdint.h>

// Problem dims
#define BB   2
#define SSQ  2048
#define DD   1024
#define HHD  16
#define DKK  64
#define MTOT (BB * SSQ)   // 4096

typedef __nv_bfloat16 bf16;
typedef __nv_bfloat162 bf162;

#define LOG2E 1.44269504f

// ---------------------------------------------------------------------------
// Scratch (__device__ globals; no allocation allowed)
// ---------------------------------------------------------------------------
__device__ bf16 g_qAh[MTOT * DD], g_qAl[MTOT * DD];
__device__ bf16 g_kAh[MTOT * DD], g_kAl[MTOT * DD];   // compacted k input
__device__ bf16 g_vAh[MTOT * DD], g_vAl[MTOT * DD];   // compacted v input
__device__ bf16 g_WqH[DD * DD], g_WqL[DD * DD];
__device__ bf16 g_WkH[DD * DD], g_WkL[DD * DD];
__device__ bf16 g_WvH[DD * DD], g_WvL[DD * DD];
__device__ bf16 g_WoH[DD * DD], g_WoL[DD * DD];
__device__ bf16 g_Qh[MTOT * DD], g_Ql[MTOT * DD];
__device__ bf16 g_Kh[MTOT * DD], g_Kl[MTOT * DD];     // compacted projected K
__device__ __half g_Vf[MTOT * DD];                    // compacted projected V (fp16)
__device__ bf16 g_Oh[MTOT * DD], g_Ol[MTOT * DD];
__device__ float g_cbias[MTOT];                       // compacted bias
__device__ int   g_idx[MTOT];                         // compaction permutation
__device__ int   g_nv[BB];                            // valid keys per batch

// ---------------------------------------------------------------------------
// PTX helpers
// ---------------------------------------------------------------------------
__device__ __forceinline__ uint32_t smem_u32(const void* p) {
    uint32_t a;
    asm("{ .reg .u64 t; cvta.to.shared.u64 t, %1; cvt.u32.u64 %0, t; }"
        : "=r"(a) : "l"(p));
    return a;
}
__device__ __forceinline__ void ldsm4(uint32_t r[4], uint32_t a) {
    asm volatile("ldmatrix.sync.aligned.m8n8.x4.shared.b16 {%0,%1,%2,%3}, [%4];"
                 : "=r"(r[0]), "=r"(r[1]), "=r"(r[2]), "=r"(r[3]) : "r"(a));
}
__device__ __forceinline__ void ldsm4t(uint32_t r[4], uint32_t a) {
    asm volatile("ldmatrix.sync.aligned.m8n8.x4.trans.shared.b16 {%0,%1,%2,%3}, [%4];"
                 : "=r"(r[0]), "=r"(r[1]), "=r"(r[2]), "=r"(r[3]) : "r"(a));
}
__device__ __forceinline__ void mma16816(float* c, const uint32_t* a,
                                         uint32_t b0, uint32_t b1) {
    asm("mma.sync.aligned.m16n8k16.row.col.f32.bf16.bf16.f32 "
        "{%0,%1,%2,%3}, {%4,%5,%6,%7}, {%8,%9}, {%0,%1,%2,%3};"
        : "+f"(c[0]), "+f"(c[1]), "+f"(c[2]), "+f"(c[3])
        : "r"(a[0]), "r"(a[1]), "r"(a[2]), "r"(a[3]), "r"(b0), "r"(b1));
}
// fp16 variant (f32 accumulate)
__device__ __forceinline__ void mma16816h(float* c, const uint32_t* a,
                                          uint32_t b0, uint32_t b1) {
    asm("mma.sync.aligned.m16n8k16.row.col.f32.f16.f16.f32 "
        "{%0,%1,%2,%3}, {%4,%5,%6,%7}, {%8,%9}, {%0,%1,%2,%3};"
        : "+f"(c[0]), "+f"(c[1]), "+f"(c[2]), "+f"(c[3])
        : "r"(a[0]), "r"(a[1]), "r"(a[2]), "r"(a[3]), "r"(b0), "r"(b1));
}
__device__ __forceinline__ uint32_t bits(bf162 h) {
    return *reinterpret_cast<uint32_t*>(&h);
}
__device__ __forceinline__ uint32_t bitsh(__half2 h) {
    return *reinterpret_cast<uint32_t*>(&h);
}
__device__ __forceinline__ float ex2f(float x) {
    float y;
    asm("ex2.approx.ftz.f32 %0, %1;" : "=f"(y) : "f"(x));
    return y;
}
#define CP16(dst, src) \
    asm volatile("cp.async.cg.shared.global [%0], [%1], 16;" \
                 :: "r"(dst), "l"(src) : "memory")
#define CPCOMMIT() asm volatile("cp.async.commit_group;" ::: "memory")
#define CPWAIT1()  asm volatile("cp.async.wait_group 1;" ::: "memory")
#define CPWAIT0()  asm volatile("cp.async.wait_group 0;" ::: "memory")

// defensive clamp for scratch-derived control values
__device__ __forceinline__ int clamp_nv(int x) {
    return x < 0 ? 0 : (x > SSQ ? SSQ : x);
}

// ---------------------------------------------------------------------------
// Mask compaction: deterministic (stable) prefix scan, one block per batch.
// ---------------------------------------------------------------------------
__global__ void scan_mask_k(const int* __restrict__ mask, int* __restrict__ idx,
                            int* __restrict__ nv, float* __restrict__ cbias)
{
    __shared__ int warp_sums[16];
    __shared__ int s_nv;
    const int b = blockIdx.x;
    const int tid = threadIdx.x;          // 512 threads, 4 keys each
    const int lane = tid & 31, wrp = tid >> 5;
    const int base = tid * 4;

    int m[4];
#pragma unroll
    for (int u = 0; u < 4; u++) m[u] = mask[b * SSQ + base + u] != 0;
    int local = m[0] + m[1] + m[2] + m[3];

    int pre = local;   // inclusive warp scan
#pragma unroll
    for (int d = 1; d < 32; d <<= 1) {
        int y = __shfl_up_sync(0xffffffffu, pre, d);
        if (lane >= d) pre += y;
    }
    if (lane == 31) warp_sums[wrp] = pre;
    __syncthreads();
    if (wrp == 0) {
        int ws = (lane < 16) ? warp_sums[lane] : 0;
#pragma unroll
        for (int d = 1; d < 16; d <<= 1) {
            int y = __shfl_up_sync(0xffffffffu, ws, d);
            if (lane >= d) ws += y;
        }
        if (lane < 16) warp_sums[lane] = ws;
        if (lane == 15) s_nv = ws;
    }
    __syncthreads();

    int offset = (pre - local) + (wrp > 0 ? warp_sums[wrp - 1] : 0);
#pragma unroll
    for (int u = 0; u < 4; u++) {
        if (m[u] && offset < SSQ) { idx[b * SSQ + offset] = base + u; offset++; }
    }
    const int total = s_nv;
    if (tid == 0) nv[b] = total;
#pragma unroll
    for (int u = 0; u < 4; u++) {
        int j = base + u;
        cbias[b * SSQ + j] = (j < total) ? 0.0f : -1e9f * LOG2E;
    }
}

// ---------------------------------------------------------------------------
// split helpers
// ---------------------------------------------------------------------------
__device__ __forceinline__ void split_store(float4 v, bf16* __restrict__ hi,
                                            bf16* __restrict__ lo, int i)
{
    bf16 h0 = __float2bfloat16_rn(v.x), h1 = __float2bfloat16_rn(v.y);
    bf16 h2 = __float2bfloat16_rn(v.z), h3 = __float2bfloat16_rn(v.w);
    bf16 l0 = __float2bfloat16_rn(v.x - __bfloat162float(h0));
    bf16 l1 = __float2bfloat16_rn(v.y - __bfloat162float(h1));
    bf16 l2 = __float2bfloat16_rn(v.z - __bfloat162float(h2));
    bf16 l3 = __float2bfloat16_rn(v.w - __bfloat162float(h3));
    ((bf162*)hi)[2 * i + 0] = bf162(h0, h1);
    ((bf162*)hi)[2 * i + 1] = bf162(h2, h3);
    ((bf162*)lo)[2 * i + 0] = bf162(l0, l1);
    ((bf162*)lo)[2 * i + 1] = bf162(l2, l3);
}

// q full split + k,v gathered-compacted split (+ zero pad to rnd128)
__global__ void split_gather_k(const float* __restrict__ q,
                               const float* __restrict__ k,
                               const float* __restrict__ v,
                               bf16* __restrict__ qh, bf16* __restrict__ ql,
                               bf16* __restrict__ kch, bf16* __restrict__ kcl,
                               bf16* __restrict__ vch, bf16* __restrict__ vcl,
                               const int* __restrict__ idx,
                               const int* __restrict__ nv)
{
    const int n4q = MTOT * DD / 4;          // 1M float4 (q)
    const int n4kv = 2 * MTOT * DD / 4;     // 2M float4 (k + v compacted)
    int i = blockIdx.x * blockDim.x + threadIdx.x;
    int stride = gridDim.x * blockDim.x;
    for (; i < n4q + n4kv; i += stride) {
        if (i < n4q) {
            split_store(((const float4*)q)[i], qh, ql, i);
            continue;
        }
        int r = i - n4q;                    // [0, 2M)
        int tsel = r >> 20;                 // 0=k, 1=v
        int rem = r & ((1 << 20) - 1);
        int b = rem >> 19;
        int loc = rem & ((1 << 19) - 1);
        int row = loc >> 8;                 // 0..2047
        int c4 = loc & 255;
        int nvb = clamp_nv(nv[b]);
        int rnd = (nvb + 127) & ~127;
        if (row >= rnd) continue;
        bf16* hi = tsel ? vch : kch;
        bf16* lo = tsel ? vcl : kcl;
        int dsti = (b * SSQ + row) * 256 + c4;
        if (row < nvb) {
            const float* src = tsel ? v : k;
            int srow = idx[b * SSQ + row] & (SSQ - 1);
            split_store(((const float4*)src)[(b * SSQ + srow) * 256 + c4],
                        hi, lo, dsti);
        } else {
            split_store(make_float4(0.f, 0.f, 0.f, 0.f), hi, lo, dsti);
        }
    }
}

// 4 weight matrices in one kernel
__global__ void splitW4_k(const float* __restrict__ wq, const float* __restrict__ wk,
                          const float* __restrict__ wv, const float* __restrict__ wo,
                          bf16* __restrict__ qh, bf16* __restrict__ ql,
                          bf16* __restrict__ kh, bf16* __restrict__ kl,
                          bf16* __restrict__ vh, bf16* __restrict__ vl,
                          bf16* __restrict__ oh, bf16* __restrict__ ol)
{
    const int n4 = DD * DD / 4;
    int i = blockIdx.x * blockDim.x + threadIdx.x;
    int stride = gridDim.x * blockDim.x;
    for (; i < 4 * n4; i += stride) {
        if (i < n4)           split_store(((const float4*)wq)[i], qh, ql, i);
        else if (i < 2 * n4)  split_store(((const float4*)wk)[i - n4], kh, kl, i - n4);
        else if (i < 3 * n4)  split_store(((const float4*)wv)[i - 2 * n4], vh, vl, i - 2 * n4);
        else                  split_store(((const float4*)wo)[i - 3 * n4], oh, ol, i - 3 * n4);
    }
}

// ---------------------------------------------------------------------------
// GEMM tiles: 128x128, BK=32, 8 warps (4m x 2n), warp 32x64, cp.async 2-stage
// ---------------------------------------------------------------------------
#define GS 40
#define GT_TILEB  (128 * GS * 2)
#define GT_STAGEB (4 * GT_TILEB)
#define GT_SMEM   (2 * GT_STAGEB)

__device__ __forceinline__ void gemm_stage_load(
    uint32_t sbase, const bf16* __restrict__ gAh, const bf16* __restrict__ gAl,
    const bf16* __restrict__ gBh, const bf16* __restrict__ gBl,
    int k0, int tid)
{
#pragma unroll
    for (int i = tid; i < 512; i += 256) {
        int r = i >> 2, c4 = i & 3;
        size_t go = (size_t)r * DD + k0 + c4 * 8;
        uint32_t so = (uint32_t)(r * GS + c4 * 8) * 2;
        CP16(sbase + so,                gAh + go);
        CP16(sbase + GT_TILEB + so,     gAl + go);
        CP16(sbase + 2 * GT_TILEB + so, gBh + go);
        CP16(sbase + 3 * GT_TILEB + so, gBl + go);
    }
}

__device__ __forceinline__ void gemm_mainloop(
    uint32_t sb, const bf16* gAh, const bf16* gAl,
    const bf16* gBh, const bf16* gBl,
    int tid, int lane, int wm, int wn, float acc[2][8][4])
{
    const int lrA = wm * 32 + (lane & 15);
    const int lcA = (lane >> 4) * 8;
    const int lrB = wn * 64 + ((lane >> 4) & 1) * 8 + (lane & 7);
    const int lcB = ((lane >> 3) & 1) * 8;

    gemm_stage_load(sb, gAh, gAl, gBh, gBl, 0, tid);
    CPCOMMIT();

    for (int t = 0; t < 32; ++t) {
        const int st = t & 1;
        if (t < 31) {
            gemm_stage_load(sb + (st ^ 1) * GT_STAGEB, gAh, gAl, gBh, gBl,
                            (t + 1) * 32, tid);
            CPCOMMIT();
            CPWAIT1();
        } else {
            CPWAIT0();
        }
        __syncthreads();

        const uint32_t bAh = sb + st * GT_STAGEB;
        const uint32_t bAl = bAh + GT_TILEB;
        const uint32_t bBh = bAh + 2 * GT_TILEB;
        const uint32_t bBl = bAh + 3 * GT_TILEB;

#pragma unroll
        for (int kb = 0; kb < 2; kb++) {
            uint32_t ah[2][4], al[2][4];
#pragma unroll
            for (int mi = 0; mi < 2; mi++) {
                uint32_t off = ((lrA + mi * 16) * GS + kb * 16 + lcA) * 2;
                ldsm4(ah[mi], bAh + off);
                ldsm4(al[mi], bAl + off);
            }
#pragma unroll
            for (int njp = 0; njp < 4; njp++) {
                uint32_t off = ((lrB + njp * 16) * GS + kb * 16 + lcB) * 2;
                uint32_t bh[4], bl[4];
                ldsm4(bh, bBh + off);
                ldsm4(bl, bBl + off);
                float* c00 = acc[0][njp * 2];
                float* c01 = acc[0][njp * 2 + 1];
                float* c10 = acc[1][njp * 2];
                float* c11 = acc[1][njp * 2 + 1];
                mma16816(c00, ah[0], bh[0], bh[1]);
                mma16816(c10, ah[1], bh[0], bh[1]);
                mma16816(c01, ah[0], bh[2], bh[3]);
                mma16816(c11, ah[1], bh[2], bh[3]);
                mma16816(c00, ah[0], bl[0], bl[1]);
                mma16816(c10, ah[1], bl[0], bl[1]);
                mma16816(c01, ah[0], bl[2], bl[3]);
                mma16816(c11, ah[1], bl[2], bl[3]);
                mma16816(c00, al[0], bh[0], bh[1]);
                mma16816(c10, al[1], bh[0], bh[1]);
                mma16816(c01, al[0], bh[2], bh[3]);
                mma16816(c11, al[1], bh[2], bh[3]);
            }
        }
        __syncthreads();
    }
}

// Fused QKV projections; K/V (z>0) skip CTAs above the valid compacted rows.
// z==2 (V) writes SINGLE fp16 output; z<2 write bf16 hi/lo.
struct G3Args {
    const bf16 *Ah[3], *Al[3], *Bh[3], *Bl[3];
    const float* bias[3];
    bf16 *Ch[3], *Cl[3];
    __half* Vf;
    const int* nv;
};

__global__ __launch_bounds__(256, 2) void gemm3_mma(G3Args p)
{
    extern __shared__ __align__(16) char dyn[];
    const uint32_t sb = smem_u32(dyn);
    const int z = blockIdx.z;
    const int bm = blockIdx.y * 128;
    const int bn = blockIdx.x * 128;

    if (z > 0) {   // K or V projection: skip masked-out row tiles
        int batch = bm >> 11;
        int local = bm & 2047;
        int rnd = (clamp_nv(p.nv[batch]) + 127) & ~127;
        if (local >= rnd) return;
    }

    const int tid  = threadIdx.x;
    const int lane = tid & 31;
    const int warp = tid >> 5;
    const int wm = warp & 3, wn = warp >> 2;

    float acc[2][8][4];
#pragma unroll
    for (int mi = 0; mi < 2; mi++)
#pragma unroll
        for (int nj = 0; nj < 8; nj++)
#pragma unroll
            for (int e = 0; e < 4; e++) acc[mi][nj][e] = 0.0f;

    gemm_mainloop(sb,
                  p.Ah[z] + (size_t)bm * DD, p.Al[z] + (size_t)bm * DD,
                  p.Bh[z] + (size_t)bn * DD, p.Bl[z] + (size_t)bn * DD,
                  tid, lane, wm, wn, acc);

    const float* bias = p.bias[z];
    const int g = lane >> 2, c = lane & 3;
    if (z == 2) {
        __half* Vf = p.Vf;
#pragma unroll
        for (int mi = 0; mi < 2; mi++) {
#pragma unroll
            for (int nj = 0; nj < 8; nj++) {
                int row = bm + wm * 32 + mi * 16 + g;
                int col = bn + wn * 64 + nj * 8 + c * 2;
                float b0 = bias[col], b1 = bias[col + 1];
                __half2 v01 = __float22half2_rn(
                    make_float2(acc[mi][nj][0] + b0, acc[mi][nj][1] + b1));
                __half2 v23 = __float22half2_rn(
                    make_float2(acc[mi][nj][2] + b0, acc[mi][nj][3] + b1));
                *(__half2*)&Vf[(size_t)row * DD + col] = v01;
                *(__half2*)&Vf[(size_t)(row + 8) * DD + col] = v23;
            }
        }
    } else {
        bf16* Chi = p.Ch[z];
        bf16* Clo = p.Cl[z];
#pragma unroll
        for (int mi = 0; mi < 2; mi++) {
#pragma unroll
            for (int nj = 0; nj < 8; nj++) {
                int row = bm + wm * 32 + mi * 16 + g;
                int col = bn + wn * 64 + nj * 8 + c * 2;
                float b0 = bias[col], b1 = bias[col + 1];
                float x0 = acc[mi][nj][0] + b0, x1 = acc[mi][nj][1] + b1;
                float x2 = acc[mi][nj][2] + b0, x3 = acc[mi][nj][3] + b1;
                bf162 h01 = __float22bfloat162_rn(make_float2(x0, x1));
                bf162 h23 = __float22bfloat162_rn(make_float2(x2, x3));
                bf162 l01 = __float22bfloat162_rn(make_float2(
                    x0 - __low2float(h01), x1 - __high2float(h01)));
                bf162 l23 = __float22bfloat162_rn(make_float2(
                    x2 - __low2float(h23), x3 - __high2float(h23)));
                *(bf162*)&Chi[(size_t)row * DD + col] = h01;
                *(bf162*)&Clo[(size_t)row * DD + col] = l01;
                *(bf162*)&Chi[(size_t)(row + 8) * DD + col] = h23;
                *(bf162*)&Clo[(size_t)(row + 8) * DD + col] = l23;
            }
        }
    }
}

// Output projection (fp32 result)
__global__ __launch_bounds__(256, 2) void gemm_out_mma(
    const bf16* __restrict__ Ah, const bf16* __restrict__ Al,
    const bf16* __restrict__ Wh, const bf16* __restrict__ Wl,
    const float* __restrict__ bias, float* __restrict__ Cf)
{
    extern __shared__ __align__(16) char dyn[];
    const uint32_t sb = smem_u32(dyn);
    const int tid  = threadIdx.x;
    const int lane = tid & 31;
    const int warp = tid >> 5;
    const int wm = warp & 3, wn = warp >> 2;
    const int bm = blockIdx.y * 128;
    const int bn = blockIdx.x * 128;

    float acc[2][8][4];
#pragma unroll
    for (int mi = 0; mi < 2; mi++)
#pragma unroll
        for (int nj = 0; nj < 8; nj++)
#pragma unroll
            for (int e = 0; e < 4; e++) acc[mi][nj][e] = 0.0f;

    gemm_mainloop(sb,
                  Ah + (size_t)bm * DD, Al + (size_t)bm * DD,
                  Wh + (size_t)bn * DD, Wl + (size_t)bn * DD,
                  tid, lane, wm, wn, acc);

    const int g = lane >> 2, c = lane & 3;
#pragma unroll
    for (int mi = 0; mi < 2; mi++) {
#pragma unroll
        for (int nj = 0; nj < 8; nj++) {
            int row = bm + wm * 32 + mi * 16 + g;
            int col = bn + wn * 64 + nj * 8 + c * 2;
            float b0 = bias[col], b1 = bias[col + 1];
            *(float2*)&Cf[(size_t)row * DD + col] =
                make_float2(acc[mi][nj][0] + b0, acc[mi][nj][1] + b1);
            *(float2*)&Cf[(size_t)(row + 8) * DD + col] =
                make_float2(acc[mi][nj][2] + b0, acc[mi][nj][3] + b1);
        }
    }
}

// ---------------------------------------------------------------------------
// Flash attention over COMPACTED keys: nt = ceil(nv/64) tiles.
// QK: bf16 x3 terms.  PV: single fp16 x fp16 MMA (P, V quantization ~2^-12).
// KV stage: [Kh | Kl | Vf] = 3 tiles.
// ---------------------------------------------------------------------------
#define AS 72
#define AT_TILEB  (64 * AS * 2)
#define AT_STAGEB (3 * AT_TILEB)
#define AT_SMEM   (2 * AT_STAGEB)

__device__ __forceinline__ void att_stage_load(
    uint32_t sbase, const bf16* __restrict__ Kh, const bf16* __restrict__ Kl,
    const __half* __restrict__ Vf, size_t gbase, int tid)
{
#pragma unroll
    for (int i = tid; i < 512; i += 256) {
        int r = i >> 3, c8 = i & 7;
        size_t go = gbase + (size_t)r * DD + c8 * 8;
        uint32_t so = (uint32_t)(r * AS + c8 * 8) * 2;
        CP16(sbase + so,                Kh + go);
        CP16(sbase + AT_TILEB + so,     Kl + go);
        CP16(sbase + 2 * AT_TILEB + so, Vf + go);
    }
}

__global__ __launch_bounds__(256) void flash_mma_k(
    const bf16* __restrict__ Qh, const bf16* __restrict__ Ql,
    const bf16* __restrict__ Kh, const bf16* __restrict__ Kl,
    const __half* __restrict__ Vf,
    const float* __restrict__ cb, const int* __restrict__ nvp,
    bf16* __restrict__ Oh, bf16* __restrict__ Ol)
{
    extern __shared__ __align__(16) char dyn[];
    __shared__ __align__(16) float sBias[2][64];
    const uint32_t sb = smem_u32(dyn);
    const uint32_t sbias_u32 = smem_u32(&sBias[0][0]);

    const int tid  = threadIdx.x;
    const int lane = tid & 31;
    const int w    = tid >> 5;
    const int b  = blockIdx.y >> 4;
    const int h  = blockIdx.y & 15;
    const int q0 = blockIdx.x * 128;
    const int g = lane >> 2, c = lane & 3;
    const int nt = (clamp_nv(nvp[b]) + 63) >> 6;

    // ---- Phase 1: Q tile -> fragments ----
    {
        bf16* sQh = (bf16*)dyn;
        bf16* sQl = (bf16*)(dyn + 128 * AS * 2);
        const bf16* gQh = Qh + (size_t)(b * SSQ + q0) * DD + h * DKK;
        const bf16* gQl = Ql + (size_t)(b * SSQ + q0) * DD + h * DKK;
#pragma unroll
        for (int i = tid; i < 1024; i += 256) {
            int r = i >> 3, c8 = i & 7;
            size_t go = (size_t)r * DD + c8 * 8;
            int so = r * AS + c8 * 8;
            *(uint4*)&sQh[so] = *(const uint4*)&gQh[go];
            *(uint4*)&sQl[so] = *(const uint4*)&gQl[go];
        }
    }
    __syncthreads();

    uint32_t qh[4][4], ql[4][4];
    {
        const int lrQ = w * 16 + (lane & 15);
        const int lcQ = (lane >> 4) * 8;
        const uint32_t bQh = sb;
        const uint32_t bQl = sb + 128 * AS * 2;
#pragma unroll
        for (int kb = 0; kb < 4; kb++) {
            uint32_t off = (lrQ * AS + kb * 16 + lcQ) * 2;
            ldsm4(qh[kb], bQh + off);
            ldsm4(ql[kb], bQl + off);
        }
    }
    __syncthreads();

    float m0 = -INFINITY, m1 = -INFINITY, l0 = 0.0f, l1 = 0.0f;
    float acc[8][4];
#pragma unroll
    for (int on = 0; on < 8; on++)
#pragma unroll
        for (int e = 0; e < 4; e++) acc[on][e] = 0.0f;

    const int lrK = ((lane >> 4) & 1) * 8 + (lane & 7);
    const int lcK = ((lane >> 3) & 1) * 8;
    const int lrV = ((lane >> 3) & 1) * 8 + (lane & 7);
    const int lcV = (lane >> 4) * 8;
    const float scale2 = 0.125f * LOG2E;
    const size_t gKV0 = (size_t)(b * SSQ) * DD + h * DKK;

    if (nt > 0) {
        att_stage_load(sb, Kh, Kl, Vf, gKV0, tid);
        if (tid < 16) CP16(sbias_u32 + tid * 16, &cb[b * SSQ + tid * 4]);
        CPCOMMIT();
    }

    for (int t = 0; t < nt; ++t) {
        const int st = t & 1;
        if (t + 1 < nt) {
            att_stage_load(sb + (st ^ 1) * AT_STAGEB, Kh, Kl, Vf,
                           gKV0 + (size_t)(t + 1) * 64 * DD, tid);
            if (tid < 16)
                CP16(sbias_u32 + (st ^ 1) * 256 + tid * 16,
                     &cb[b * SSQ + (t + 1) * 64 + tid * 4]);
            CPCOMMIT();
            CPWAIT1();
        } else {
            CPWAIT0();
        }
        __syncthreads();

        const uint32_t bKh = sb + st * AT_STAGEB;
        const uint32_t bKl = bKh + AT_TILEB;
        const uint32_t bVf = bKh + 2 * AT_TILEB;

        // ---- S = Q K^T (bf16 x3) ----
        float s[8][4];
#pragma unroll
        for (int nj = 0; nj < 8; nj++)
#pragma unroll
            for (int e = 0; e < 4; e++) s[nj][e] = 0.0f;

#pragma unroll
        for (int kb = 0; kb < 4; kb++) {
#pragma unroll
            for (int np = 0; np < 2; np++) {
                uint32_t kh0[4], kl0[4], kh1[4], kl1[4];
                uint32_t off0 = (((np * 2 + 0) * 16 + lrK) * AS + kb * 16 + lcK) * 2;
                uint32_t off1 = (((np * 2 + 1) * 16 + lrK) * AS + kb * 16 + lcK) * 2;
                ldsm4(kh0, bKh + off0);
                ldsm4(kl0, bKl + off0);
                ldsm4(kh1, bKh + off1);
                ldsm4(kl1, bKl + off1);
                float* c0 = s[np * 4 + 0];
                float* c1 = s[np * 4 + 1];
                float* c2 = s[np * 4 + 2];
                float* c3 = s[np * 4 + 3];
                mma16816(c0, qh[kb], kh0[0], kh0[1]);
                mma16816(c1, qh[kb], kh0[2], kh0[3]);
                mma16816(c2, qh[kb], kh1[0], kh1[1]);
                mma16816(c3, qh[kb], kh1[2], kh1[3]);
                mma16816(c0, qh[kb], kl0[0], kl0[1]);
                mma16816(c1, qh[kb], kl0[2], kl0[3]);
                mma16816(c2, qh[kb], kl1[0], kl1[1]);
                mma16816(c3, qh[kb], kl1[2], kl1[3]);
                mma16816(c0, ql[kb], kh0[0], kh0[1]);
                mma16816(c1, ql[kb], kh0[2], kh0[3]);
                mma16816(c2, ql[kb], kh1[0], kh1[1]);
                mma16816(c3, ql[kb], kh1[2], kh1[3]);
            }
        }

        // ---- scale + bias (exp2 domain; pad slots get -BIG) ----
#pragma unroll
        for (int nj = 0; nj < 8; nj++) {
            float b0 = sBias[st][nj * 8 + c * 2];
            float b1 = sBias[st][nj * 8 + c * 2 + 1];
            s[nj][0] = fmaf(s[nj][0], scale2, b0);
            s[nj][1] = fmaf(s[nj][1], scale2, b1);
            s[nj][2] = fmaf(s[nj][2], scale2, b0);
            s[nj][3] = fmaf(s[nj][3], scale2, b1);
        }

        // ---- online softmax ----
        float mx0 = -INFINITY, mx1 = -INFINITY;
#pragma unroll
        for (int nj = 0; nj < 8; nj++) {
            mx0 = fmaxf(mx0, fmaxf(s[nj][0], s[nj][1]));
            mx1 = fmaxf(mx1, fmaxf(s[nj][2], s[nj][3]));
        }
        mx0 = fmaxf(mx0, __shfl_xor_sync(0xffffffffu, mx0, 1));
        mx0 = fmaxf(mx0, __shfl_xor_sync(0xffffffffu, mx0, 2));
        mx1 = fmaxf(mx1, __shfl_xor_sync(0xffffffffu, mx1, 1));
        mx1 = fmaxf(mx1, __shfl_xor_sync(0xffffffffu, mx1, 2));
        float mn0 = fmaxf(m0, mx0), mn1 = fmaxf(m1, mx1);
        float f0 = ex2f(m0 - mn0), f1 = ex2f(m1 - mn1);
        m0 = mn0; m1 = mn1;

        float sum0 = 0.0f, sum1 = 0.0f;
#pragma unroll
        for (int nj = 0; nj < 8; nj++) {
            s[nj][0] = ex2f(s[nj][0] - m0);
            s[nj][1] = ex2f(s[nj][1] - m0);
            s[nj][2] = ex2f(s[nj][2] - m1);
            s[nj][3] = ex2f(s[nj][3] - m1);
            sum0 += s[nj][0] + s[nj][1];
            sum1 += s[nj][2] + s[nj][3];
        }
        sum0 += __shfl_xor_sync(0xffffffffu, sum0, 1);
        sum0 += __shfl_xor_sync(0xffffffffu, sum0, 2);
        sum1 += __shfl_xor_sync(0xffffffffu, sum1, 1);
        sum1 += __shfl_xor_sync(0xffffffffu, sum1, 2);
        l0 = l0 * f0 + sum0;
        l1 = l1 * f1 + sum1;
#pragma unroll
        for (int on = 0; on < 8; on++) {
            acc[on][0] *= f0; acc[on][1] *= f0;
            acc[on][2] *= f1; acc[on][3] *= f1;
        }

        // ---- O += P V : single fp16 MMA per (kb2, output pair) ----
#pragma unroll
        for (int kb2 = 0; kb2 < 4; kb2++) {
            uint32_t pa[4];
#pragma unroll
            for (int q2 = 0; q2 < 2; q2++) {
                float* sp = s[2 * kb2 + q2];
                pa[q2 * 2]     = bitsh(__float22half2_rn(make_float2(sp[0], sp[1])));
                pa[q2 * 2 + 1] = bitsh(__float22half2_rn(make_float2(sp[2], sp[3])));
            }
#pragma unroll
            for (int op = 0; op < 2; op++) {
                uint32_t vh0[4], vh1[4];
                uint32_t off0 = ((kb2 * 16 + lrV) * AS + (op * 2 + 0) * 16 + lcV) * 2;
                uint32_t off1 = ((kb2 * 16 + lrV) * AS + (op * 2 + 1) * 16 + lcV) * 2;
                ldsm4t(vh0, bVf + off0);
                ldsm4t(vh1, bVf + off1);
                mma16816h(acc[op * 4 + 0], pa, vh0[0], vh0[1]);
                mma16816h(acc[op * 4 + 1], pa, vh0[2], vh0[3]);
                mma16816h(acc[op * 4 + 2], pa, vh1[0], vh1[1]);
                mma16816h(acc[op * 4 + 3], pa, vh1[2], vh1[3]);
            }
        }
        __syncthreads();
    }

    // ---- epilogue ----
    float inv0 = l0 > 0.f ? 1.0f / l0 : 0.f;
    float inv1 = l1 > 0.f ? 1.0f / l1 : 0.f;
    int rowg = b * SSQ + q0 + w * 16 + g;
#pragma unroll
    for (int on = 0; on < 8; on++) {
        int col = h * DKK + on * 8 + c * 2;
        float x0 = acc[on][0] * inv0, x1 = acc[on][1] * inv0;
        float x2 = acc[on][2] * inv1, x3 = acc[on][3] * inv1;
        bf162 h01 = __float22bfloat162_rn(make_float2(x0, x1));
        bf162 h23 = __float22bfloat162_rn(make_float2(x2, x3));
        bf162 l01 = __float22bfloat162_rn(make_float2(
            x0 - __low2float(h01), x1 - __high2float(h01)));
        bf162 l23 = __float22bfloat162_rn(make_float2(
            x2 - __low2float(h23), x3 - __high2float(h23)));
        *(bf162*)&Oh[(size_t)rowg * DD + col] = h01;
        *(bf162*)&Ol[(size_t)rowg * DD + col] = l01;
        *(bf162*)&Oh[(size_t)(rowg + 8) * DD + col] = h23;
        *(bf162*)&Ol[(size_t)(rowg + 8) * DD + col] = l23;
    }
}

// ---------------------------------------------------------------------------
// Launch. Index 3 (profiled) = gemm3_mma.
// ---------------------------------------------------------------------------
extern "C" void kernel_launch(void* const* d_in, const int* in_sizes, int n_in,
                              void* d_out, int out_size)
{
    const float* q    = (const float*)d_in[0];
    const float* k    = (const float*)d_in[1];
    const float* v    = (const float*)d_in[2];
    const int*   mask = (const int*)  d_in[3];
    const float* Wq   = (const float*)d_in[4];
    const float* bq   = (const float*)d_in[5];
    const float* Wk   = (const float*)d_in[6];
    const float* bk   = (const float*)d_in[7];
    const float* Wv   = (const float*)d_in[8];
    const float* bv   = (const float*)d_in[9];
    const float* Wo   = (const float*)d_in[10];
    const float* bo   = (const float*)d_in[11];
    float* out = (float*)d_out;

    bf16 *qAh, *qAl, *kAh, *kAl, *vAh, *vAl;
    bf16 *WqH, *WqL, *WkH, *WkL, *WvH, *WvL, *WoH, *WoL;
    bf16 *Qh, *Ql, *Kh, *Kl, *Oh, *Ol;
    __half* Vf;
    float *cb; int *idx, *nv;
    cudaGetSymbolAddress((void**)&qAh, g_qAh); cudaGetSymbolAddress((void**)&qAl, g_qAl);
    cudaGetSymbolAddress((void**)&kAh, g_kAh); cudaGetSymbolAddress((void**)&kAl, g_kAl);
    cudaGetSymbolAddress((void**)&vAh, g_vAh); cudaGetSymbolAddress((void**)&vAl, g_vAl);
    cudaGetSymbolAddress((void**)&WqH, g_WqH); cudaGetSymbolAddress((void**)&WqL, g_WqL);
    cudaGetSymbolAddress((void**)&WkH, g_WkH); cudaGetSymbolAddress((void**)&WkL, g_WkL);
    cudaGetSymbolAddress((void**)&WvH, g_WvH); cudaGetSymbolAddress((void**)&WvL, g_WvL);
    cudaGetSymbolAddress((void**)&WoH, g_WoH); cudaGetSymbolAddress((void**)&WoL, g_WoL);
    cudaGetSymbolAddress((void**)&Qh, g_Qh);   cudaGetSymbolAddress((void**)&Ql, g_Ql);
    cudaGetSymbolAddress((void**)&Kh, g_Kh);   cudaGetSymbolAddress((void**)&Kl, g_Kl);
    cudaGetSymbolAddress((void**)&Vf, g_Vf);
    cudaGetSymbolAddress((void**)&Oh, g_Oh);   cudaGetSymbolAddress((void**)&Ol, g_Ol);
    cudaGetSymbolAddress((void**)&cb, g_cbias);
    cudaGetSymbolAddress((void**)&idx, g_idx);
    cudaGetSymbolAddress((void**)&nv, g_nv);

    cudaFuncSetAttribute(gemm3_mma,
                         cudaFuncAttributeMaxDynamicSharedMemorySize, GT_SMEM);
    cudaFuncSetAttribute(gemm_out_mma,
                         cudaFuncAttributeMaxDynamicSharedMemorySize, GT_SMEM);
    cudaFuncSetAttribute(flash_mma_k,
                         cudaFuncAttributeMaxDynamicSharedMemorySize, AT_SMEM);

    // 0: mask scan/compaction
    scan_mask_k<<<BB, 512>>>(mask, idx, nv, cb);
    // 1: split q (full) + k,v (gathered/compacted)
    split_gather_k<<<1024, 256>>>(q, k, v, qAh, qAl, kAh, kAl, vAh, vAl, idx, nv);
    // 2: split weights
    splitW4_k<<<1024, 256>>>(Wq, Wk, Wv, Wo, WqH, WqL, WkH, WkL,
                             WvH, WvL, WoH, WoL);
    // 3: fused QKV projections (profiled)
    G3Args p;
    p.Ah[0] = qAh; p.Al[0] = qAl; p.Bh[0] = WqH; p.Bl[0] = WqL;
    p.bias[0] = bq; p.Ch[0] = Qh; p.Cl[0] = Ql;
    p.Ah[1] = kAh; p.Al[1] = kAl; p.Bh[1] = WkH; p.Bl[1] = WkL;
    p.bias[1] = bk; p.Ch[1] = Kh; p.Cl[1] = Kl;
    p.Ah[2] = vAh; p.Al[2] = vAl; p.Bh[2] = WvH; p.Bl[2] = WvL;
    p.bias[2] = bv; p.Ch[2] = nullptr; p.Cl[2] = nullptr;
    p.Vf = Vf;
    p.nv = nv;
    dim3 gg3(DD / 128, MTOT / 128, 3);
    gemm3_mma<<<gg3, 256, GT_SMEM>>>(p);
    // 4: attention over compacted keys (QK bf16x3, PV fp16x1)
    dim3 ga(SSQ / 128, BB * HHD);
    flash_mma_k<<<ga, 256, AT_SMEM>>>(Qh, Ql, Kh, Kl, Vf, cb, nv, Oh, Ol);
    // 5: output projection
    dim3 gg(DD / 128, MTOT / 128);
    gemm_out_mma<<<gg, 256, GT_SMEM>>>(Oh, Ol, WoH, WoL, bo, out);
}